// round 10
// baseline (speedup 1.0000x reference)
#include <cuda_runtime.h>
#include <cuda_fp16.h>
#include <math.h>
#include <stdint.h>

// ---------------- problem constants ----------------
#define NU    2048
#define SL    50
#define DE    300
#define KPAD  320      // 20 k-groups of 16; 10 chunks of 32
#define DOUT  100
#define NC    7
#define WIND  10
#define HOPS  3
#define NB    2047
#define VOCAB 50000
#define VPAD  50048    // 391 * 128
#define NCOL  768
#define FCAT  192

// ---------------- static scratch ----------------
__device__ __half g_Ah[(size_t)VPAD*KPAD];      // A fp16 fragment order (128-row mblk)
__device__ __half g_Bh[NCOL*KPAD];              // B fp16 nt-pair fragment order (128-col nblk)
__device__ __half g_Zh[(size_t)VPAD*NCOL];      // fp16 projections (77 MB)
__device__ float g_twT[FCAT*DOUT];
__device__ float g_sutt[NU*DOUT];
__device__ float g_xproj[NB*3*DOUT];
__device__ float g_memb[NB*WIND*DOUT];
__device__ float g_q[NB*DOUT];
__device__ float g_attn_scratch[HOPS*NB*WIND];

// ---------------- helpers ----------------
__device__ __forceinline__ uint32_t smem_u32(const void* p) {
    uint32_t a;
    asm("{ .reg .u64 t; cvta.to.shared.u64 t, %1; cvt.u32.u64 %0, t; }" : "=r"(a) : "l"(p));
    return a;
}
#define CP_ASYNC16(sa, gp) asm volatile("cp.async.cg.shared.global [%0], [%1], 16;" :: "r"(sa), "l"(gp) : "memory")
#define CP_COMMIT()        asm volatile("cp.async.commit_group;" ::: "memory")
#define CP_WAIT(n)         asm volatile("cp.async.wait_group %0;" :: "n"(n) : "memory")

__device__ __forceinline__ void mma_fp16(float* d, const uint32_t* a, const uint32_t* b) {
    asm volatile("mma.sync.aligned.m16n8k16.row.col.f32.f16.f16.f32 "
        "{%0,%1,%2,%3}, {%4,%5,%6,%7}, {%8,%9}, {%0,%1,%2,%3};"
        : "+f"(d[0]), "+f"(d[1]), "+f"(d[2]), "+f"(d[3])
        : "r"(a[0]), "r"(a[1]), "r"(a[2]), "r"(a[3]), "r"(b[0]), "r"(b[1]));
}

// ---------------- pack A v2: coalesced read -> smem -> fragment-order write --
// One block per 128-row mblk. smem tile [128][328] fp16 (stride 328 => phase-2
// LDS bank = (4*m + kk) mod 32, conflict-free).
#define PA_LDK 328
#define PACKA_SMEM (128*PA_LDK*2)
__global__ void __launch_bounds__(256) pack_Ah(const float* __restrict__ emb) {
    extern __shared__ __half sa[];
    const int tid = threadIdx.x;
    const int mblk = blockIdx.x;

    // zero tile (covers k>=300 tail and rows >= VOCAB)
    {
        uint4* s4 = reinterpret_cast<uint4*>(sa);
        for (int i = tid; i < 128*PA_LDK/8; i += 256)
            s4[i] = make_uint4(0, 0, 0, 0);
    }
    __syncthreads();

    // phase 1: coalesced fp32 read, fp16 convert, smem store
    {
        const float4* e4 = reinterpret_cast<const float4*>(emb);
        for (int i = tid; i < 128*75; i += 256) {
            int row = i / 75, c4 = i - row*75;
            int m = mblk*128 + row;
            if (m < VOCAB) {
                float4 v = e4[(size_t)m*75 + c4];
                __half2 lo = __floats2half2_rn(v.x, v.y);
                __half2 hi = __floats2half2_rn(v.z, v.w);
                uint2 pk = make_uint2(*(uint32_t*)&lo, *(uint32_t*)&hi);
                *reinterpret_cast<uint2*>(sa + row*PA_LDK + c4*4) = pk;
            }
        }
    }
    __syncthreads();

    // phase 2: fragment-order coalesced write
    {
        const int lane = tid & 31;
        const int r16  = tid >> 5;          // 0..7
        const int mloc = r16*16 + (lane >> 2);
        const int kk   = (lane & 3)*2;
        const uint32_t* s32 = reinterpret_cast<const uint32_t*>(sa);
        uint4* out4 = reinterpret_cast<uint4*>(g_Ah);
        #pragma unroll 4
        for (int kc16 = 0; kc16 < 20; kc16++) {
            int k = kc16*16 + kk;
            uint32_t h0 = s32[( mloc      *PA_LDK + k    ) >> 1];
            uint32_t h1 = s32[((mloc + 8)*PA_LDK + k    ) >> 1];
            uint32_t h2 = s32[( mloc      *PA_LDK + k + 8) >> 1];
            uint32_t h3 = s32[((mloc + 8)*PA_LDK + k + 8) >> 1];
            out4[((size_t)(mblk*20 + kc16)*8 + r16)*32 + lane] = make_uint4(h0, h1, h2, h3);
        }
    }
}

// ---------------- pack B (dst-linear, 128-col nblk, nt-pair order) ----------
__device__ __forceinline__ __half wall_h(const float* w3, const float* w4,
                                         const float* w5, int c, int k) {
    if (k >= DE) return __float2half_rn(0.f);
    float v;
    if (c < 192)      { int cc = c;       int dt = cc >> 6, o = cc & 63; v = w3[(o*3 + dt)*DE + k]; }
    else if (c < 448) { int cc = c - 192; int dt = cc >> 6, o = cc & 63; v = w4[(o*4 + dt)*DE + k]; }
    else              { int cc = c - 448; int dt = cc >> 6, o = cc & 63; v = w5[(o*5 + dt)*DE + k]; }
    return __float2half_rn(v);
}
__global__ void pack_Bh(const float* __restrict__ w3,
                        const float* __restrict__ w4,
                        const float* __restrict__ w5) {
    int d4 = blockIdx.x * blockDim.x + threadIdx.x;
    if (d4 >= NCOL*KPAD/8) return;
    int lane = d4 & 31;
    int np   = (d4 >> 5) & 7;
    int rest = d4 >> 8;
    int kc16 = rest % 20;
    int nblk = rest / 20;
    int na = nblk*128 + np*16 + (lane >> 2);
    int nb = na + 8;
    int k = kc16*16 + (lane & 3)*2;
    __half2 h0 = __halves2half2(wall_h(w3,w4,w5, na, k),     wall_h(w3,w4,w5, na, k + 1));
    __half2 h1 = __halves2half2(wall_h(w3,w4,w5, na, k + 8), wall_h(w3,w4,w5, na, k + 9));
    __half2 h2 = __halves2half2(wall_h(w3,w4,w5, nb, k),     wall_h(w3,w4,w5, nb, k + 1));
    __half2 h3 = __halves2half2(wall_h(w3,w4,w5, nb, k + 8), wall_h(w3,w4,w5, nb, k + 9));
    uint4 v = make_uint4(*(uint32_t*)&h0, *(uint32_t*)&h1, *(uint32_t*)&h2, *(uint32_t*)&h3);
    reinterpret_cast<uint4*>(g_Bh)[d4] = v;
}

__global__ void transpose_tw(const float* __restrict__ tw) {
    int idx = blockIdx.x * blockDim.x + threadIdx.x;
    if (idx >= FCAT*DOUT) return;
    int j = idx / DOUT, d = idx % DOUT;
    g_twT[idx] = tw[d*FCAT + j];
}

// ---------------- fp16 mma GEMM: Z = Ah @ Bh^T (fp16 out) ----------------
// CTA 128(M) x 128(N), 256 thr = 8 warps (4 M x 2 N), warp tile 32x64.
// 2 CTAs/SM. 3-stage cp.async, one sync per chunk.
#define GEMM_SMEM 49152

__global__ void __launch_bounds__(256, 2) conv_gemm_mma() {
    extern __shared__ char smc[];
    const int tid  = threadIdx.x;
    const int lane = tid & 31, wid = tid >> 5;
    const int warp_m = wid & 3;
    const int warp_n = wid >> 2;
    const int by = blockIdx.y, bx = blockIdx.x;
    const int m0 = by * 128, n0 = bx * 128;

    const uint32_t smb = smem_u32(smc);
    const uint4* Ah4 = reinterpret_cast<const uint4*>(g_Ah);
    const uint4* Bh4 = reinterpret_cast<const uint4*>(g_Bh);

    float acc[2][8][4];
    #pragma unroll
    for (int mt = 0; mt < 2; mt++)
        #pragma unroll
        for (int nt = 0; nt < 8; nt++)
            #pragma unroll
            for (int i = 0; i < 4; i++) acc[mt][nt][i] = 0.f;

    #pragma unroll
    for (int c = 0; c < 2; c++) {
        size_t aG = ((size_t)by*20 + c*2) * 256;
        size_t bG = ((size_t)bx*20 + c*2) * 256;
        #pragma unroll
        for (int i = 0; i < 2; i++) {
            CP_ASYNC16(smb +         c*8192 + (tid + i*256)*16, Ah4 + aG + tid + i*256);
            CP_ASYNC16(smb + 24576 + c*8192 + (tid + i*256)*16, Bh4 + bG + tid + i*256);
        }
        CP_COMMIT();
    }

    for (int c = 0; c < 10; c++) {
        const int buf = c % 3;
        if (c < 9) CP_WAIT(1); else CP_WAIT(0);
        __syncthreads();
        if (c + 2 < 10) {
            const int nb = (c + 2) % 3;
            size_t aG = ((size_t)by*20 + (c + 2)*2) * 256;
            size_t bG = ((size_t)bx*20 + (c + 2)*2) * 256;
            #pragma unroll
            for (int i = 0; i < 2; i++) {
                CP_ASYNC16(smb +         nb*8192 + (tid + i*256)*16, Ah4 + aG + tid + i*256);
                CP_ASYNC16(smb + 24576 + nb*8192 + (tid + i*256)*16, Bh4 + bG + tid + i*256);
            }
            CP_COMMIT();
        }

        const uint4* A4 = reinterpret_cast<const uint4*>(smc + buf*8192);
        const uint4* B4 = reinterpret_cast<const uint4*>(smc + 24576 + buf*8192);
        #pragma unroll
        for (int ks = 0; ks < 2; ks++) {
            uint32_t a[2][4], b[8][2];
            #pragma unroll
            for (int mt = 0; mt < 2; mt++) {
                uint4 v = A4[(ks*8 + warp_m*2 + mt)*32 + lane];
                a[mt][0] = v.x; a[mt][1] = v.y; a[mt][2] = v.z; a[mt][3] = v.w;
            }
            #pragma unroll
            for (int np = 0; np < 4; np++) {
                uint4 u = B4[(ks*8 + warp_n*4 + np)*32 + lane];
                b[2*np  ][0] = u.x; b[2*np  ][1] = u.y;
                b[2*np+1][0] = u.z; b[2*np+1][1] = u.w;
            }
            #pragma unroll
            for (int mt = 0; mt < 2; mt++)
                #pragma unroll
                for (int nt = 0; nt < 8; nt++)
                    mma_fp16(acc[mt][nt], a[mt], b[nt]);
        }
    }

    __half2* Z2 = reinterpret_cast<__half2*>(g_Zh);
    #pragma unroll
    for (int mt = 0; mt < 2; mt++) {
        int r = m0 + warp_m*32 + mt*16 + (lane >> 2);
        #pragma unroll
        for (int nt = 0; nt < 8; nt++) {
            int cc = n0 + warp_n*64 + nt*8 + (lane & 3)*2;
            Z2[((size_t) r      *NCOL + cc) >> 1] = __floats2half2_rn(acc[mt][nt][0], acc[mt][nt][1]);
            Z2[((size_t)(r + 8)*NCOL + cc) >> 1] = __floats2half2_rn(acc[mt][nt][2], acc[mt][nt][3]);
        }
    }
}

// ---------------- fused pool + relu + tanh projection (smem staged) ---------
#define POOL_SMEM (76800 + 200 + 1536 + 768)
__global__ void __launch_bounds__(384) poolsutt_kernel(
        const int* __restrict__ sents,
        const float* __restrict__ b3, const float* __restrict__ b4,
        const float* __restrict__ b5, const float* __restrict__ tb) {
    extern __shared__ char psm[];
    __half* Zs   = reinterpret_cast<__half*>(psm);
    int*    toks = reinterpret_cast<int*>(psm + 76800);
    float*  pmax = reinterpret_cast<float*>(psm + 77000);
    float*  fsh  = reinterpret_cast<float*>(psm + 78536);
    const int n = blockIdx.x;
    const int tid = threadIdx.x;

    if (tid < SL) toks[tid] = sents[n*SL + tid];
    __syncthreads();
    {
        uint4* Zs4 = reinterpret_cast<uint4*>(Zs);
        const uint4* Zg4 = reinterpret_cast<const uint4*>(g_Zh);
        for (int i = tid; i < SL*96; i += 384) {
            int row = i / 96, c4 = i - row*96;
            Zs4[i] = Zg4[(size_t)toks[row]*96 + c4];
        }
    }
    __syncthreads();
    {
        const int half = tid / FCAT;
        const int f = tid - half*FCAT;
        const int fi = f >> 6, o = f & 63;
        const int fs  = 3 + fi;
        const int off = (fi == 0) ? 0 : (fi == 1) ? 192 : 448;
        const int T = SL - fs + 1;
        const int t0 = half ? (T >> 1) : 0;
        const int t1 = half ? T : (T >> 1);
        float mx = -1e30f;
        for (int t = t0; t < t1; t++) {
            float v = 0.f;
            #pragma unroll 5
            for (int dt = 0; dt < fs; dt++)
                v += __half2float(Zs[(t + dt)*NCOL + off + dt*64 + o]);
            mx = fmaxf(mx, v);
        }
        pmax[tid] = mx;
    }
    __syncthreads();
    if (tid < FCAT) {
        int fi = tid >> 6, o = tid & 63;
        float bias = (fi == 0) ? b3[o] : (fi == 1) ? b4[o] : b5[o];
        float mx = fmaxf(pmax[tid], pmax[tid + FCAT]);
        fsh[tid] = fmaxf(0.f, mx + bias);
    }
    __syncthreads();
    if (tid < DOUT) {
        float acc = tb[tid];
        #pragma unroll 8
        for (int j = 0; j < FCAT; j++) acc += fsh[j] * g_twT[j*DOUT + tid];
        g_sutt[n*DOUT + tid] = tanhf(acc);
    }
}

// ---------------- GRU input projection ----------------
__global__ void __launch_bounds__(256) xproj_kernel(
        const float* __restrict__ wih, const float* __restrict__ bih) {
    __shared__ float ss[16][DOUT];
    const int tid = threadIdx.x;
    const int v0 = blockIdx.x * 16;
    for (int idx = tid; idx < 16*DOUT; idx += 256) {
        int r = idx / DOUT, d = idx % DOUT;
        int v = v0 + r;
        ss[r][d] = (v < NB) ? g_sutt[v*DOUT + d] : 0.f;
    }
    __syncthreads();
    for (int idx = tid; idx < 16*3*DOUT; idx += 256) {
        int j = idx >> 4, r = idx & 15;
        int v = v0 + r;
        if (v >= NB) continue;
        const float4* wI = reinterpret_cast<const float4*>(wih + j*DOUT);
        const float4* xv = reinterpret_cast<const float4*>(ss[r]);
        float acc = 0.f;
        #pragma unroll
        for (int k = 0; k < DOUT/4; k++) {
            float4 w = wI[k], x = xv[k];
            acc += w.x*x.x + w.y*x.y + w.z*x.z + w.w*x.w;
        }
        g_xproj[v*3*DOUT + j] = acc + bih[j];
    }
}

// ---------------- fused GRU: weights-in-registers, broadcast-h ----------------
#define GRB 16
#define GRU_T 320
__global__ void __launch_bounds__(GRU_T) gru_fused(
        const float* __restrict__ whh, const float* __restrict__ bhh,
        const float* __restrict__ bih) {
    __shared__ float hs[GRB*DOUT];
    __shared__ float gh[GRB*3*DOUT];
    const int tid = threadIdx.x;
    const int b0 = blockIdx.x * GRB;
    const int j = tid;
    const bool active = (j < 3*DOUT);

    float w[DOUT];
    float bh = 0.f;
    if (active) {
        const float4* wr = reinterpret_cast<const float4*>(whh + j*DOUT);
        #pragma unroll
        for (int k4 = 0; k4 < DOUT/4; k4++) {
            float4 v = wr[k4];
            w[4*k4] = v.x; w[4*k4+1] = v.y; w[4*k4+2] = v.z; w[4*k4+3] = v.w;
        }
        bh = bhh[j];
    }
    for (int i = tid; i < GRB*DOUT; i += GRU_T) hs[i] = 0.f;
    __syncthreads();

    for (int s = 0; s < WIND; s++) {
        if (active) {
            #pragma unroll
            for (int r = 0; r < GRB; r++) {
                const float4* h4 = reinterpret_cast<const float4*>(hs + r*DOUT);
                float acc = 0.f;
                #pragma unroll
                for (int k4 = 0; k4 < DOUT/4; k4++) {
                    float4 h = h4[k4];
                    acc += w[4*k4]*h.x + w[4*k4+1]*h.y + w[4*k4+2]*h.z + w[4*k4+3]*h.w;
                }
                gh[r*3*DOUT + j] = acc + bh;
            }
        }
        __syncthreads();
        for (int idx = tid; idx < GRB*DOUT; idx += GRU_T) {
            int r = idx / DOUT, d = idx - r*DOUT;
            int b = b0 + r;
            if (b < NB) {
                int src = b + s - (WIND - 1);
                float giR, giZ, giN, xv;
                if (src >= 0) {
                    const float* xp = g_xproj + src*3*DOUT;
                    giR = xp[d]; giZ = xp[DOUT + d]; giN = xp[2*DOUT + d];
                    xv = g_sutt[src*DOUT + d];
                } else {
                    giR = bih[d]; giZ = bih[DOUT + d]; giN = bih[2*DOUT + d];
                    xv = 0.f;
                }
                float hr = gh[r*3*DOUT + d];
                float hz = gh[r*3*DOUT + DOUT + d];
                float hn = gh[r*3*DOUT + 2*DOUT + d];
                float rr = 1.f / (1.f + expf(-(giR + hr)));
                float zz = 1.f / (1.f + expf(-(giZ + hz)));
                float nn = tanhf(giN + rr*hn);
                float hnew = (1.f - zz)*nn + zz*hs[r*DOUT + d];
                hs[r*DOUT + d] = hnew;
                g_memb[(b*WIND + s)*DOUT + d] = xv + hnew;
            }
        }
        __syncthreads();
    }
}

// ---------------- 3-hop attention: warp per window, register M --------------
__global__ void __launch_bounds__(256) attn_kernel(float* __restrict__ attn_out) {
    const int w = blockIdx.x * 8 + (threadIdx.x >> 5);
    const int lane = threadIdx.x & 31;
    if (w >= NB) return;

    float M[WIND][4], q[4];
    #pragma unroll
    for (int jj = 0; jj < 4; jj++) {
        int d = lane + 32*jj;
        bool ok = d < DOUT;
        q[jj] = ok ? g_sutt[(w + 1)*DOUT + d] : 0.f;
        #pragma unroll
        for (int k = 0; k < WIND; k++)
            M[k][jj] = ok ? g_memb[(w*WIND + k)*DOUT + d] : 0.f;
    }

    #pragma unroll
    for (int hop = 0; hop < HOPS; hop++) {
        float l[WIND];
        #pragma unroll
        for (int k = 0; k < WIND; k++) {
            float p = q[0]*M[k][0] + q[1]*M[k][1] + q[2]*M[k][2] + q[3]*M[k][3];
            #pragma unroll
            for (int off = 16; off; off >>= 1)
                p += __shfl_xor_sync(0xFFFFFFFFu, p, off);
            l[k] = (w + k - (WIND - 1) >= 0) ? p : -1e10f;
        }
        float mx = l[0];
        #pragma unroll
        for (int k = 1; k < WIND; k++) mx = fmaxf(mx, l[k]);
        float a[WIND], sum = 0.f;
        #pragma unroll
        for (int k = 0; k < WIND; k++) { a[k] = expf(l[k] - mx); sum += a[k]; }
        float inv = 1.f / sum;
        #pragma unroll
        for (int k = 0; k < WIND; k++) {
            a[k] *= inv;
            if (lane == k) attn_out[hop*(NB*WIND) + w*WIND + k] = a[k];
        }
        #pragma unroll
        for (int jj = 0; jj < 4; jj++) {
            float acc = 0.f;
            #pragma unroll
            for (int k = 0; k < WIND; k++) acc += a[k] * M[k][jj];
            q[jj] += acc;
        }
    }
    #pragma unroll
    for (int jj = 0; jj < 4; jj++) {
        int d = lane + 32*jj;
        if (d < DOUT) g_q[w*DOUT + d] = q[jj];
    }
}

// ---------------- classifier + log_softmax ----------------
__global__ void cls_kernel(const float* __restrict__ cw,
                           const float* __restrict__ cb,
                           float* __restrict__ pred_out) {
    int row = blockIdx.x * blockDim.x + threadIdx.x;
    if (row >= NU) return;
    const float* s = (row == 0) ? g_sutt : (g_q + (row - 1)*DOUT);
    float lg[NC];
    #pragma unroll
    for (int c = 0; c < NC; c++) {
        float acc = cb[c];
        const float* wr = cw + c*DOUT;
        #pragma unroll 4
        for (int k = 0; k < DOUT; k++) acc += s[k] * wr[k];
        lg[c] = acc;
    }
    float mx = lg[0];
    #pragma unroll
    for (int c = 1; c < NC; c++) mx = fmaxf(mx, lg[c]);
    float sum = 0.f;
    #pragma unroll
    for (int c = 0; c < NC; c++) sum += expf(lg[c] - mx);
    float lse = mx + logf(sum);
    #pragma unroll
    for (int c = 0; c < NC; c++) pred_out[row*NC + c] = lg[c] - lse;
}

// ---------------- launch sequence ----------------
extern "C" void kernel_launch(void* const* d_in, const int* in_sizes, int n_in,
                              void* d_out, int out_size) {
    const int*   sents   = (const int*)  d_in[0];
    const float* emb     = (const float*)d_in[2];
    const float* trans_w = (const float*)d_in[3];
    const float* trans_b = (const float*)d_in[4];
    const float* gru_wih = (const float*)d_in[5];
    const float* gru_whh = (const float*)d_in[6];
    const float* gru_bih = (const float*)d_in[7];
    const float* gru_bhh = (const float*)d_in[8];
    const float* cls_w   = (const float*)d_in[9];
    const float* cls_b   = (const float*)d_in[10];
    const float* conv_w3 = (const float*)d_in[11];
    const float* conv_b3 = (const float*)d_in[12];
    const float* conv_w4 = (const float*)d_in[13];
    const float* conv_b4 = (const float*)d_in[14];
    const float* conv_w5 = (const float*)d_in[15];
    const float* conv_b5 = (const float*)d_in[16];

    float* outF = (float*)d_out;
    float* pred_out = outF;
    float* attn_out;
    if (out_size >= NU*NC + HOPS*NB*WIND) attn_out = outF + NU*NC;
    else cudaGetSymbolAddress((void**)&attn_out, g_attn_scratch);

    cudaFuncSetAttribute(conv_gemm_mma,   cudaFuncAttributeMaxDynamicSharedMemorySize, GEMM_SMEM);
    cudaFuncSetAttribute(poolsutt_kernel, cudaFuncAttributeMaxDynamicSharedMemorySize, POOL_SMEM);
    cudaFuncSetAttribute(pack_Ah,         cudaFuncAttributeMaxDynamicSharedMemorySize, PACKA_SMEM);

    pack_Ah<<<VPAD/128, 256, PACKA_SMEM>>>(emb);
    pack_Bh<<<(NCOL*KPAD/8 + 255)/256, 256>>>(conv_w3, conv_w4, conv_w5);
    transpose_tw<<<(FCAT*DOUT + 255)/256, 256>>>(trans_w);

    dim3 ggrid(NCOL/128, VPAD/128);   // (6, 391)
    conv_gemm_mma<<<ggrid, 256, GEMM_SMEM>>>();

    poolsutt_kernel<<<NU, 384, POOL_SMEM>>>(sents, conv_b3, conv_b4, conv_b5, trans_b);
    xproj_kernel<<<(NB + 15)/16, 256>>>(gru_wih, gru_bih);
    gru_fused<<<(NB + GRB - 1)/GRB, GRU_T>>>(gru_whh, gru_bhh, gru_bih);

    attn_kernel<<<(NB + 7)/8, 256>>>(attn_out);
    cls_kernel<<<(NU + 255)/256, 256>>>(cls_w, cls_b, pred_out);
}

// round 11
// speedup vs baseline: 1.1213x; 1.1213x over previous
#include <cuda_runtime.h>
#include <cuda_fp16.h>
#include <math.h>
#include <stdint.h>

// ---------------- problem constants ----------------
#define NU    2048
#define SL    50
#define DE    300
#define KPAD  320      // 20 k-groups of 16; 10 chunks of 32
#define DOUT  100
#define NC    7
#define WIND  10
#define HOPS  3
#define NB    2047
#define VOCAB 50000
#define VPAD  50048    // 391 * 128
#define NCOL  768
#define FCAT  192

// ---------------- static scratch ----------------
__device__ __half g_Ah[(size_t)VPAD*KPAD];      // A fp16 fragment order (128-row mblk)
__device__ __half g_Bh[NCOL*KPAD];              // B fp16 nt-pair fragment order (128-col nblk)
__device__ __half g_Zh[(size_t)VPAD*NCOL];      // fp16 projections (77 MB)
__device__ float g_twT[FCAT*DOUT];
__device__ float g_sutt[NU*DOUT];
__device__ float g_xproj[NB*3*DOUT];
__device__ float g_memb[NB*WIND*DOUT];
__device__ float g_q[NB*DOUT];
__device__ float g_attn_scratch[HOPS*NB*WIND];

// ---------------- helpers ----------------
__device__ __forceinline__ uint32_t smem_u32(const void* p) {
    uint32_t a;
    asm("{ .reg .u64 t; cvta.to.shared.u64 t, %1; cvt.u32.u64 %0, t; }" : "=r"(a) : "l"(p));
    return a;
}
#define CP_ASYNC16(sa, gp) asm volatile("cp.async.cg.shared.global [%0], [%1], 16;" :: "r"(sa), "l"(gp) : "memory")
#define CP_COMMIT()        asm volatile("cp.async.commit_group;" ::: "memory")
#define CP_WAIT(n)         asm volatile("cp.async.wait_group %0;" :: "n"(n) : "memory")

__device__ __forceinline__ void mma_fp16(float* d, const uint32_t* a, const uint32_t* b) {
    asm volatile("mma.sync.aligned.m16n8k16.row.col.f32.f16.f16.f32 "
        "{%0,%1,%2,%3}, {%4,%5,%6,%7}, {%8,%9}, {%0,%1,%2,%3};"
        : "+f"(d[0]), "+f"(d[1]), "+f"(d[2]), "+f"(d[3])
        : "r"(a[0]), "r"(a[1]), "r"(a[2]), "r"(a[3]), "r"(b[0]), "r"(b[1]));
}

// ---------------- pack A: coalesced read -> smem -> fragment-order write ----
#define PA_LDK 328
#define PACKA_SMEM (128*PA_LDK*2)
__global__ void __launch_bounds__(256) pack_Ah(const float* __restrict__ emb) {
    extern __shared__ __half sa[];
    const int tid = threadIdx.x;
    const int mblk = blockIdx.x;

    {
        uint4* s4 = reinterpret_cast<uint4*>(sa);
        for (int i = tid; i < 128*PA_LDK/8; i += 256)
            s4[i] = make_uint4(0, 0, 0, 0);
    }
    __syncthreads();
    {
        const float4* e4 = reinterpret_cast<const float4*>(emb);
        for (int i = tid; i < 128*75; i += 256) {
            int row = i / 75, c4 = i - row*75;
            int m = mblk*128 + row;
            if (m < VOCAB) {
                float4 v = e4[(size_t)m*75 + c4];
                __half2 lo = __floats2half2_rn(v.x, v.y);
                __half2 hi = __floats2half2_rn(v.z, v.w);
                uint2 pk = make_uint2(*(uint32_t*)&lo, *(uint32_t*)&hi);
                *reinterpret_cast<uint2*>(sa + row*PA_LDK + c4*4) = pk;
            }
        }
    }
    __syncthreads();
    {
        const int lane = tid & 31;
        const int r16  = tid >> 5;
        const int mloc = r16*16 + (lane >> 2);
        const int kk   = (lane & 3)*2;
        const uint32_t* s32 = reinterpret_cast<const uint32_t*>(sa);
        uint4* out4 = reinterpret_cast<uint4*>(g_Ah);
        #pragma unroll 4
        for (int kc16 = 0; kc16 < 20; kc16++) {
            int k = kc16*16 + kk;
            uint32_t h0 = s32[( mloc      *PA_LDK + k    ) >> 1];
            uint32_t h1 = s32[((mloc + 8)*PA_LDK + k    ) >> 1];
            uint32_t h2 = s32[( mloc      *PA_LDK + k + 8) >> 1];
            uint32_t h3 = s32[((mloc + 8)*PA_LDK + k + 8) >> 1];
            out4[((size_t)(mblk*20 + kc16)*8 + r16)*32 + lane] = make_uint4(h0, h1, h2, h3);
        }
    }
}

// ---------------- merged pack B + transpose_tw (one launch) -----------------
__device__ __forceinline__ __half wall_h(const float* w3, const float* w4,
                                         const float* w5, int c, int k) {
    if (k >= DE) return __float2half_rn(0.f);
    float v;
    if (c < 192)      { int cc = c;       int dt = cc >> 6, o = cc & 63; v = w3[(o*3 + dt)*DE + k]; }
    else if (c < 448) { int cc = c - 192; int dt = cc >> 6, o = cc & 63; v = w4[(o*4 + dt)*DE + k]; }
    else              { int cc = c - 448; int dt = cc >> 6, o = cc & 63; v = w5[(o*5 + dt)*DE + k]; }
    return __float2half_rn(v);
}
#define PB_BLOCKS 120          // 30720 d4 / 256
#define TW_BLOCKS 75           // 19200 / 256
__global__ void pack_misc(const float* __restrict__ w3,
                          const float* __restrict__ w4,
                          const float* __restrict__ w5,
                          const float* __restrict__ tw) {
    if (blockIdx.x < PB_BLOCKS) {
        int d4 = blockIdx.x * 256 + threadIdx.x;
        int lane = d4 & 31;
        int np   = (d4 >> 5) & 7;
        int rest = d4 >> 8;
        int kc16 = rest % 20;
        int nblk = rest / 20;
        int na = nblk*128 + np*16 + (lane >> 2);
        int nb = na + 8;
        int k = kc16*16 + (lane & 3)*2;
        __half2 h0 = __halves2half2(wall_h(w3,w4,w5, na, k),     wall_h(w3,w4,w5, na, k + 1));
        __half2 h1 = __halves2half2(wall_h(w3,w4,w5, na, k + 8), wall_h(w3,w4,w5, na, k + 9));
        __half2 h2 = __halves2half2(wall_h(w3,w4,w5, nb, k),     wall_h(w3,w4,w5, nb, k + 1));
        __half2 h3 = __halves2half2(wall_h(w3,w4,w5, nb, k + 8), wall_h(w3,w4,w5, nb, k + 9));
        uint4 v = make_uint4(*(uint32_t*)&h0, *(uint32_t*)&h1, *(uint32_t*)&h2, *(uint32_t*)&h3);
        reinterpret_cast<uint4*>(g_Bh)[d4] = v;
    } else {
        int idx = (blockIdx.x - PB_BLOCKS) * 256 + threadIdx.x;
        if (idx < FCAT*DOUT) {
            int j = idx / DOUT, d = idx % DOUT;
            g_twT[idx] = tw[d*FCAT + j];
        }
    }
}

// ---------------- fp16 mma GEMM: Z = Ah @ Bh^T (fp16 out) ----------------
// CTA 128x128, 256 thr = 8 warps (4M x 2N), warp tile 32x64, 2 CTAs/SM.
#define GEMM_SMEM 49152

__global__ void __launch_bounds__(256, 2) conv_gemm_mma() {
    extern __shared__ char smc[];
    const int tid  = threadIdx.x;
    const int lane = tid & 31, wid = tid >> 5;
    const int warp_m = wid & 3;
    const int warp_n = wid >> 2;
    const int by = blockIdx.y, bx = blockIdx.x;
    const int m0 = by * 128, n0 = bx * 128;

    const uint32_t smb = smem_u32(smc);
    const uint4* Ah4 = reinterpret_cast<const uint4*>(g_Ah);
    const uint4* Bh4 = reinterpret_cast<const uint4*>(g_Bh);

    float acc[2][8][4];
    #pragma unroll
    for (int mt = 0; mt < 2; mt++)
        #pragma unroll
        for (int nt = 0; nt < 8; nt++)
            #pragma unroll
            for (int i = 0; i < 4; i++) acc[mt][nt][i] = 0.f;

    #pragma unroll
    for (int c = 0; c < 2; c++) {
        size_t aG = ((size_t)by*20 + c*2) * 256;
        size_t bG = ((size_t)bx*20 + c*2) * 256;
        #pragma unroll
        for (int i = 0; i < 2; i++) {
            CP_ASYNC16(smb +         c*8192 + (tid + i*256)*16, Ah4 + aG + tid + i*256);
            CP_ASYNC16(smb + 24576 + c*8192 + (tid + i*256)*16, Bh4 + bG + tid + i*256);
        }
        CP_COMMIT();
    }

    for (int c = 0; c < 10; c++) {
        const int buf = c % 3;
        if (c < 9) CP_WAIT(1); else CP_WAIT(0);
        __syncthreads();
        if (c + 2 < 10) {
            const int nb = (c + 2) % 3;
            size_t aG = ((size_t)by*20 + (c + 2)*2) * 256;
            size_t bG = ((size_t)bx*20 + (c + 2)*2) * 256;
            #pragma unroll
            for (int i = 0; i < 2; i++) {
                CP_ASYNC16(smb +         nb*8192 + (tid + i*256)*16, Ah4 + aG + tid + i*256);
                CP_ASYNC16(smb + 24576 + nb*8192 + (tid + i*256)*16, Bh4 + bG + tid + i*256);
            }
            CP_COMMIT();
        }

        const uint4* A4 = reinterpret_cast<const uint4*>(smc + buf*8192);
        const uint4* B4 = reinterpret_cast<const uint4*>(smc + 24576 + buf*8192);
        #pragma unroll
        for (int ks = 0; ks < 2; ks++) {
            uint32_t a[2][4], b[8][2];
            #pragma unroll
            for (int mt = 0; mt < 2; mt++) {
                uint4 v = A4[(ks*8 + warp_m*2 + mt)*32 + lane];
                a[mt][0] = v.x; a[mt][1] = v.y; a[mt][2] = v.z; a[mt][3] = v.w;
            }
            #pragma unroll
            for (int np = 0; np < 4; np++) {
                uint4 u = B4[(ks*8 + warp_n*4 + np)*32 + lane];
                b[2*np  ][0] = u.x; b[2*np  ][1] = u.y;
                b[2*np+1][0] = u.z; b[2*np+1][1] = u.w;
            }
            #pragma unroll
            for (int mt = 0; mt < 2; mt++)
                #pragma unroll
                for (int nt = 0; nt < 8; nt++)
                    mma_fp16(acc[mt][nt], a[mt], b[nt]);
        }
    }

    __half2* Z2 = reinterpret_cast<__half2*>(g_Zh);
    #pragma unroll
    for (int mt = 0; mt < 2; mt++) {
        int r = m0 + warp_m*32 + mt*16 + (lane >> 2);
        #pragma unroll
        for (int nt = 0; nt < 8; nt++) {
            int cc = n0 + warp_n*64 + nt*8 + (lane & 3)*2;
            Z2[((size_t) r      *NCOL + cc) >> 1] = __floats2half2_rn(acc[mt][nt][0], acc[mt][nt][1]);
            Z2[((size_t)(r + 8)*NCOL + cc) >> 1] = __floats2half2_rn(acc[mt][nt][2], acc[mt][nt][3]);
        }
    }
}

// ---------------- fused pool + relu + tanh projection -----------------------
// cp.async staging (fire-and-forget MLP), 768 thr, 4-way t-split.
// smem: Zs[76800] | toks@76800 | pmax@77000 (768 f) | fsh@80072 (192 f)
#define POOL_T 768
#define POOL_SMEM (76800 + 200 + 3072 + 768)
__global__ void __launch_bounds__(POOL_T) poolsutt_kernel(
        const int* __restrict__ sents,
        const float* __restrict__ b3, const float* __restrict__ b4,
        const float* __restrict__ b5, const float* __restrict__ tb) {
    extern __shared__ char psm[];
    __half* Zs   = reinterpret_cast<__half*>(psm);
    int*    toks = reinterpret_cast<int*>(psm + 76800);
    float*  pmax = reinterpret_cast<float*>(psm + 77000);
    float*  fsh  = reinterpret_cast<float*>(psm + 80072);
    const int n = blockIdx.x;
    const int tid = threadIdx.x;
    const uint32_t zsb = smem_u32(Zs);

    if (tid < SL) toks[tid] = sents[n*SL + tid];
    __syncthreads();

    // stage 50 rows x 96 uint4 via cp.async (independent, high MLP)
    {
        const uint4* Zg4 = reinterpret_cast<const uint4*>(g_Zh);
        for (int i = tid; i < SL*96; i += POOL_T) {
            int row = i / 96, c4 = i - row*96;
            CP_ASYNC16(zsb + i*16, Zg4 + (size_t)toks[row]*96 + c4);
        }
        CP_COMMIT();
        CP_WAIT(0);
    }
    __syncthreads();

    // pool from smem (4-way t-split)
    {
        const int q = tid / FCAT;            // 0..3
        const int f = tid - q*FCAT;
        const int fi = f >> 6, o = f & 63;
        const int fs  = 3 + fi;
        const int off = (fi == 0) ? 0 : (fi == 1) ? 192 : 448;
        const int T = SL - fs + 1;
        const int t0 = (T * q) >> 2;
        const int t1 = (T * (q + 1)) >> 2;
        float mx = -1e30f;
        for (int t = t0; t < t1; t++) {
            float v = 0.f;
            #pragma unroll 5
            for (int dt = 0; dt < fs; dt++)
                v += __half2float(Zs[(t + dt)*NCOL + off + dt*64 + o]);
            mx = fmaxf(mx, v);
        }
        pmax[tid] = mx;
    }
    __syncthreads();
    if (tid < FCAT) {
        int fi = tid >> 6, o = tid & 63;
        float bias = (fi == 0) ? b3[o] : (fi == 1) ? b4[o] : b5[o];
        float mx = fmaxf(fmaxf(pmax[tid], pmax[tid + FCAT]),
                         fmaxf(pmax[tid + 2*FCAT], pmax[tid + 3*FCAT]));
        fsh[tid] = fmaxf(0.f, mx + bias);
    }
    __syncthreads();
    if (tid < DOUT) {
        float acc = tb[tid];
        #pragma unroll 8
        for (int j = 0; j < FCAT; j++) acc += fsh[j] * g_twT[j*DOUT + tid];
        g_sutt[n*DOUT + tid] = tanhf(acc);
    }
}

// ---------------- GRU input projection ----------------
__global__ void __launch_bounds__(256) xproj_kernel(
        const float* __restrict__ wih, const float* __restrict__ bih) {
    __shared__ float ss[16][DOUT];
    const int tid = threadIdx.x;
    const int v0 = blockIdx.x * 16;
    for (int idx = tid; idx < 16*DOUT; idx += 256) {
        int r = idx / DOUT, d = idx % DOUT;
        int v = v0 + r;
        ss[r][d] = (v < NB) ? g_sutt[v*DOUT + d] : 0.f;
    }
    __syncthreads();
    for (int idx = tid; idx < 16*3*DOUT; idx += 256) {
        int j = idx >> 4, r = idx & 15;
        int v = v0 + r;
        if (v >= NB) continue;
        const float4* wI = reinterpret_cast<const float4*>(wih + j*DOUT);
        const float4* xv = reinterpret_cast<const float4*>(ss[r]);
        float acc = 0.f;
        #pragma unroll
        for (int k = 0; k < DOUT/4; k++) {
            float4 w = wI[k], x = xv[k];
            acc += w.x*x.x + w.y*x.y + w.z*x.z + w.w*x.w;
        }
        g_xproj[v*3*DOUT + j] = acc + bih[j];
    }
}

// ---------------- fused GRU: weights-in-registers, broadcast-h ---------------
#define GRB 16
#define GRU_T 320
__global__ void __launch_bounds__(GRU_T) gru_fused(
        const float* __restrict__ whh, const float* __restrict__ bhh,
        const float* __restrict__ bih) {
    __shared__ float hs[GRB*DOUT];
    __shared__ float gh[GRB*3*DOUT];
    const int tid = threadIdx.x;
    const int b0 = blockIdx.x * GRB;
    const int j = tid;
    const bool active = (j < 3*DOUT);

    float w[DOUT];
    float bh = 0.f;
    if (active) {
        const float4* wr = reinterpret_cast<const float4*>(whh + j*DOUT);
        #pragma unroll
        for (int k4 = 0; k4 < DOUT/4; k4++) {
            float4 v = wr[k4];
            w[4*k4] = v.x; w[4*k4+1] = v.y; w[4*k4+2] = v.z; w[4*k4+3] = v.w;
        }
        bh = bhh[j];
    }
    for (int i = tid; i < GRB*DOUT; i += GRU_T) hs[i] = 0.f;
    __syncthreads();

    for (int s = 0; s < WIND; s++) {
        if (active) {
            #pragma unroll
            for (int r = 0; r < GRB; r++) {
                const float4* h4 = reinterpret_cast<const float4*>(hs + r*DOUT);
                float acc = 0.f;
                #pragma unroll
                for (int k4 = 0; k4 < DOUT/4; k4++) {
                    float4 h = h4[k4];
                    acc += w[4*k4]*h.x + w[4*k4+1]*h.y + w[4*k4+2]*h.z + w[4*k4+3]*h.w;
                }
                gh[r*3*DOUT + j] = acc + bh;
            }
        }
        __syncthreads();
        for (int idx = tid; idx < GRB*DOUT; idx += GRU_T) {
            int r = idx / DOUT, d = idx - r*DOUT;
            int b = b0 + r;
            if (b < NB) {
                int src = b + s - (WIND - 1);
                float giR, giZ, giN, xv;
                if (src >= 0) {
                    const float* xp = g_xproj + src*3*DOUT;
                    giR = xp[d]; giZ = xp[DOUT + d]; giN = xp[2*DOUT + d];
                    xv = g_sutt[src*DOUT + d];
                } else {
                    giR = bih[d]; giZ = bih[DOUT + d]; giN = bih[2*DOUT + d];
                    xv = 0.f;
                }
                float hr = gh[r*3*DOUT + d];
                float hz = gh[r*3*DOUT + DOUT + d];
                float hn = gh[r*3*DOUT + 2*DOUT + d];
                float rr = 1.f / (1.f + expf(-(giR + hr)));
                float zz = 1.f / (1.f + expf(-(giZ + hz)));
                float nn = tanhf(giN + rr*hn);
                float hnew = (1.f - zz)*nn + zz*hs[r*DOUT + d];
                hs[r*DOUT + d] = hnew;
                g_memb[(b*WIND + s)*DOUT + d] = xv + hnew;
            }
        }
        __syncthreads();
    }
}

// ---------------- 3-hop attention: warp per window, register M --------------
__global__ void __launch_bounds__(256) attn_kernel(float* __restrict__ attn_out) {
    const int w = blockIdx.x * 8 + (threadIdx.x >> 5);
    const int lane = threadIdx.x & 31;
    if (w >= NB) return;

    float M[WIND][4], q[4];
    #pragma unroll
    for (int jj = 0; jj < 4; jj++) {
        int d = lane + 32*jj;
        bool ok = d < DOUT;
        q[jj] = ok ? g_sutt[(w + 1)*DOUT + d] : 0.f;
        #pragma unroll
        for (int k = 0; k < WIND; k++)
            M[k][jj] = ok ? g_memb[(w*WIND + k)*DOUT + d] : 0.f;
    }

    #pragma unroll
    for (int hop = 0; hop < HOPS; hop++) {
        float l[WIND];
        #pragma unroll
        for (int k = 0; k < WIND; k++) {
            float p = q[0]*M[k][0] + q[1]*M[k][1] + q[2]*M[k][2] + q[3]*M[k][3];
            #pragma unroll
            for (int off = 16; off; off >>= 1)
                p += __shfl_xor_sync(0xFFFFFFFFu, p, off);
            l[k] = (w + k - (WIND - 1) >= 0) ? p : -1e10f;
        }
        float mx = l[0];
        #pragma unroll
        for (int k = 1; k < WIND; k++) mx = fmaxf(mx, l[k]);
        float a[WIND], sum = 0.f;
        #pragma unroll
        for (int k = 0; k < WIND; k++) { a[k] = expf(l[k] - mx); sum += a[k]; }
        float inv = 1.f / sum;
        #pragma unroll
        for (int k = 0; k < WIND; k++) {
            a[k] *= inv;
            if (lane == k) attn_out[hop*(NB*WIND) + w*WIND + k] = a[k];
        }
        #pragma unroll
        for (int jj = 0; jj < 4; jj++) {
            float acc = 0.f;
            #pragma unroll
            for (int k = 0; k < WIND; k++) acc += a[k] * M[k][jj];
            q[jj] += acc;
        }
    }
    #pragma unroll
    for (int jj = 0; jj < 4; jj++) {
        int d = lane + 32*jj;
        if (d < DOUT) g_q[w*DOUT + d] = q[jj];
    }
}

// ---------------- classifier + log_softmax ----------------
__global__ void cls_kernel(const float* __restrict__ cw,
                           const float* __restrict__ cb,
                           float* __restrict__ pred_out) {
    int row = blockIdx.x * blockDim.x + threadIdx.x;
    if (row >= NU) return;
    const float* s = (row == 0) ? g_sutt : (g_q + (row - 1)*DOUT);
    float lg[NC];
    #pragma unroll
    for (int c = 0; c < NC; c++) {
        float acc = cb[c];
        const float* wr = cw + c*DOUT;
        #pragma unroll 4
        for (int k = 0; k < DOUT; k++) acc += s[k] * wr[k];
        lg[c] = acc;
    }
    float mx = lg[0];
    #pragma unroll
    for (int c = 1; c < NC; c++) mx = fmaxf(mx, lg[c]);
    float sum = 0.f;
    #pragma unroll
    for (int c = 0; c < NC; c++) sum += expf(lg[c] - mx);
    float lse = mx + logf(sum);
    #pragma unroll
    for (int c = 0; c < NC; c++) pred_out[row*NC + c] = lg[c] - lse;
}

// ---------------- launch sequence ----------------
extern "C" void kernel_launch(void* const* d_in, const int* in_sizes, int n_in,
                              void* d_out, int out_size) {
    const int*   sents   = (const int*)  d_in[0];
    const float* emb     = (const float*)d_in[2];
    const float* trans_w = (const float*)d_in[3];
    const float* trans_b = (const float*)d_in[4];
    const float* gru_wih = (const float*)d_in[5];
    const float* gru_whh = (const float*)d_in[6];
    const float* gru_bih = (const float*)d_in[7];
    const float* gru_bhh = (const float*)d_in[8];
    const float* cls_w   = (const float*)d_in[9];
    const float* cls_b   = (const float*)d_in[10];
    const float* conv_w3 = (const float*)d_in[11];
    const float* conv_b3 = (const float*)d_in[12];
    const float* conv_w4 = (const float*)d_in[13];
    const float* conv_b4 = (const float*)d_in[14];
    const float* conv_w5 = (const float*)d_in[15];
    const float* conv_b5 = (const float*)d_in[16];

    float* outF = (float*)d_out;
    float* pred_out = outF;
    float* attn_out;
    if (out_size >= NU*NC + HOPS*NB*WIND) attn_out = outF + NU*NC;
    else cudaGetSymbolAddress((void**)&attn_out, g_attn_scratch);

    cudaFuncSetAttribute(conv_gemm_mma,   cudaFuncAttributeMaxDynamicSharedMemorySize, GEMM_SMEM);
    cudaFuncSetAttribute(poolsutt_kernel, cudaFuncAttributeMaxDynamicSharedMemorySize, POOL_SMEM);
    cudaFuncSetAttribute(pack_Ah,         cudaFuncAttributeMaxDynamicSharedMemorySize, PACKA_SMEM);

    // launch order chosen so poolsutt is the 4th launch (ncu capture slot)
    pack_Ah<<<VPAD/128, 256, PACKA_SMEM>>>(emb);
    pack_misc<<<PB_BLOCKS + TW_BLOCKS, 256>>>(conv_w3, conv_w4, conv_w5, trans_w);

    dim3 ggrid(NCOL/128, VPAD/128);   // (6, 391)
    conv_gemm_mma<<<ggrid, 256, GEMM_SMEM>>>();

    poolsutt_kernel<<<NU, POOL_T, POOL_SMEM>>>(sents, conv_b3, conv_b4, conv_b5, trans_b);
    xproj_kernel<<<(NB + 15)/16, 256>>>(gru_wih, gru_bih);
    gru_fused<<<(NB + GRB - 1)/GRB, GRU_T>>>(gru_whh, gru_bhh, gru_bih);

    attn_kernel<<<(NB + 7)/8, 256>>>(attn_out);
    cls_kernel<<<(NU + 255)/256, 256>>>(cls_w, cls_b, pred_out);
}

// round 12
// speedup vs baseline: 1.1288x; 1.0066x over previous
#include <cuda_runtime.h>
#include <cuda_fp16.h>
#include <math.h>
#include <stdint.h>

// ---------------- problem constants ----------------
#define NU    2048
#define SL    50
#define DE    300
#define KPAD  320      // 20 k-groups of 16
#define DOUT  100
#define NC    7
#define WIND  10
#define HOPS  3
#define NB    2047
#define VOCAB 50000
#define VPAD  50048    // 391 * 128
#define NCOL  768
#define FCAT  192

// ---------------- static scratch ----------------
__device__ __half g_Ah[(size_t)VPAD*KPAD];      // A fp16 fragment order (128-row mblk)
__device__ __half g_Bh[NCOL*KPAD];              // B fp16 nt-pair fragment order (128-col nblk)
__device__ __half g_Zh[(size_t)VPAD*NCOL];      // fp16 projections (77 MB)
__device__ float g_twT[FCAT*DOUT];
__device__ float g_sutt[NU*DOUT];
__device__ float g_memb[NB*WIND*DOUT];
__device__ float g_q[NB*DOUT];
__device__ float g_attn_scratch[HOPS*NB*WIND];

// ---------------- helpers ----------------
__device__ __forceinline__ uint32_t smem_u32(const void* p) {
    uint32_t a;
    asm("{ .reg .u64 t; cvta.to.shared.u64 t, %1; cvt.u32.u64 %0, t; }" : "=r"(a) : "l"(p));
    return a;
}
#define CP_ASYNC16(sa, gp) asm volatile("cp.async.cg.shared.global [%0], [%1], 16;" :: "r"(sa), "l"(gp) : "memory")
#define CP_COMMIT()        asm volatile("cp.async.commit_group;" ::: "memory")
#define CP_WAIT(n)         asm volatile("cp.async.wait_group %0;" :: "n"(n) : "memory")

__device__ __forceinline__ void mma_fp16(float* d, const uint32_t* a, const uint32_t* b) {
    asm volatile("mma.sync.aligned.m16n8k16.row.col.f32.f16.f16.f32 "
        "{%0,%1,%2,%3}, {%4,%5,%6,%7}, {%8,%9}, {%0,%1,%2,%3};"
        : "+f"(d[0]), "+f"(d[1]), "+f"(d[2]), "+f"(d[3])
        : "r"(a[0]), "r"(a[1]), "r"(a[2]), "r"(a[3]), "r"(b[0]), "r"(b[1]));
}

// ---------------- merged pack: A-transpose + B + twT (one launch) -----------
#define PA_LDK 328
#define PACKA_SMEM (128*PA_LDK*2)
#define PA_BLOCKS (VPAD/128)   // 391
#define PB_BLOCKS 120          // 30720 d4 / 256
#define TW_BLOCKS 75           // 19200 / 256

__device__ __forceinline__ __half wall_h(const float* w3, const float* w4,
                                         const float* w5, int c, int k) {
    if (k >= DE) return __float2half_rn(0.f);
    float v;
    if (c < 192)      { int cc = c;       int dt = cc >> 6, o = cc & 63; v = w3[(o*3 + dt)*DE + k]; }
    else if (c < 448) { int cc = c - 192; int dt = cc >> 6, o = cc & 63; v = w4[(o*4 + dt)*DE + k]; }
    else              { int cc = c - 448; int dt = cc >> 6, o = cc & 63; v = w5[(o*5 + dt)*DE + k]; }
    return __float2half_rn(v);
}

__global__ void __launch_bounds__(256) packall(
        const float* __restrict__ emb,
        const float* __restrict__ w3, const float* __restrict__ w4,
        const float* __restrict__ w5, const float* __restrict__ tw) {
    const int tid = threadIdx.x;
    if (blockIdx.x < PA_BLOCKS) {
        // ---- pack A: coalesced read -> smem transpose -> fragment write ----
        extern __shared__ __half sa[];
        const int mblk = blockIdx.x;
        {
            uint4* s4 = reinterpret_cast<uint4*>(sa);
            for (int i = tid; i < 128*PA_LDK/8; i += 256)
                s4[i] = make_uint4(0, 0, 0, 0);
        }
        __syncthreads();
        {
            const float4* e4 = reinterpret_cast<const float4*>(emb);
            for (int i = tid; i < 128*75; i += 256) {
                int row = i / 75, c4 = i - row*75;
                int m = mblk*128 + row;
                if (m < VOCAB) {
                    float4 v = e4[(size_t)m*75 + c4];
                    __half2 lo = __floats2half2_rn(v.x, v.y);
                    __half2 hi = __floats2half2_rn(v.z, v.w);
                    uint2 pk = make_uint2(*(uint32_t*)&lo, *(uint32_t*)&hi);
                    *reinterpret_cast<uint2*>(sa + row*PA_LDK + c4*4) = pk;
                }
            }
        }
        __syncthreads();
        {
            const int lane = tid & 31;
            const int r16  = tid >> 5;
            const int mloc = r16*16 + (lane >> 2);
            const int kk   = (lane & 3)*2;
            const uint32_t* s32 = reinterpret_cast<const uint32_t*>(sa);
            uint4* out4 = reinterpret_cast<uint4*>(g_Ah);
            #pragma unroll 4
            for (int kc16 = 0; kc16 < 20; kc16++) {
                int k = kc16*16 + kk;
                uint32_t h0 = s32[( mloc      *PA_LDK + k    ) >> 1];
                uint32_t h1 = s32[((mloc + 8)*PA_LDK + k    ) >> 1];
                uint32_t h2 = s32[( mloc      *PA_LDK + k + 8) >> 1];
                uint32_t h3 = s32[((mloc + 8)*PA_LDK + k + 8) >> 1];
                out4[((size_t)(mblk*20 + kc16)*8 + r16)*32 + lane] = make_uint4(h0, h1, h2, h3);
            }
        }
    } else if (blockIdx.x < PA_BLOCKS + PB_BLOCKS) {
        // ---- pack B (nt-pair fragment order) ----
        int d4 = (blockIdx.x - PA_BLOCKS) * 256 + tid;
        int lane = d4 & 31;
        int np   = (d4 >> 5) & 7;
        int rest = d4 >> 8;
        int kc16 = rest % 20;
        int nblk = rest / 20;
        int na = nblk*128 + np*16 + (lane >> 2);
        int nb = na + 8;
        int k = kc16*16 + (lane & 3)*2;
        __half2 h0 = __halves2half2(wall_h(w3,w4,w5, na, k),     wall_h(w3,w4,w5, na, k + 1));
        __half2 h1 = __halves2half2(wall_h(w3,w4,w5, na, k + 8), wall_h(w3,w4,w5, na, k + 9));
        __half2 h2 = __halves2half2(wall_h(w3,w4,w5, nb, k),     wall_h(w3,w4,w5, nb, k + 1));
        __half2 h3 = __halves2half2(wall_h(w3,w4,w5, nb, k + 8), wall_h(w3,w4,w5, nb, k + 9));
        uint4 v = make_uint4(*(uint32_t*)&h0, *(uint32_t*)&h1, *(uint32_t*)&h2, *(uint32_t*)&h3);
        reinterpret_cast<uint4*>(g_Bh)[d4] = v;
    } else {
        // ---- transpose trans_w ----
        int idx = (blockIdx.x - PA_BLOCKS - PB_BLOCKS) * 256 + tid;
        if (idx < FCAT*DOUT) {
            int j = idx / DOUT, d = idx % DOUT;
            g_twT[idx] = tw[d*FCAT + j];
        }
    }
}

// ---------------- fp16 mma GEMM: Z = Ah @ Bh^T (fp16 out) ----------------
// CTA 128x128, 256 thr = 8 warps (4M x 2N), warp tile 32x64, 2 CTAs/SM.
#define GEMM_SMEM 49152

__global__ void __launch_bounds__(256, 2) conv_gemm_mma() {
    extern __shared__ char smc[];
    const int tid  = threadIdx.x;
    const int lane = tid & 31, wid = tid >> 5;
    const int warp_m = wid & 3;
    const int warp_n = wid >> 2;
    const int by = blockIdx.y, bx = blockIdx.x;
    const int m0 = by * 128, n0 = bx * 128;

    const uint32_t smb = smem_u32(smc);
    const uint4* Ah4 = reinterpret_cast<const uint4*>(g_Ah);
    const uint4* Bh4 = reinterpret_cast<const uint4*>(g_Bh);

    float acc[2][8][4];
    #pragma unroll
    for (int mt = 0; mt < 2; mt++)
        #pragma unroll
        for (int nt = 0; nt < 8; nt++)
            #pragma unroll
            for (int i = 0; i < 4; i++) acc[mt][nt][i] = 0.f;

    #pragma unroll
    for (int c = 0; c < 2; c++) {
        size_t aG = ((size_t)by*20 + c*2) * 256;
        size_t bG = ((size_t)bx*20 + c*2) * 256;
        #pragma unroll
        for (int i = 0; i < 2; i++) {
            CP_ASYNC16(smb +         c*8192 + (tid + i*256)*16, Ah4 + aG + tid + i*256);
            CP_ASYNC16(smb + 24576 + c*8192 + (tid + i*256)*16, Bh4 + bG + tid + i*256);
        }
        CP_COMMIT();
    }

    for (int c = 0; c < 10; c++) {
        const int buf = c % 3;
        if (c < 9) CP_WAIT(1); else CP_WAIT(0);
        __syncthreads();
        if (c + 2 < 10) {
            const int nb = (c + 2) % 3;
            size_t aG = ((size_t)by*20 + (c + 2)*2) * 256;
            size_t bG = ((size_t)bx*20 + (c + 2)*2) * 256;
            #pragma unroll
            for (int i = 0; i < 2; i++) {
                CP_ASYNC16(smb +         nb*8192 + (tid + i*256)*16, Ah4 + aG + tid + i*256);
                CP_ASYNC16(smb + 24576 + nb*8192 + (tid + i*256)*16, Bh4 + bG + tid + i*256);
            }
            CP_COMMIT();
        }

        const uint4* A4 = reinterpret_cast<const uint4*>(smc + buf*8192);
        const uint4* B4 = reinterpret_cast<const uint4*>(smc + 24576 + buf*8192);
        #pragma unroll
        for (int ks = 0; ks < 2; ks++) {
            uint32_t a[2][4], b[8][2];
            #pragma unroll
            for (int mt = 0; mt < 2; mt++) {
                uint4 v = A4[(ks*8 + warp_m*2 + mt)*32 + lane];
                a[mt][0] = v.x; a[mt][1] = v.y; a[mt][2] = v.z; a[mt][3] = v.w;
            }
            #pragma unroll
            for (int np = 0; np < 4; np++) {
                uint4 u = B4[(ks*8 + warp_n*4 + np)*32 + lane];
                b[2*np  ][0] = u.x; b[2*np  ][1] = u.y;
                b[2*np+1][0] = u.z; b[2*np+1][1] = u.w;
            }
            #pragma unroll
            for (int mt = 0; mt < 2; mt++)
                #pragma unroll
                for (int nt = 0; nt < 8; nt++)
                    mma_fp16(acc[mt][nt], a[mt], b[nt]);
        }
    }

    __half2* Z2 = reinterpret_cast<__half2*>(g_Zh);
    #pragma unroll
    for (int mt = 0; mt < 2; mt++) {
        int r = m0 + warp_m*32 + mt*16 + (lane >> 2);
        #pragma unroll
        for (int nt = 0; nt < 8; nt++) {
            int cc = n0 + warp_n*64 + nt*8 + (lane & 3)*2;
            Z2[((size_t) r      *NCOL + cc) >> 1] = __floats2half2_rn(acc[mt][nt][0], acc[mt][nt][1]);
            Z2[((size_t)(r + 8)*NCOL + cc) >> 1] = __floats2half2_rn(acc[mt][nt][2], acc[mt][nt][3]);
        }
    }
}

// ---------------- fused pool + relu + tanh projection -----------------------
// cp.async staging; half2 feature pairs (1 LDS.32 per 2 features); 8-way t-split.
// smem: Zs[76800] | toks@76800 (200) | pmax2@77000 (768 float2 = 6144) | fsh@83144 (768)
#define POOL_T 768
#define POOL_SMEM (76800 + 200 + 6144 + 768)
__global__ void __launch_bounds__(POOL_T) poolsutt_kernel(
        const int* __restrict__ sents,
        const float* __restrict__ b3, const float* __restrict__ b4,
        const float* __restrict__ b5, const float* __restrict__ tb) {
    extern __shared__ char psm[];
    __half*  Zs    = reinterpret_cast<__half*>(psm);
    int*     toks  = reinterpret_cast<int*>(psm + 76800);
    float2*  pmax2 = reinterpret_cast<float2*>(psm + 77000);
    float*   fsh   = reinterpret_cast<float*>(psm + 83144);
    const int n = blockIdx.x;
    const int tid = threadIdx.x;
    const uint32_t zsb = smem_u32(Zs);

    if (tid < SL) toks[tid] = sents[n*SL + tid];
    __syncthreads();

    // stage 50 rows x 96 uint4 via cp.async (independent, high MLP)
    {
        const uint4* Zg4 = reinterpret_cast<const uint4*>(g_Zh);
        for (int i = tid; i < SL*96; i += POOL_T) {
            int row = i / 96, c4 = i - row*96;
            CP_ASYNC16(zsb + i*16, Zg4 + (size_t)toks[row]*96 + c4);
        }
        CP_COMMIT();
        CP_WAIT(0);
    }
    __syncthreads();

    // pool: 96 feature-pairs x 8 t-slices; half2 loads, float adds (same math)
    {
        const int q  = tid / 96;            // 0..7 t-slice
        const int p  = tid - q*96;          // 0..95 feature pair
        const int fi = p >> 5, o2 = p & 31; // features fi*64 + 2*o2 (+1)
        const int fs  = 3 + fi;
        const int offh = ((fi == 0) ? 0 : (fi == 1) ? 192 : 448) / 2;
        const int T = SL - fs + 1;
        const int t0 = (T * q) >> 3;
        const int t1 = (T * (q + 1)) >> 3;
        const __half2* Zs2 = reinterpret_cast<const __half2*>(Zs);
        float mx0 = -1e30f, mx1 = -1e30f;
        for (int t = t0; t < t1; t++) {
            float v0 = 0.f, v1 = 0.f;
            #pragma unroll 5
            for (int dt = 0; dt < fs; dt++) {
                __half2 h = Zs2[(t + dt)*384 + offh + dt*32 + o2];
                float2 f = __half22float2(h);
                v0 += f.x; v1 += f.y;
            }
            mx0 = fmaxf(mx0, v0); mx1 = fmaxf(mx1, v1);
        }
        pmax2[q*96 + p] = make_float2(mx0, mx1);
    }
    __syncthreads();
    if (tid < 96) {
        const int fi = tid >> 5, o2 = tid & 31;
        const int fa = fi*64 + 2*o2;
        float m0 = -1e30f, m1 = -1e30f;
        #pragma unroll
        for (int q = 0; q < 8; q++) {
            float2 v = pmax2[q*96 + tid];
            m0 = fmaxf(m0, v.x); m1 = fmaxf(m1, v.y);
        }
        float ba = (fi == 0) ? b3[2*o2]     : (fi == 1) ? b4[2*o2]     : b5[2*o2];
        float bb = (fi == 0) ? b3[2*o2 + 1] : (fi == 1) ? b4[2*o2 + 1] : b5[2*o2 + 1];
        fsh[fa]     = fmaxf(0.f, m0 + ba);
        fsh[fa + 1] = fmaxf(0.f, m1 + bb);
    }
    __syncthreads();
    if (tid < DOUT) {
        float acc = tb[tid];
        #pragma unroll 8
        for (int j = 0; j < FCAT; j++) acc += fsh[j] * g_twT[j*DOUT + tid];
        g_sutt[n*DOUT + tid] = tanhf(acc);
    }
}

// ---------------- fused GRU (xproj folded in): 10 steps, weights-in-regs ----
// Block: 16 batch rows. Local xproj for the 25 needed source rows (invalid
// rows reduce to bih exactly as before, since xv=0 there).
#define GRB 16
#define GRU_T 320
#define NXV 25
// smem floats: xp[25*300] | xvs[25*100] | hs[16*100] | gh[16*300]
#define GRU_SMEM ((NXV*3*DOUT + NXV*DOUT + GRB*DOUT + GRB*3*DOUT) * 4)
__global__ void __launch_bounds__(GRU_T) gru_fused(
        const float* __restrict__ wih, const float* __restrict__ bih,
        const float* __restrict__ whh, const float* __restrict__ bhh) {
    extern __shared__ float smg[];
    float* xp  = smg;                      // [25][300]
    float* xvs = xp + NXV*3*DOUT;          // [25][100]
    float* hs  = xvs + NXV*DOUT;           // [16][100]
    float* gh  = hs + GRB*DOUT;            // [16][300]
    const int tid = threadIdx.x;
    const int b0 = blockIdx.x * GRB;

    // stage s_utt slice (v = b0-9 .. b0+15); invalid -> 0
    for (int i = tid; i < NXV*DOUT; i += GRU_T) {
        int vi = i / DOUT, d = i - vi*DOUT;
        int v = b0 - (WIND - 1) + vi;
        xvs[i] = (v >= 0 && v < NB) ? g_sutt[v*DOUT + d] : 0.f;
    }
    for (int i = tid; i < GRB*DOUT; i += GRU_T) hs[i] = 0.f;
    __syncthreads();

    // local xproj: xp[vi][j] = xvs[vi] . wih[j] + bih[j]
    for (int i = tid; i < NXV*3*DOUT; i += GRU_T) {
        int vi = i / (3*DOUT), j = i - vi*3*DOUT;
        const float4* wI = reinterpret_cast<const float4*>(wih + j*DOUT);
        const float4* xv = reinterpret_cast<const float4*>(xvs + vi*DOUT);
        float acc = 0.f;
        #pragma unroll
        for (int k = 0; k < DOUT/4; k++) {
            float4 w = wI[k], x = xv[k];
            acc += w.x*x.x + w.y*x.y + w.z*x.z + w.w*x.w;
        }
        xp[i] = acc + bih[j];
    }

    // recurrent weights into registers (thread j owns whh row j)
    const int j = tid;
    const bool active = (j < 3*DOUT);
    float w[DOUT];
    float bh = 0.f;
    if (active) {
        const float4* wr = reinterpret_cast<const float4*>(whh + j*DOUT);
        #pragma unroll
        for (int k4 = 0; k4 < DOUT/4; k4++) {
            float4 v = wr[k4];
            w[4*k4] = v.x; w[4*k4+1] = v.y; w[4*k4+2] = v.z; w[4*k4+3] = v.w;
        }
        bh = bhh[j];
    }
    __syncthreads();

    for (int s = 0; s < WIND; s++) {
        if (active) {
            #pragma unroll
            for (int r = 0; r < GRB; r++) {
                const float4* h4 = reinterpret_cast<const float4*>(hs + r*DOUT);
                float acc = 0.f;
                #pragma unroll
                for (int k4 = 0; k4 < DOUT/4; k4++) {
                    float4 h = h4[k4];
                    acc += w[4*k4]*h.x + w[4*k4+1]*h.y + w[4*k4+2]*h.z + w[4*k4+3]*h.w;
                }
                gh[r*3*DOUT + j] = acc + bh;
            }
        }
        __syncthreads();
        for (int idx = tid; idx < GRB*DOUT; idx += GRU_T) {
            int r = idx / DOUT, d = idx - r*DOUT;
            int b = b0 + r;
            if (b < NB) {
                int vi = r + s;                         // xp row for src=b+s-9
                float giR = xp[vi*3*DOUT + d];
                float giZ = xp[vi*3*DOUT + DOUT + d];
                float giN = xp[vi*3*DOUT + 2*DOUT + d];
                float xv  = xvs[vi*DOUT + d];
                float hr = gh[r*3*DOUT + d];
                float hz = gh[r*3*DOUT + DOUT + d];
                float hn = gh[r*3*DOUT + 2*DOUT + d];
                float rr = 1.f / (1.f + expf(-(giR + hr)));
                float zz = 1.f / (1.f + expf(-(giZ + hz)));
                float nn = tanhf(giN + rr*hn);
                float hnew = (1.f - zz)*nn + zz*hs[r*DOUT + d];
                hs[r*DOUT + d] = hnew;
                g_memb[(b*WIND + s)*DOUT + d] = xv + hnew;
            }
        }
        __syncthreads();
    }
}

// ---------------- 3-hop attention: warp per window, register M --------------
__global__ void __launch_bounds__(256) attn_kernel(float* __restrict__ attn_out) {
    const int w = blockIdx.x * 8 + (threadIdx.x >> 5);
    const int lane = threadIdx.x & 31;
    if (w >= NB) return;

    float M[WIND][4], q[4];
    #pragma unroll
    for (int jj = 0; jj < 4; jj++) {
        int d = lane + 32*jj;
        bool ok = d < DOUT;
        q[jj] = ok ? g_sutt[(w + 1)*DOUT + d] : 0.f;
        #pragma unroll
        for (int k = 0; k < WIND; k++)
            M[k][jj] = ok ? g_memb[(w*WIND + k)*DOUT + d] : 0.f;
    }

    #pragma unroll
    for (int hop = 0; hop < HOPS; hop++) {
        float l[WIND];
        #pragma unroll
        for (int k = 0; k < WIND; k++) {
            float p = q[0]*M[k][0] + q[1]*M[k][1] + q[2]*M[k][2] + q[3]*M[k][3];
            #pragma unroll
            for (int off = 16; off; off >>= 1)
                p += __shfl_xor_sync(0xFFFFFFFFu, p, off);
            l[k] = (w + k - (WIND - 1) >= 0) ? p : -1e10f;
        }
        float mx = l[0];
        #pragma unroll
        for (int k = 1; k < WIND; k++) mx = fmaxf(mx, l[k]);
        float a[WIND], sum = 0.f;
        #pragma unroll
        for (int k = 0; k < WIND; k++) { a[k] = expf(l[k] - mx); sum += a[k]; }
        float inv = 1.f / sum;
        #pragma unroll
        for (int k = 0; k < WIND; k++) {
            a[k] *= inv;
            if (lane == k) attn_out[hop*(NB*WIND) + w*WIND + k] = a[k];
        }
        #pragma unroll
        for (int jj = 0; jj < 4; jj++) {
            float acc = 0.f;
            #pragma unroll
            for (int k = 0; k < WIND; k++) acc += a[k] * M[k][jj];
            q[jj] += acc;
        }
    }
    #pragma unroll
    for (int jj = 0; jj < 4; jj++) {
        int d = lane + 32*jj;
        if (d < DOUT) g_q[w*DOUT + d] = q[jj];
    }
}

// ---------------- classifier + log_softmax ----------------
__global__ void cls_kernel(const float* __restrict__ cw,
                           const float* __restrict__ cb,
                           float* __restrict__ pred_out) {
    int row = blockIdx.x * blockDim.x + threadIdx.x;
    if (row >= NU) return;
    const float* s = (row == 0) ? g_sutt : (g_q + (row - 1)*DOUT);
    float lg[NC];
    #pragma unroll
    for (int c = 0; c < NC; c++) {
        float acc = cb[c];
        const float* wr = cw + c*DOUT;
        #pragma unroll 4
        for (int k = 0; k < DOUT; k++) acc += s[k] * wr[k];
        lg[c] = acc;
    }
    float mx = lg[0];
    #pragma unroll
    for (int c = 1; c < NC; c++) mx = fmaxf(mx, lg[c]);
    float sum = 0.f;
    #pragma unroll
    for (int c = 0; c < NC; c++) sum += expf(lg[c] - mx);
    float lse = mx + logf(sum);
    #pragma unroll
    for (int c = 0; c < NC; c++) pred_out[row*NC + c] = lg[c] - lse;
}

// ---------------- launch sequence ----------------
extern "C" void kernel_launch(void* const* d_in, const int* in_sizes, int n_in,
                              void* d_out, int out_size) {
    const int*   sents   = (const int*)  d_in[0];
    const float* emb     = (const float*)d_in[2];
    const float* trans_w = (const float*)d_in[3];
    const float* trans_b = (const float*)d_in[4];
    const float* gru_wih = (const float*)d_in[5];
    const float* gru_whh = (const float*)d_in[6];
    const float* gru_bih = (const float*)d_in[7];
    const float* gru_bhh = (const float*)d_in[8];
    const float* cls_w   = (const float*)d_in[9];
    const float* cls_b   = (const float*)d_in[10];
    const float* conv_w3 = (const float*)d_in[11];
    const float* conv_b3 = (const float*)d_in[12];
    const float* conv_w4 = (const float*)d_in[13];
    const float* conv_b4 = (const float*)d_in[14];
    const float* conv_w5 = (const float*)d_in[15];
    const float* conv_b5 = (const float*)d_in[16];

    float* outF = (float*)d_out;
    float* pred_out = outF;
    float* attn_out;
    if (out_size >= NU*NC + HOPS*NB*WIND) attn_out = outF + NU*NC;
    else cudaGetSymbolAddress((void**)&attn_out, g_attn_scratch);

    cudaFuncSetAttribute(packall,         cudaFuncAttributeMaxDynamicSharedMemorySize, PACKA_SMEM);
    cudaFuncSetAttribute(conv_gemm_mma,   cudaFuncAttributeMaxDynamicSharedMemorySize, GEMM_SMEM);
    cudaFuncSetAttribute(poolsutt_kernel, cudaFuncAttributeMaxDynamicSharedMemorySize, POOL_SMEM);
    cudaFuncSetAttribute(gru_fused,       cudaFuncAttributeMaxDynamicSharedMemorySize, GRU_SMEM);

    // launch order: gru_fused is 4th (ncu capture slot)
    packall<<<PA_BLOCKS + PB_BLOCKS + TW_BLOCKS, 256, PACKA_SMEM>>>(
        emb, conv_w3, conv_w4, conv_w5, trans_w);

    dim3 ggrid(NCOL/128, VPAD/128);   // (6, 391)
    conv_gemm_mma<<<ggrid, 256, GEMM_SMEM>>>();

    poolsutt_kernel<<<NU, POOL_T, POOL_SMEM>>>(sents, conv_b3, conv_b4, conv_b5, trans_b);
    gru_fused<<<(NB + GRB - 1)/GRB, GRU_T, GRU_SMEM>>>(gru_wih, gru_bih, gru_whh, gru_bhh);

    attn_kernel<<<(NB + 7)/8, 256>>>(attn_out);
    cls_kernel<<<(NU + 255)/256, 256>>>(cls_w, cls_b, pred_out);
}

// round 13
// speedup vs baseline: 1.1775x; 1.0431x over previous
#include <cuda_runtime.h>
#include <cuda_fp16.h>
#include <math.h>
#include <stdint.h>

// ---------------- problem constants ----------------
#define NU    2048
#define SL    50
#define DE    300
#define KPAD  320      // 20 k-groups of 16
#define DOUT  100
#define NC    7
#define WIND  10
#define HOPS  3
#define NB    2047
#define VOCAB 50000
#define VPAD  50048    // 391 * 128
#define NCOL  768
#define FCAT  192

// ---------------- static scratch ----------------
__device__ __half g_Ah[(size_t)VPAD*KPAD];      // A fp16 fragment order (128-row mblk)
__device__ __half g_Bh[NCOL*KPAD];              // B fp16 nt-pair fragment order (128-col nblk)
__device__ __half g_Zh[(size_t)VPAD*NCOL];      // fp16 projections (77 MB)
__device__ float g_twT[FCAT*DOUT];
__device__ float g_sutt[NU*DOUT];
__device__ float g_memb[NB*WIND*DOUT];
__device__ float g_q[NB*DOUT];
__device__ float g_attn_scratch[HOPS*NB*WIND];

// ---------------- helpers ----------------
__device__ __forceinline__ uint32_t smem_u32(const void* p) {
    uint32_t a;
    asm("{ .reg .u64 t; cvta.to.shared.u64 t, %1; cvt.u32.u64 %0, t; }" : "=r"(a) : "l"(p));
    return a;
}
#define CP_ASYNC16(sa, gp) asm volatile("cp.async.cg.shared.global [%0], [%1], 16;" :: "r"(sa), "l"(gp) : "memory")
#define CP_COMMIT()        asm volatile("cp.async.commit_group;" ::: "memory")
#define CP_WAIT(n)         asm volatile("cp.async.wait_group %0;" :: "n"(n) : "memory")

__device__ __forceinline__ void mma_fp16(float* d, const uint32_t* a, const uint32_t* b) {
    asm volatile("mma.sync.aligned.m16n8k16.row.col.f32.f16.f16.f32 "
        "{%0,%1,%2,%3}, {%4,%5,%6,%7}, {%8,%9}, {%0,%1,%2,%3};"
        : "+f"(d[0]), "+f"(d[1]), "+f"(d[2]), "+f"(d[3])
        : "r"(a[0]), "r"(a[1]), "r"(a[2]), "r"(a[3]), "r"(b[0]), "r"(b[1]));
}

// ---------------- merged pack: A-transpose + B + twT (one launch) -----------
#define PA_LDK 328
#define PACKA_SMEM (128*PA_LDK*2)
#define PA_BLOCKS (VPAD/128)   // 391
#define PB_BLOCKS 120          // 30720 d4 / 256
#define TW_BLOCKS 75           // 19200 / 256

__device__ __forceinline__ __half wall_h(const float* w3, const float* w4,
                                         const float* w5, int c, int k) {
    if (k >= DE) return __float2half_rn(0.f);
    float v;
    if (c < 192)      { int cc = c;       int dt = cc >> 6, o = cc & 63; v = w3[(o*3 + dt)*DE + k]; }
    else if (c < 448) { int cc = c - 192; int dt = cc >> 6, o = cc & 63; v = w4[(o*4 + dt)*DE + k]; }
    else              { int cc = c - 448; int dt = cc >> 6, o = cc & 63; v = w5[(o*5 + dt)*DE + k]; }
    return __float2half_rn(v);
}

__global__ void __launch_bounds__(256) packall(
        const float* __restrict__ emb,
        const float* __restrict__ w3, const float* __restrict__ w4,
        const float* __restrict__ w5, const float* __restrict__ tw) {
    const int tid = threadIdx.x;
    if (blockIdx.x < PA_BLOCKS) {
        extern __shared__ __half sa[];
        const int mblk = blockIdx.x;
        {
            uint4* s4 = reinterpret_cast<uint4*>(sa);
            for (int i = tid; i < 128*PA_LDK/8; i += 256)
                s4[i] = make_uint4(0, 0, 0, 0);
        }
        __syncthreads();
        {
            const float4* e4 = reinterpret_cast<const float4*>(emb);
            for (int i = tid; i < 128*75; i += 256) {
                int row = i / 75, c4 = i - row*75;
                int m = mblk*128 + row;
                if (m < VOCAB) {
                    float4 v = e4[(size_t)m*75 + c4];
                    __half2 lo = __floats2half2_rn(v.x, v.y);
                    __half2 hi = __floats2half2_rn(v.z, v.w);
                    uint2 pk = make_uint2(*(uint32_t*)&lo, *(uint32_t*)&hi);
                    *reinterpret_cast<uint2*>(sa + row*PA_LDK + c4*4) = pk;
                }
            }
        }
        __syncthreads();
        {
            const int lane = tid & 31;
            const int r16  = tid >> 5;
            const int mloc = r16*16 + (lane >> 2);
            const int kk   = (lane & 3)*2;
            const uint32_t* s32 = reinterpret_cast<const uint32_t*>(sa);
            uint4* out4 = reinterpret_cast<uint4*>(g_Ah);
            #pragma unroll 4
            for (int kc16 = 0; kc16 < 20; kc16++) {
                int k = kc16*16 + kk;
                uint32_t h0 = s32[( mloc      *PA_LDK + k    ) >> 1];
                uint32_t h1 = s32[((mloc + 8)*PA_LDK + k    ) >> 1];
                uint32_t h2 = s32[( mloc      *PA_LDK + k + 8) >> 1];
                uint32_t h3 = s32[((mloc + 8)*PA_LDK + k + 8) >> 1];
                out4[((size_t)(mblk*20 + kc16)*8 + r16)*32 + lane] = make_uint4(h0, h1, h2, h3);
            }
        }
    } else if (blockIdx.x < PA_BLOCKS + PB_BLOCKS) {
        int d4 = (blockIdx.x - PA_BLOCKS) * 256 + tid;
        int lane = d4 & 31;
        int np   = (d4 >> 5) & 7;
        int rest = d4 >> 8;
        int kc16 = rest % 20;
        int nblk = rest / 20;
        int na = nblk*128 + np*16 + (lane >> 2);
        int nb = na + 8;
        int k = kc16*16 + (lane & 3)*2;
        __half2 h0 = __halves2half2(wall_h(w3,w4,w5, na, k),     wall_h(w3,w4,w5, na, k + 1));
        __half2 h1 = __halves2half2(wall_h(w3,w4,w5, na, k + 8), wall_h(w3,w4,w5, na, k + 9));
        __half2 h2 = __halves2half2(wall_h(w3,w4,w5, nb, k),     wall_h(w3,w4,w5, nb, k + 1));
        __half2 h3 = __halves2half2(wall_h(w3,w4,w5, nb, k + 8), wall_h(w3,w4,w5, nb, k + 9));
        uint4 v = make_uint4(*(uint32_t*)&h0, *(uint32_t*)&h1, *(uint32_t*)&h2, *(uint32_t*)&h3);
        reinterpret_cast<uint4*>(g_Bh)[d4] = v;
    } else {
        int idx = (blockIdx.x - PA_BLOCKS - PB_BLOCKS) * 256 + tid;
        if (idx < FCAT*DOUT) {
            int j = idx / DOUT, d = idx % DOUT;
            g_twT[idx] = tw[d*FCAT + j];
        }
    }
}

// ---------------- fp16 mma GEMM: Z = Ah @ Bh^T (fp16 out) ----------------
#define GEMM_SMEM 49152

__global__ void __launch_bounds__(256, 2) conv_gemm_mma() {
    extern __shared__ char smc[];
    const int tid  = threadIdx.x;
    const int lane = tid & 31, wid = tid >> 5;
    const int warp_m = wid & 3;
    const int warp_n = wid >> 2;
    const int by = blockIdx.y, bx = blockIdx.x;
    const int m0 = by * 128, n0 = bx * 128;

    const uint32_t smb = smem_u32(smc);
    const uint4* Ah4 = reinterpret_cast<const uint4*>(g_Ah);
    const uint4* Bh4 = reinterpret_cast<const uint4*>(g_Bh);

    float acc[2][8][4];
    #pragma unroll
    for (int mt = 0; mt < 2; mt++)
        #pragma unroll
        for (int nt = 0; nt < 8; nt++)
            #pragma unroll
            for (int i = 0; i < 4; i++) acc[mt][nt][i] = 0.f;

    #pragma unroll
    for (int c = 0; c < 2; c++) {
        size_t aG = ((size_t)by*20 + c*2) * 256;
        size_t bG = ((size_t)bx*20 + c*2) * 256;
        #pragma unroll
        for (int i = 0; i < 2; i++) {
            CP_ASYNC16(smb +         c*8192 + (tid + i*256)*16, Ah4 + aG + tid + i*256);
            CP_ASYNC16(smb + 24576 + c*8192 + (tid + i*256)*16, Bh4 + bG + tid + i*256);
        }
        CP_COMMIT();
    }

    for (int c = 0; c < 10; c++) {
        const int buf = c % 3;
        if (c < 9) CP_WAIT(1); else CP_WAIT(0);
        __syncthreads();
        if (c + 2 < 10) {
            const int nb = (c + 2) % 3;
            size_t aG = ((size_t)by*20 + (c + 2)*2) * 256;
            size_t bG = ((size_t)bx*20 + (c + 2)*2) * 256;
            #pragma unroll
            for (int i = 0; i < 2; i++) {
                CP_ASYNC16(smb +         nb*8192 + (tid + i*256)*16, Ah4 + aG + tid + i*256);
                CP_ASYNC16(smb + 24576 + nb*8192 + (tid + i*256)*16, Bh4 + bG + tid + i*256);
            }
            CP_COMMIT();
        }

        const uint4* A4 = reinterpret_cast<const uint4*>(smc + buf*8192);
        const uint4* B4 = reinterpret_cast<const uint4*>(smc + 24576 + buf*8192);
        #pragma unroll
        for (int ks = 0; ks < 2; ks++) {
            uint32_t a[2][4], b[8][2];
            #pragma unroll
            for (int mt = 0; mt < 2; mt++) {
                uint4 v = A4[(ks*8 + warp_m*2 + mt)*32 + lane];
                a[mt][0] = v.x; a[mt][1] = v.y; a[mt][2] = v.z; a[mt][3] = v.w;
            }
            #pragma unroll
            for (int np = 0; np < 4; np++) {
                uint4 u = B4[(ks*8 + warp_n*4 + np)*32 + lane];
                b[2*np  ][0] = u.x; b[2*np  ][1] = u.y;
                b[2*np+1][0] = u.z; b[2*np+1][1] = u.w;
            }
            #pragma unroll
            for (int mt = 0; mt < 2; mt++)
                #pragma unroll
                for (int nt = 0; nt < 8; nt++)
                    mma_fp16(acc[mt][nt], a[mt], b[nt]);
        }
    }

    __half2* Z2 = reinterpret_cast<__half2*>(g_Zh);
    #pragma unroll
    for (int mt = 0; mt < 2; mt++) {
        int r = m0 + warp_m*32 + mt*16 + (lane >> 2);
        #pragma unroll
        for (int nt = 0; nt < 8; nt++) {
            int cc = n0 + warp_n*64 + nt*8 + (lane & 3)*2;
            Z2[((size_t) r      *NCOL + cc) >> 1] = __floats2half2_rn(acc[mt][nt][0], acc[mt][nt][1]);
            Z2[((size_t)(r + 8)*NCOL + cc) >> 1] = __floats2half2_rn(acc[mt][nt][2], acc[mt][nt][3]);
        }
    }
}

// ---------------- fused pool + relu + tanh projection -----------------------
#define POOL_T 768
#define POOL_SMEM (76800 + 200 + 6144 + 768)
__global__ void __launch_bounds__(POOL_T) poolsutt_kernel(
        const int* __restrict__ sents,
        const float* __restrict__ b3, const float* __restrict__ b4,
        const float* __restrict__ b5, const float* __restrict__ tb) {
    extern __shared__ char psm[];
    __half*  Zs    = reinterpret_cast<__half*>(psm);
    int*     toks  = reinterpret_cast<int*>(psm + 76800);
    float2*  pmax2 = reinterpret_cast<float2*>(psm + 77000);
    float*   fsh   = reinterpret_cast<float*>(psm + 83144);
    const int n = blockIdx.x;
    const int tid = threadIdx.x;
    const uint32_t zsb = smem_u32(Zs);

    if (tid < SL) toks[tid] = sents[n*SL + tid];
    __syncthreads();
    {
        const uint4* Zg4 = reinterpret_cast<const uint4*>(g_Zh);
        for (int i = tid; i < SL*96; i += POOL_T) {
            int row = i / 96, c4 = i - row*96;
            CP_ASYNC16(zsb + i*16, Zg4 + (size_t)toks[row]*96 + c4);
        }
        CP_COMMIT();
        CP_WAIT(0);
    }
    __syncthreads();
    {
        const int q  = tid / 96;
        const int p  = tid - q*96;
        const int fi = p >> 5, o2 = p & 31;
        const int fs  = 3 + fi;
        const int offh = ((fi == 0) ? 0 : (fi == 1) ? 192 : 448) / 2;
        const int T = SL - fs + 1;
        const int t0 = (T * q) >> 3;
        const int t1 = (T * (q + 1)) >> 3;
        const __half2* Zs2 = reinterpret_cast<const __half2*>(Zs);
        float mx0 = -1e30f, mx1 = -1e30f;
        for (int t = t0; t < t1; t++) {
            float v0 = 0.f, v1 = 0.f;
            #pragma unroll 5
            for (int dt = 0; dt < fs; dt++) {
                __half2 h = Zs2[(t + dt)*384 + offh + dt*32 + o2];
                float2 f = __half22float2(h);
                v0 += f.x; v1 += f.y;
            }
            mx0 = fmaxf(mx0, v0); mx1 = fmaxf(mx1, v1);
        }
        pmax2[q*96 + p] = make_float2(mx0, mx1);
    }
    __syncthreads();
    if (tid < 96) {
        const int fi = tid >> 5, o2 = tid & 31;
        const int fa = fi*64 + 2*o2;
        float m0 = -1e30f, m1 = -1e30f;
        #pragma unroll
        for (int q = 0; q < 8; q++) {
            float2 v = pmax2[q*96 + tid];
            m0 = fmaxf(m0, v.x); m1 = fmaxf(m1, v.y);
        }
        float ba = (fi == 0) ? b3[2*o2]     : (fi == 1) ? b4[2*o2]     : b5[2*o2];
        float bb = (fi == 0) ? b3[2*o2 + 1] : (fi == 1) ? b4[2*o2 + 1] : b5[2*o2 + 1];
        fsh[fa]     = fmaxf(0.f, m0 + ba);
        fsh[fa + 1] = fmaxf(0.f, m1 + bb);
    }
    __syncthreads();
    if (tid < DOUT) {
        float acc = tb[tid];
        #pragma unroll 8
        for (int j = 0; j < FCAT; j++) acc += fsh[j] * g_twT[j*DOUT + tid];
        g_sutt[n*DOUT + tid] = tanhf(acc);
    }
}

// ---------------- fused GRU v3: split-row weights, 19 warps ------------------
// GRB=14 rows/block, grid 147 (one wave). 608 threads; threads t<600:
// j = t>>1, half = t&1; half0 owns whh[j][0:48), half1 owns [48:100).
// Partial dots go to smem; elementwise sums the two halves + bhh.
#define GRB 14
#define GRU_T 608
#define NXV (GRB + WIND - 1)   // 23
// smem floats: xp[23*300] | xvs[23*100] | hs[14*100] | part[14*600] | bhs[300]
#define GRU_SMEM ((NXV*3*DOUT + NXV*DOUT + GRB*DOUT + GRB*600 + 3*DOUT) * 4)
__global__ void __launch_bounds__(GRU_T) gru_fused(
        const float* __restrict__ wih, const float* __restrict__ bih,
        const float* __restrict__ whh, const float* __restrict__ bhh) {
    extern __shared__ float smg[];
    float* xp   = smg;                       // [23][300]
    float* xvs  = xp + NXV*3*DOUT;           // [23][100]
    float* hs   = xvs + NXV*DOUT;            // [14][100]
    float* part = hs + GRB*DOUT;             // [14][600]
    float* bhs  = part + GRB*600;            // [300]
    const int tid = threadIdx.x;
    const int b0 = blockIdx.x * GRB;

    // stage s_utt slice + init
    for (int i = tid; i < NXV*DOUT; i += GRU_T) {
        int vi = i / DOUT, d = i - vi*DOUT;
        int v = b0 - (WIND - 1) + vi;
        xvs[i] = (v >= 0 && v < NB) ? g_sutt[v*DOUT + d] : 0.f;
    }
    for (int i = tid; i < GRB*DOUT; i += GRU_T) hs[i] = 0.f;
    for (int i = tid; i < 3*DOUT; i += GRU_T) bhs[i] = bhh[i];
    __syncthreads();

    // local xproj: xp[vi][j] = xvs[vi] . wih[j] + bih[j]
    for (int i = tid; i < NXV*3*DOUT; i += GRU_T) {
        int vi = i / (3*DOUT), j = i - vi*3*DOUT;
        const float4* wI = reinterpret_cast<const float4*>(wih + j*DOUT);
        const float4* xv = reinterpret_cast<const float4*>(xvs + vi*DOUT);
        float acc = 0.f;
        #pragma unroll
        for (int k = 0; k < DOUT/4; k++) {
            float4 w = wI[k], x = xv[k];
            acc += w.x*x.x + w.y*x.y + w.z*x.z + w.w*x.w;
        }
        xp[i] = acc + bih[j];
    }

    // split recurrent weights into registers
    const int j    = tid >> 1;
    const int half = tid & 1;
    const bool active = (tid < 600);
    const int k0  = half ? 48 : 0;       // float offset
    const int nk4 = half ? 13 : 12;      // float4 count (52 / 48)
    float4 w[13];
    if (active) {
        const float4* wr = reinterpret_cast<const float4*>(whh + j*DOUT + k0);
        for (int k4 = 0; k4 < nk4; k4++) w[k4] = wr[k4];
    }
    __syncthreads();

    for (int s = 0; s < WIND; s++) {
        if (active) {
            #pragma unroll
            for (int r = 0; r < GRB; r++) {
                const float4* h4 = reinterpret_cast<const float4*>(hs + r*DOUT + k0);
                float acc = 0.f;
                for (int k4 = 0; k4 < nk4; k4++) {
                    float4 wv = w[k4], h = h4[k4];
                    acc += wv.x*h.x + wv.y*h.y + wv.z*h.z + wv.w*h.w;
                }
                part[r*600 + tid] = acc;
            }
        }
        __syncthreads();
        for (int idx = tid; idx < GRB*DOUT; idx += GRU_T) {
            int r = idx / DOUT, d = idx - r*DOUT;
            int b = b0 + r;
            if (b < NB) {
                int vi = r + s;
                float giR = xp[vi*3*DOUT + d];
                float giZ = xp[vi*3*DOUT + DOUT + d];
                float giN = xp[vi*3*DOUT + 2*DOUT + d];
                float xv  = xvs[vi*DOUT + d];
                const float* pr = part + r*600;
                float hr = pr[2*d]            + pr[2*d + 1]            + bhs[d];
                float hz = pr[2*(DOUT + d)]   + pr[2*(DOUT + d) + 1]   + bhs[DOUT + d];
                float hn = pr[2*(2*DOUT + d)] + pr[2*(2*DOUT + d) + 1] + bhs[2*DOUT + d];
                float rr = 1.f / (1.f + expf(-(giR + hr)));
                float zz = 1.f / (1.f + expf(-(giZ + hz)));
                float nn = tanhf(giN + rr*hn);
                float hnew = (1.f - zz)*nn + zz*hs[r*DOUT + d];
                hs[r*DOUT + d] = hnew;
                g_memb[(b*WIND + s)*DOUT + d] = xv + hnew;
            }
        }
        __syncthreads();
    }
}

// ---------------- 3-hop attention: warp per window, register M --------------
__global__ void __launch_bounds__(256) attn_kernel(float* __restrict__ attn_out) {
    const int w = blockIdx.x * 8 + (threadIdx.x >> 5);
    const int lane = threadIdx.x & 31;
    if (w >= NB) return;

    float M[WIND][4], q[4];
    #pragma unroll
    for (int jj = 0; jj < 4; jj++) {
        int d = lane + 32*jj;
        bool ok = d < DOUT;
        q[jj] = ok ? g_sutt[(w + 1)*DOUT + d] : 0.f;
        #pragma unroll
        for (int k = 0; k < WIND; k++)
            M[k][jj] = ok ? g_memb[(w*WIND + k)*DOUT + d] : 0.f;
    }

    #pragma unroll
    for (int hop = 0; hop < HOPS; hop++) {
        float l[WIND];
        #pragma unroll
        for (int k = 0; k < WIND; k++) {
            float p = q[0]*M[k][0] + q[1]*M[k][1] + q[2]*M[k][2] + q[3]*M[k][3];
            #pragma unroll
            for (int off = 16; off; off >>= 1)
                p += __shfl_xor_sync(0xFFFFFFFFu, p, off);
            l[k] = (w + k - (WIND - 1) >= 0) ? p : -1e10f;
        }
        float mx = l[0];
        #pragma unroll
        for (int k = 1; k < WIND; k++) mx = fmaxf(mx, l[k]);
        float a[WIND], sum = 0.f;
        #pragma unroll
        for (int k = 0; k < WIND; k++) { a[k] = expf(l[k] - mx); sum += a[k]; }
        float inv = 1.f / sum;
        #pragma unroll
        for (int k = 0; k < WIND; k++) {
            a[k] *= inv;
            if (lane == k) attn_out[hop*(NB*WIND) + w*WIND + k] = a[k];
        }
        #pragma unroll
        for (int jj = 0; jj < 4; jj++) {
            float acc = 0.f;
            #pragma unroll
            for (int k = 0; k < WIND; k++) acc += a[k] * M[k][jj];
            q[jj] += acc;
        }
    }
    #pragma unroll
    for (int jj = 0; jj < 4; jj++) {
        int d = lane + 32*jj;
        if (d < DOUT) g_q[w*DOUT + d] = q[jj];
    }
}

// ---------------- classifier + log_softmax ----------------
__global__ void cls_kernel(const float* __restrict__ cw,
                           const float* __restrict__ cb,
                           float* __restrict__ pred_out) {
    int row = blockIdx.x * blockDim.x + threadIdx.x;
    if (row >= NU) return;
    const float* s = (row == 0) ? g_sutt : (g_q + (row - 1)*DOUT);
    float lg[NC];
    #pragma unroll
    for (int c = 0; c < NC; c++) {
        float acc = cb[c];
        const float* wr = cw + c*DOUT;
        #pragma unroll 4
        for (int k = 0; k < DOUT; k++) acc += s[k] * wr[k];
        lg[c] = acc;
    }
    float mx = lg[0];
    #pragma unroll
    for (int c = 1; c < NC; c++) mx = fmaxf(mx, lg[c]);
    float sum = 0.f;
    #pragma unroll
    for (int c = 0; c < NC; c++) sum += expf(lg[c] - mx);
    float lse = mx + logf(sum);
    #pragma unroll
    for (int c = 0; c < NC; c++) pred_out[row*NC + c] = lg[c] - lse;
}

// ---------------- launch sequence ----------------
extern "C" void kernel_launch(void* const* d_in, const int* in_sizes, int n_in,
                              void* d_out, int out_size) {
    const int*   sents   = (const int*)  d_in[0];
    const float* emb     = (const float*)d_in[2];
    const float* trans_w = (const float*)d_in[3];
    const float* trans_b = (const float*)d_in[4];
    const float* gru_wih = (const float*)d_in[5];
    const float* gru_whh = (const float*)d_in[6];
    const float* gru_bih = (const float*)d_in[7];
    const float* gru_bhh = (const float*)d_in[8];
    const float* cls_w   = (const float*)d_in[9];
    const float* cls_b   = (const float*)d_in[10];
    const float* conv_w3 = (const float*)d_in[11];
    const float* conv_b3 = (const float*)d_in[12];
    const float* conv_w4 = (const float*)d_in[13];
    const float* conv_b4 = (const float*)d_in[14];
    const float* conv_w5 = (const float*)d_in[15];
    const float* conv_b5 = (const float*)d_in[16];

    float* outF = (float*)d_out;
    float* pred_out = outF;
    float* attn_out;
    if (out_size >= NU*NC + HOPS*NB*WIND) attn_out = outF + NU*NC;
    else cudaGetSymbolAddress((void**)&attn_out, g_attn_scratch);

    cudaFuncSetAttribute(packall,         cudaFuncAttributeMaxDynamicSharedMemorySize, PACKA_SMEM);
    cudaFuncSetAttribute(conv_gemm_mma,   cudaFuncAttributeMaxDynamicSharedMemorySize, GEMM_SMEM);
    cudaFuncSetAttribute(poolsutt_kernel, cudaFuncAttributeMaxDynamicSharedMemorySize, POOL_SMEM);
    cudaFuncSetAttribute(gru_fused,       cudaFuncAttributeMaxDynamicSharedMemorySize, GRU_SMEM);

    packall<<<PA_BLOCKS + PB_BLOCKS + TW_BLOCKS, 256, PACKA_SMEM>>>(
        emb, conv_w3, conv_w4, conv_w5, trans_w);

    dim3 ggrid(NCOL/128, VPAD/128);   // (6, 391)
    conv_gemm_mma<<<ggrid, 256, GEMM_SMEM>>>();

    poolsutt_kernel<<<NU, POOL_T, POOL_SMEM>>>(sents, conv_b3, conv_b4, conv_b5, trans_b);
    gru_fused<<<(NB + GRB - 1)/GRB, GRU_T, GRU_SMEM>>>(gru_wih, gru_bih, gru_whh, gru_bhh);

    attn_kernel<<<(NB + 7)/8, 256>>>(attn_out);
    cls_kernel<<<(NU + 255)/256, 256>>>(cls_w, cls_b, pred_out);
}

// round 14
// speedup vs baseline: 1.2306x; 1.0451x over previous
#include <cuda_runtime.h>
#include <cuda_fp16.h>
#include <math.h>
#include <stdint.h>

// ---------------- problem constants ----------------
#define NU    2048
#define SL    50
#define DE    300
#define KPAD  320      // 20 k-groups of 16
#define DOUT  100
#define NC    7
#define WIND  10
#define HOPS  3
#define NB    2047
#define VOCAB 50000
#define VPAD  50048    // 391 * 128
#define NCOL  768
#define FCAT  192

// ---------------- static scratch ----------------
__device__ __half g_Ah[(size_t)VPAD*KPAD];      // A fp16 fragment order (128-row mblk)
__device__ __half g_Bh[NCOL*KPAD];              // B fp16 nt-pair fragment order (128-col nblk)
__device__ __half g_Zh[(size_t)VPAD*NCOL];      // fp16 projections (77 MB)
__device__ float g_twT[FCAT*DOUT];
__device__ float g_sutt[NU*DOUT];
__device__ float g_memb[NB*WIND*DOUT];
__device__ float g_q[NB*DOUT];
__device__ float g_attn_scratch[HOPS*NB*WIND];

// ---------------- helpers ----------------
__device__ __forceinline__ uint32_t smem_u32(const void* p) {
    uint32_t a;
    asm("{ .reg .u64 t; cvta.to.shared.u64 t, %1; cvt.u32.u64 %0, t; }" : "=r"(a) : "l"(p));
    return a;
}
#define CP_ASYNC16(sa, gp) asm volatile("cp.async.cg.shared.global [%0], [%1], 16;" :: "r"(sa), "l"(gp) : "memory")
#define CP_COMMIT()        asm volatile("cp.async.commit_group;" ::: "memory")
#define CP_WAIT(n)         asm volatile("cp.async.wait_group %0;" :: "n"(n) : "memory")

__device__ __forceinline__ void mma_fp16(float* d, const uint32_t* a, const uint32_t* b) {
    asm volatile("mma.sync.aligned.m16n8k16.row.col.f32.f16.f16.f32 "
        "{%0,%1,%2,%3}, {%4,%5,%6,%7}, {%8,%9}, {%0,%1,%2,%3};"
        : "+f"(d[0]), "+f"(d[1]), "+f"(d[2]), "+f"(d[3])
        : "r"(a[0]), "r"(a[1]), "r"(a[2]), "r"(a[3]), "r"(b[0]), "r"(b[1]));
}

// ---------------- merged pack: A-transpose + B + twT (one launch) -----------
#define PA_LDK 328
#define PACKA_SMEM (128*PA_LDK*2)
#define PA_BLOCKS (VPAD/128)   // 391
#define PB_BLOCKS 120          // 30720 d4 / 256
#define TW_BLOCKS 75           // 19200 / 256

__device__ __forceinline__ __half wall_h(const float* w3, const float* w4,
                                         const float* w5, int c, int k) {
    if (k >= DE) return __float2half_rn(0.f);
    float v;
    if (c < 192)      { int cc = c;       int dt = cc >> 6, o = cc & 63; v = w3[(o*3 + dt)*DE + k]; }
    else if (c < 448) { int cc = c - 192; int dt = cc >> 6, o = cc & 63; v = w4[(o*4 + dt)*DE + k]; }
    else              { int cc = c - 448; int dt = cc >> 6, o = cc & 63; v = w5[(o*5 + dt)*DE + k]; }
    return __float2half_rn(v);
}

__global__ void __launch_bounds__(256) packall(
        const float* __restrict__ emb,
        const float* __restrict__ w3, const float* __restrict__ w4,
        const float* __restrict__ w5, const float* __restrict__ tw) {
    const int tid = threadIdx.x;
    if (blockIdx.x < PA_BLOCKS) {
        extern __shared__ __half sa[];
        const int mblk = blockIdx.x;
        {
            uint4* s4 = reinterpret_cast<uint4*>(sa);
            for (int i = tid; i < 128*PA_LDK/8; i += 256)
                s4[i] = make_uint4(0, 0, 0, 0);
        }
        __syncthreads();
        {
            const float4* e4 = reinterpret_cast<const float4*>(emb);
            for (int i = tid; i < 128*75; i += 256) {
                int row = i / 75, c4 = i - row*75;
                int m = mblk*128 + row;
                if (m < VOCAB) {
                    float4 v = e4[(size_t)m*75 + c4];
                    __half2 lo = __floats2half2_rn(v.x, v.y);
                    __half2 hi = __floats2half2_rn(v.z, v.w);
                    uint2 pk = make_uint2(*(uint32_t*)&lo, *(uint32_t*)&hi);
                    *reinterpret_cast<uint2*>(sa + row*PA_LDK + c4*4) = pk;
                }
            }
        }
        __syncthreads();
        {
            const int lane = tid & 31;
            const int r16  = tid >> 5;
            const int mloc = r16*16 + (lane >> 2);
            const int kk   = (lane & 3)*2;
            const uint32_t* s32 = reinterpret_cast<const uint32_t*>(sa);
            uint4* out4 = reinterpret_cast<uint4*>(g_Ah);
            #pragma unroll 4
            for (int kc16 = 0; kc16 < 20; kc16++) {
                int k = kc16*16 + kk;
                uint32_t h0 = s32[( mloc      *PA_LDK + k    ) >> 1];
                uint32_t h1 = s32[((mloc + 8)*PA_LDK + k    ) >> 1];
                uint32_t h2 = s32[( mloc      *PA_LDK + k + 8) >> 1];
                uint32_t h3 = s32[((mloc + 8)*PA_LDK + k + 8) >> 1];
                out4[((size_t)(mblk*20 + kc16)*8 + r16)*32 + lane] = make_uint4(h0, h1, h2, h3);
            }
        }
    } else if (blockIdx.x < PA_BLOCKS + PB_BLOCKS) {
        int d4 = (blockIdx.x - PA_BLOCKS) * 256 + tid;
        int lane = d4 & 31;
        int np   = (d4 >> 5) & 7;
        int rest = d4 >> 8;
        int kc16 = rest % 20;
        int nblk = rest / 20;
        int na = nblk*128 + np*16 + (lane >> 2);
        int nb = na + 8;
        int k = kc16*16 + (lane & 3)*2;
        __half2 h0 = __halves2half2(wall_h(w3,w4,w5, na, k),     wall_h(w3,w4,w5, na, k + 1));
        __half2 h1 = __halves2half2(wall_h(w3,w4,w5, na, k + 8), wall_h(w3,w4,w5, na, k + 9));
        __half2 h2 = __halves2half2(wall_h(w3,w4,w5, nb, k),     wall_h(w3,w4,w5, nb, k + 1));
        __half2 h3 = __halves2half2(wall_h(w3,w4,w5, nb, k + 8), wall_h(w3,w4,w5, nb, k + 9));
        uint4 v = make_uint4(*(uint32_t*)&h0, *(uint32_t*)&h1, *(uint32_t*)&h2, *(uint32_t*)&h3);
        reinterpret_cast<uint4*>(g_Bh)[d4] = v;
    } else {
        int idx = (blockIdx.x - PA_BLOCKS - PB_BLOCKS) * 256 + tid;
        if (idx < FCAT*DOUT) {
            int j = idx / DOUT, d = idx % DOUT;
            g_twT[idx] = tw[d*FCAT + j];
        }
    }
}

// ---------------- fp16 mma GEMM: Z = Ah @ Bh^T (fp16 out) ----------------
#define GEMM_SMEM 49152

__global__ void __launch_bounds__(256, 2) conv_gemm_mma() {
    extern __shared__ char smc[];
    const int tid  = threadIdx.x;
    const int lane = tid & 31, wid = tid >> 5;
    const int warp_m = wid & 3;
    const int warp_n = wid >> 2;
    const int by = blockIdx.y, bx = blockIdx.x;
    const int m0 = by * 128, n0 = bx * 128;

    const uint32_t smb = smem_u32(smc);
    const uint4* Ah4 = reinterpret_cast<const uint4*>(g_Ah);
    const uint4* Bh4 = reinterpret_cast<const uint4*>(g_Bh);

    float acc[2][8][4];
    #pragma unroll
    for (int mt = 0; mt < 2; mt++)
        #pragma unroll
        for (int nt = 0; nt < 8; nt++)
            #pragma unroll
            for (int i = 0; i < 4; i++) acc[mt][nt][i] = 0.f;

    #pragma unroll
    for (int c = 0; c < 2; c++) {
        size_t aG = ((size_t)by*20 + c*2) * 256;
        size_t bG = ((size_t)bx*20 + c*2) * 256;
        #pragma unroll
        for (int i = 0; i < 2; i++) {
            CP_ASYNC16(smb +         c*8192 + (tid + i*256)*16, Ah4 + aG + tid + i*256);
            CP_ASYNC16(smb + 24576 + c*8192 + (tid + i*256)*16, Bh4 + bG + tid + i*256);
        }
        CP_COMMIT();
    }

    for (int c = 0; c < 10; c++) {
        const int buf = c % 3;
        if (c < 9) CP_WAIT(1); else CP_WAIT(0);
        __syncthreads();
        if (c + 2 < 10) {
            const int nb = (c + 2) % 3;
            size_t aG = ((size_t)by*20 + (c + 2)*2) * 256;
            size_t bG = ((size_t)bx*20 + (c + 2)*2) * 256;
            #pragma unroll
            for (int i = 0; i < 2; i++) {
                CP_ASYNC16(smb +         nb*8192 + (tid + i*256)*16, Ah4 + aG + tid + i*256);
                CP_ASYNC16(smb + 24576 + nb*8192 + (tid + i*256)*16, Bh4 + bG + tid + i*256);
            }
            CP_COMMIT();
        }

        const uint4* A4 = reinterpret_cast<const uint4*>(smc + buf*8192);
        const uint4* B4 = reinterpret_cast<const uint4*>(smc + 24576 + buf*8192);
        #pragma unroll
        for (int ks = 0; ks < 2; ks++) {
            uint32_t a[2][4], b[8][2];
            #pragma unroll
            for (int mt = 0; mt < 2; mt++) {
                uint4 v = A4[(ks*8 + warp_m*2 + mt)*32 + lane];
                a[mt][0] = v.x; a[mt][1] = v.y; a[mt][2] = v.z; a[mt][3] = v.w;
            }
            #pragma unroll
            for (int np = 0; np < 4; np++) {
                uint4 u = B4[(ks*8 + warp_n*4 + np)*32 + lane];
                b[2*np  ][0] = u.x; b[2*np  ][1] = u.y;
                b[2*np+1][0] = u.z; b[2*np+1][1] = u.w;
            }
            #pragma unroll
            for (int mt = 0; mt < 2; mt++)
                #pragma unroll
                for (int nt = 0; nt < 8; nt++)
                    mma_fp16(acc[mt][nt], a[mt], b[nt]);
        }
    }

    __half2* Z2 = reinterpret_cast<__half2*>(g_Zh);
    #pragma unroll
    for (int mt = 0; mt < 2; mt++) {
        int r = m0 + warp_m*32 + mt*16 + (lane >> 2);
        #pragma unroll
        for (int nt = 0; nt < 8; nt++) {
            int cc = n0 + warp_n*64 + nt*8 + (lane & 3)*2;
            Z2[((size_t) r      *NCOL + cc) >> 1] = __floats2half2_rn(acc[mt][nt][0], acc[mt][nt][1]);
            Z2[((size_t)(r + 8)*NCOL + cc) >> 1] = __floats2half2_rn(acc[mt][nt][2], acc[mt][nt][3]);
        }
    }
}

// ---------------- fused pool + relu + tanh projection -----------------------
#define POOL_T 768
#define POOL_SMEM (76800 + 200 + 6144 + 768)
__global__ void __launch_bounds__(POOL_T) poolsutt_kernel(
        const int* __restrict__ sents,
        const float* __restrict__ b3, const float* __restrict__ b4,
        const float* __restrict__ b5, const float* __restrict__ tb) {
    extern __shared__ char psm[];
    __half*  Zs    = reinterpret_cast<__half*>(psm);
    int*     toks  = reinterpret_cast<int*>(psm + 76800);
    float2*  pmax2 = reinterpret_cast<float2*>(psm + 77000);
    float*   fsh   = reinterpret_cast<float*>(psm + 83144);
    const int n = blockIdx.x;
    const int tid = threadIdx.x;
    const uint32_t zsb = smem_u32(Zs);

    if (tid < SL) toks[tid] = sents[n*SL + tid];
    __syncthreads();
    {
        const uint4* Zg4 = reinterpret_cast<const uint4*>(g_Zh);
        for (int i = tid; i < SL*96; i += POOL_T) {
            int row = i / 96, c4 = i - row*96;
            CP_ASYNC16(zsb + i*16, Zg4 + (size_t)toks[row]*96 + c4);
        }
        CP_COMMIT();
        CP_WAIT(0);
    }
    __syncthreads();
    {
        const int q  = tid / 96;
        const int p  = tid - q*96;
        const int fi = p >> 5, o2 = p & 31;
        const int fs  = 3 + fi;
        const int offh = ((fi == 0) ? 0 : (fi == 1) ? 192 : 448) / 2;
        const int T = SL - fs + 1;
        const int t0 = (T * q) >> 3;
        const int t1 = (T * (q + 1)) >> 3;
        const __half2* Zs2 = reinterpret_cast<const __half2*>(Zs);
        float mx0 = -1e30f, mx1 = -1e30f;
        for (int t = t0; t < t1; t++) {
            float v0 = 0.f, v1 = 0.f;
            #pragma unroll 5
            for (int dt = 0; dt < fs; dt++) {
                __half2 h = Zs2[(t + dt)*384 + offh + dt*32 + o2];
                float2 f = __half22float2(h);
                v0 += f.x; v1 += f.y;
            }
            mx0 = fmaxf(mx0, v0); mx1 = fmaxf(mx1, v1);
        }
        pmax2[q*96 + p] = make_float2(mx0, mx1);
    }
    __syncthreads();
    if (tid < 96) {
        const int fi = tid >> 5, o2 = tid & 31;
        const int fa = fi*64 + 2*o2;
        float m0 = -1e30f, m1 = -1e30f;
        #pragma unroll
        for (int q = 0; q < 8; q++) {
            float2 v = pmax2[q*96 + tid];
            m0 = fmaxf(m0, v.x); m1 = fmaxf(m1, v.y);
        }
        float ba = (fi == 0) ? b3[2*o2]     : (fi == 1) ? b4[2*o2]     : b5[2*o2];
        float bb = (fi == 0) ? b3[2*o2 + 1] : (fi == 1) ? b4[2*o2 + 1] : b5[2*o2 + 1];
        fsh[fa]     = fmaxf(0.f, m0 + ba);
        fsh[fa + 1] = fmaxf(0.f, m1 + bb);
    }
    __syncthreads();
    if (tid < DOUT) {
        float acc = tb[tid];
        #pragma unroll 8
        for (int j = 0; j < FCAT; j++) acc += fsh[j] * g_twT[j*DOUT + tid];
        g_sutt[n*DOUT + tid] = tanhf(acc);
    }
}

// ---------------- fused GRU v4: gate-sharing, 1 LDS : 12 FMA -----------------
// 512 thr; t<500: d = t%100, sl = t/100 (k-slice of 20 floats). Thread owns
// whh rows {d, 100+d, 200+d} slice [sl*20, sl*20+20) in regs (60 floats).
// Per step/r: 5 broadcast h-loads feed 15 FMA4 (3 independent chains).
// Partials [r][gate][sl][d] summed (5 slices + bias) in the elementwise phase.
#define GRB 14
#define GRU_T 512
#define NXV (GRB + WIND - 1)   // 23
// smem floats: xp[23*300] | xvs[23*100] | hs[14*100] | part[14*1500] | bhs[300]
#define GRU_SMEM ((NXV*3*DOUT + NXV*DOUT + GRB*DOUT + GRB*1500 + 3*DOUT) * 4)
__global__ void __launch_bounds__(GRU_T) gru_fused(
        const float* __restrict__ wih, const float* __restrict__ bih,
        const float* __restrict__ whh, const float* __restrict__ bhh) {
    extern __shared__ float smg[];
    float* xp   = smg;                       // [23][300]
    float* xvs  = xp + NXV*3*DOUT;           // [23][100]
    float* hs   = xvs + NXV*DOUT;            // [14][100]
    float* part = hs + GRB*DOUT;             // [14][3][5][100]
    float* bhs  = part + GRB*1500;           // [300]
    const int tid = threadIdx.x;
    const int b0 = blockIdx.x * GRB;

    // stage s_utt slice + init
    for (int i = tid; i < NXV*DOUT; i += GRU_T) {
        int vi = i / DOUT, d = i - vi*DOUT;
        int v = b0 - (WIND - 1) + vi;
        xvs[i] = (v >= 0 && v < NB) ? g_sutt[v*DOUT + d] : 0.f;
    }
    for (int i = tid; i < GRB*DOUT; i += GRU_T) hs[i] = 0.f;
    for (int i = tid; i < 3*DOUT; i += GRU_T) bhs[i] = bhh[i];
    __syncthreads();

    // local xproj: xp[vi][j] = xvs[vi] . wih[j] + bih[j]
    for (int i = tid; i < NXV*3*DOUT; i += GRU_T) {
        int vi = i / (3*DOUT), j = i - vi*3*DOUT;
        const float4* wI = reinterpret_cast<const float4*>(wih + j*DOUT);
        const float4* xv = reinterpret_cast<const float4*>(xvs + vi*DOUT);
        float acc = 0.f;
        #pragma unroll
        for (int k = 0; k < DOUT/4; k++) {
            float4 w = wI[k], x = xv[k];
            acc += w.x*x.x + w.y*x.y + w.z*x.z + w.w*x.w;
        }
        xp[i] = acc + bih[j];
    }

    // gate-triple recurrent weights into registers
    const int d_own = tid % 100;
    const int sl    = tid / 100;         // 0..4 (tid<500)
    const bool active = (tid < 500);
    const int k0 = sl * 20;
    float4 w[3][5];
    if (active) {
        #pragma unroll
        for (int g = 0; g < 3; g++) {
            const float4* wr = reinterpret_cast<const float4*>(whh + (g*DOUT + d_own)*DOUT + k0);
            #pragma unroll
            for (int k4 = 0; k4 < 5; k4++) w[g][k4] = wr[k4];
        }
    }
    __syncthreads();

    for (int s = 0; s < WIND; s++) {
        if (active) {
            float* pbase = part + sl*100 + d_own;
            #pragma unroll
            for (int r = 0; r < GRB; r++) {
                const float4* h4 = reinterpret_cast<const float4*>(hs + r*DOUT + k0);
                float a0 = 0.f, a1 = 0.f, a2 = 0.f;
                #pragma unroll
                for (int k4 = 0; k4 < 5; k4++) {
                    float4 h = h4[k4];
                    a0 += w[0][k4].x*h.x + w[0][k4].y*h.y + w[0][k4].z*h.z + w[0][k4].w*h.w;
                    a1 += w[1][k4].x*h.x + w[1][k4].y*h.y + w[1][k4].z*h.z + w[1][k4].w*h.w;
                    a2 += w[2][k4].x*h.x + w[2][k4].y*h.y + w[2][k4].z*h.z + w[2][k4].w*h.w;
                }
                float* pr = pbase + r*1500;
                pr[0] = a0; pr[500] = a1; pr[1000] = a2;
            }
        }
        __syncthreads();
        for (int idx = tid; idx < GRB*DOUT; idx += GRU_T) {
            int r = idx / DOUT, d = idx - r*DOUT;
            int b = b0 + r;
            if (b < NB) {
                int vi = r + s;
                float giR = xp[vi*3*DOUT + d];
                float giZ = xp[vi*3*DOUT + DOUT + d];
                float giN = xp[vi*3*DOUT + 2*DOUT + d];
                float xv  = xvs[vi*DOUT + d];
                const float* pr = part + r*1500 + d;
                float hr = ((pr[0]    + pr[100])  + (pr[200]  + pr[300]))  + (pr[400]  + bhs[d]);
                float hz = ((pr[500]  + pr[600])  + (pr[700]  + pr[800]))  + (pr[900]  + bhs[DOUT + d]);
                float hn = ((pr[1000] + pr[1100]) + (pr[1200] + pr[1300])) + (pr[1400] + bhs[2*DOUT + d]);
                float rr = 1.f / (1.f + expf(-(giR + hr)));
                float zz = 1.f / (1.f + expf(-(giZ + hz)));
                float nn = tanhf(giN + rr*hn);
                float hnew = (1.f - zz)*nn + zz*hs[r*DOUT + d];
                hs[r*DOUT + d] = hnew;
                g_memb[(b*WIND + s)*DOUT + d] = xv + hnew;
            }
        }
        __syncthreads();
    }
}

// ---------------- 3-hop attention: warp per window, register M --------------
__global__ void __launch_bounds__(256) attn_kernel(float* __restrict__ attn_out) {
    const int w = blockIdx.x * 8 + (threadIdx.x >> 5);
    const int lane = threadIdx.x & 31;
    if (w >= NB) return;

    float M[WIND][4], q[4];
    #pragma unroll
    for (int jj = 0; jj < 4; jj++) {
        int d = lane + 32*jj;
        bool ok = d < DOUT;
        q[jj] = ok ? g_sutt[(w + 1)*DOUT + d] : 0.f;
        #pragma unroll
        for (int k = 0; k < WIND; k++)
            M[k][jj] = ok ? g_memb[(w*WIND + k)*DOUT + d] : 0.f;
    }

    #pragma unroll
    for (int hop = 0; hop < HOPS; hop++) {
        float l[WIND];
        #pragma unroll
        for (int k = 0; k < WIND; k++) {
            float p = q[0]*M[k][0] + q[1]*M[k][1] + q[2]*M[k][2] + q[3]*M[k][3];
            #pragma unroll
            for (int off = 16; off; off >>= 1)
                p += __shfl_xor_sync(0xFFFFFFFFu, p, off);
            l[k] = (w + k - (WIND - 1) >= 0) ? p : -1e10f;
        }
        float mx = l[0];
        #pragma unroll
        for (int k = 1; k < WIND; k++) mx = fmaxf(mx, l[k]);
        float a[WIND], sum = 0.f;
        #pragma unroll
        for (int k = 0; k < WIND; k++) { a[k] = expf(l[k] - mx); sum += a[k]; }
        float inv = 1.f / sum;
        #pragma unroll
        for (int k = 0; k < WIND; k++) {
            a[k] *= inv;
            if (lane == k) attn_out[hop*(NB*WIND) + w*WIND + k] = a[k];
        }
        #pragma unroll
        for (int jj = 0; jj < 4; jj++) {
            float acc = 0.f;
            #pragma unroll
            for (int k = 0; k < WIND; k++) acc += a[k] * M[k][jj];
            q[jj] += acc;
        }
    }
    #pragma unroll
    for (int jj = 0; jj < 4; jj++) {
        int d = lane + 32*jj;
        if (d < DOUT) g_q[w*DOUT + d] = q[jj];
    }
}

// ---------------- classifier + log_softmax ----------------
__global__ void cls_kernel(const float* __restrict__ cw,
                           const float* __restrict__ cb,
                           float* __restrict__ pred_out) {
    int row = blockIdx.x * blockDim.x + threadIdx.x;
    if (row >= NU) return;
    const float* s = (row == 0) ? g_sutt : (g_q + (row - 1)*DOUT);
    float lg[NC];
    #pragma unroll
    for (int c = 0; c < NC; c++) {
        float acc = cb[c];
        const float* wr = cw + c*DOUT;
        #pragma unroll 4
        for (int k = 0; k < DOUT; k++) acc += s[k] * wr[k];
        lg[c] = acc;
    }
    float mx = lg[0];
    #pragma unroll
    for (int c = 1; c < NC; c++) mx = fmaxf(mx, lg[c]);
    float sum = 0.f;
    #pragma unroll
    for (int c = 0; c < NC; c++) sum += expf(lg[c] - mx);
    float lse = mx + logf(sum);
    #pragma unroll
    for (int c = 0; c < NC; c++) pred_out[row*NC + c] = lg[c] - lse;
}

// ---------------- launch sequence ----------------
extern "C" void kernel_launch(void* const* d_in, const int* in_sizes, int n_in,
                              void* d_out, int out_size) {
    const int*   sents   = (const int*)  d_in[0];
    const float* emb     = (const float*)d_in[2];
    const float* trans_w = (const float*)d_in[3];
    const float* trans_b = (const float*)d_in[4];
    const float* gru_wih = (const float*)d_in[5];
    const float* gru_whh = (const float*)d_in[6];
    const float* gru_bih = (const float*)d_in[7];
    const float* gru_bhh = (const float*)d_in[8];
    const float* cls_w   = (const float*)d_in[9];
    const float* cls_b   = (const float*)d_in[10];
    const float* conv_w3 = (const float*)d_in[11];
    const float* conv_b3 = (const float*)d_in[12];
    const float* conv_w4 = (const float*)d_in[13];
    const float* conv_b4 = (const float*)d_in[14];
    const float* conv_w5 = (const float*)d_in[15];
    const float* conv_b5 = (const float*)d_in[16];

    float* outF = (float*)d_out;
    float* pred_out = outF;
    float* attn_out;
    if (out_size >= NU*NC + HOPS*NB*WIND) attn_out = outF + NU*NC;
    else cudaGetSymbolAddress((void**)&attn_out, g_attn_scratch);

    cudaFuncSetAttribute(packall,         cudaFuncAttributeMaxDynamicSharedMemorySize, PACKA_SMEM);
    cudaFuncSetAttribute(conv_gemm_mma,   cudaFuncAttributeMaxDynamicSharedMemorySize, GEMM_SMEM);
    cudaFuncSetAttribute(poolsutt_kernel, cudaFuncAttributeMaxDynamicSharedMemorySize, POOL_SMEM);
    cudaFuncSetAttribute(gru_fused,       cudaFuncAttributeMaxDynamicSharedMemorySize, GRU_SMEM);

    packall<<<PA_BLOCKS + PB_BLOCKS + TW_BLOCKS, 256, PACKA_SMEM>>>(
        emb, conv_w3, conv_w4, conv_w5, trans_w);

    dim3 ggrid(NCOL/128, VPAD/128);   // (6, 391)
    conv_gemm_mma<<<ggrid, 256, GEMM_SMEM>>>();

    poolsutt_kernel<<<NU, POOL_T, POOL_SMEM>>>(sents, conv_b3, conv_b4, conv_b5, trans_b);
    gru_fused<<<(NB + GRB - 1)/GRB, GRU_T, GRU_SMEM>>>(gru_wih, gru_bih, gru_whh, gru_bhh);

    attn_kernel<<<(NB + 7)/8, 256>>>(attn_out);
    cls_kernel<<<(NU + 255)/256, 256>>>(cls_w, cls_b, pred_out);
}

// round 15
// speedup vs baseline: 1.2864x; 1.0453x over previous
#include <cuda_runtime.h>
#include <cuda_fp16.h>
#include <math.h>
#include <stdint.h>

// ---------------- problem constants ----------------
#define NU    2048
#define SL    50
#define DE    300
#define KPAD  320      // 20 k-groups of 16
#define DOUT  100
#define NC    7
#define WIND  10
#define HOPS  3
#define NB    2047
#define VOCAB 50000
#define VPAD  50048    // 391 * 128
#define NCOL  768
#define FCAT  192

// ---------------- static scratch ----------------
__device__ __half g_Ah[(size_t)VPAD*KPAD];      // A fp16 fragment order (128-row mblk)
__device__ __half g_Bh[NCOL*KPAD];              // B fp16 nt-pair fragment order (128-col nblk)
__device__ __half g_Zh[(size_t)VPAD*NCOL];      // fp16 projections (77 MB)
__device__ float g_twT[FCAT*DOUT];
__device__ float g_sutt[NU*DOUT];
__device__ float g_memb[NB*WIND*DOUT];
__device__ float g_q[NB*DOUT];
__device__ float g_attn_scratch[HOPS*NB*WIND];
__device__ uint2 g_WhhF[8*5*7*32];               // whh fp16 B-fragments [w][t][c][lane]

// ---------------- helpers ----------------
__device__ __forceinline__ uint32_t smem_u32(const void* p) {
    uint32_t a;
    asm("{ .reg .u64 t; cvta.to.shared.u64 t, %1; cvt.u32.u64 %0, t; }" : "=r"(a) : "l"(p));
    return a;
}
#define CP_ASYNC16(sa, gp) asm volatile("cp.async.cg.shared.global [%0], [%1], 16;" :: "r"(sa), "l"(gp) : "memory")
#define CP_COMMIT()        asm volatile("cp.async.commit_group;" ::: "memory")
#define CP_WAIT(n)         asm volatile("cp.async.wait_group %0;" :: "n"(n) : "memory")

__device__ __forceinline__ void mma_fp16(float* d, const uint32_t* a, const uint32_t* b) {
    asm volatile("mma.sync.aligned.m16n8k16.row.col.f32.f16.f16.f32 "
        "{%0,%1,%2,%3}, {%4,%5,%6,%7}, {%8,%9}, {%0,%1,%2,%3};"
        : "+f"(d[0]), "+f"(d[1]), "+f"(d[2]), "+f"(d[3])
        : "r"(a[0]), "r"(a[1]), "r"(a[2]), "r"(a[3]), "r"(b[0]), "r"(b[1]));
}

// ---------------- merged pack: A-transpose + B + twT + WhhF ----------------
#define PA_LDK 328
#define PACKA_SMEM (128*PA_LDK*2)
#define PA_BLOCKS (VPAD/128)   // 391
#define PB_BLOCKS 120          // 30720 d4 / 256
#define TW_BLOCKS 75           // 19200 / 256
#define WF_BLOCKS 35           // 8960 uint2 / 256

__device__ __forceinline__ __half wall_h(const float* w3, const float* w4,
                                         const float* w5, int c, int k) {
    if (k >= DE) return __float2half_rn(0.f);
    float v;
    if (c < 192)      { int cc = c;       int dt = cc >> 6, o = cc & 63; v = w3[(o*3 + dt)*DE + k]; }
    else if (c < 448) { int cc = c - 192; int dt = cc >> 6, o = cc & 63; v = w4[(o*4 + dt)*DE + k]; }
    else              { int cc = c - 448; int dt = cc >> 6, o = cc & 63; v = w5[(o*5 + dt)*DE + k]; }
    return __float2half_rn(v);
}
__device__ __forceinline__ __half whh_h(const float* whh, int n, int k) {
    if (n >= 3*DOUT || k >= DOUT) return __float2half_rn(0.f);
    return __float2half_rn(whh[n*DOUT + k]);
}

__global__ void __launch_bounds__(256) packall(
        const float* __restrict__ emb,
        const float* __restrict__ w3, const float* __restrict__ w4,
        const float* __restrict__ w5, const float* __restrict__ tw,
        const float* __restrict__ whh) {
    const int tid = threadIdx.x;
    if (blockIdx.x < PA_BLOCKS) {
        extern __shared__ __half sa[];
        const int mblk = blockIdx.x;
        {
            uint4* s4 = reinterpret_cast<uint4*>(sa);
            for (int i = tid; i < 128*PA_LDK/8; i += 256)
                s4[i] = make_uint4(0, 0, 0, 0);
        }
        __syncthreads();
        {
            const float4* e4 = reinterpret_cast<const float4*>(emb);
            for (int i = tid; i < 128*75; i += 256) {
                int row = i / 75, c4 = i - row*75;
                int m = mblk*128 + row;
                if (m < VOCAB) {
                    float4 v = e4[(size_t)m*75 + c4];
                    __half2 lo = __floats2half2_rn(v.x, v.y);
                    __half2 hi = __floats2half2_rn(v.z, v.w);
                    uint2 pk = make_uint2(*(uint32_t*)&lo, *(uint32_t*)&hi);
                    *reinterpret_cast<uint2*>(sa + row*PA_LDK + c4*4) = pk;
                }
            }
        }
        __syncthreads();
        {
            const int lane = tid & 31;
            const int r16  = tid >> 5;
            const int mloc = r16*16 + (lane >> 2);
            const int kk   = (lane & 3)*2;
            const uint32_t* s32 = reinterpret_cast<const uint32_t*>(sa);
            uint4* out4 = reinterpret_cast<uint4*>(g_Ah);
            #pragma unroll 4
            for (int kc16 = 0; kc16 < 20; kc16++) {
                int k = kc16*16 + kk;
                uint32_t h0 = s32[( mloc      *PA_LDK + k    ) >> 1];
                uint32_t h1 = s32[((mloc + 8)*PA_LDK + k    ) >> 1];
                uint32_t h2 = s32[( mloc      *PA_LDK + k + 8) >> 1];
                uint32_t h3 = s32[((mloc + 8)*PA_LDK + k + 8) >> 1];
                out4[((size_t)(mblk*20 + kc16)*8 + r16)*32 + lane] = make_uint4(h0, h1, h2, h3);
            }
        }
    } else if (blockIdx.x < PA_BLOCKS + PB_BLOCKS) {
        int d4 = (blockIdx.x - PA_BLOCKS) * 256 + tid;
        int lane = d4 & 31;
        int np   = (d4 >> 5) & 7;
        int rest = d4 >> 8;
        int kc16 = rest % 20;
        int nblk = rest / 20;
        int na = nblk*128 + np*16 + (lane >> 2);
        int nb = na + 8;
        int k = kc16*16 + (lane & 3)*2;
        __half2 h0 = __halves2half2(wall_h(w3,w4,w5, na, k),     wall_h(w3,w4,w5, na, k + 1));
        __half2 h1 = __halves2half2(wall_h(w3,w4,w5, na, k + 8), wall_h(w3,w4,w5, na, k + 9));
        __half2 h2 = __halves2half2(wall_h(w3,w4,w5, nb, k),     wall_h(w3,w4,w5, nb, k + 1));
        __half2 h3 = __halves2half2(wall_h(w3,w4,w5, nb, k + 8), wall_h(w3,w4,w5, nb, k + 9));
        uint4 v = make_uint4(*(uint32_t*)&h0, *(uint32_t*)&h1, *(uint32_t*)&h2, *(uint32_t*)&h3);
        reinterpret_cast<uint4*>(g_Bh)[d4] = v;
    } else if (blockIdx.x < PA_BLOCKS + PB_BLOCKS + TW_BLOCKS) {
        int idx = (blockIdx.x - PA_BLOCKS - PB_BLOCKS) * 256 + tid;
        if (idx < FCAT*DOUT) {
            int j = idx / DOUT, d = idx % DOUT;
            g_twT[idx] = tw[d*FCAT + j];
        }
    } else {
        // pack whh B-fragments: idx -> [w][t][c][lane]
        int idx = (blockIdx.x - PA_BLOCKS - PB_BLOCKS - TW_BLOCKS) * 256 + tid;
        if (idx < 8*5*7*32) {
            int lane = idx & 31;
            int c = (idx >> 5) % 7;
            int rest = (idx >> 5) / 7;
            int t = rest % 5;
            int w = rest / 5;
            int n = w*40 + t*8 + (lane >> 2);
            int k = c*16 + (lane & 3)*2;
            __half2 b0 = __halves2half2(whh_h(whh, n, k),     whh_h(whh, n, k + 1));
            __half2 b1 = __halves2half2(whh_h(whh, n, k + 8), whh_h(whh, n, k + 9));
            g_WhhF[idx] = make_uint2(*(uint32_t*)&b0, *(uint32_t*)&b1);
        }
    }
}

// ---------------- fp16 mma GEMM: Z = Ah @ Bh^T (fp16 out) ----------------
#define GEMM_SMEM 49152

__global__ void __launch_bounds__(256, 2) conv_gemm_mma() {
    extern __shared__ char smc[];
    const int tid  = threadIdx.x;
    const int lane = tid & 31, wid = tid >> 5;
    const int warp_m = wid & 3;
    const int warp_n = wid >> 2;
    const int by = blockIdx.y, bx = blockIdx.x;
    const int m0 = by * 128, n0 = bx * 128;

    const uint32_t smb = smem_u32(smc);
    const uint4* Ah4 = reinterpret_cast<const uint4*>(g_Ah);
    const uint4* Bh4 = reinterpret_cast<const uint4*>(g_Bh);

    float acc[2][8][4];
    #pragma unroll
    for (int mt = 0; mt < 2; mt++)
        #pragma unroll
        for (int nt = 0; nt < 8; nt++)
            #pragma unroll
            for (int i = 0; i < 4; i++) acc[mt][nt][i] = 0.f;

    #pragma unroll
    for (int c = 0; c < 2; c++) {
        size_t aG = ((size_t)by*20 + c*2) * 256;
        size_t bG = ((size_t)bx*20 + c*2) * 256;
        #pragma unroll
        for (int i = 0; i < 2; i++) {
            CP_ASYNC16(smb +         c*8192 + (tid + i*256)*16, Ah4 + aG + tid + i*256);
            CP_ASYNC16(smb + 24576 + c*8192 + (tid + i*256)*16, Bh4 + bG + tid + i*256);
        }
        CP_COMMIT();
    }

    for (int c = 0; c < 10; c++) {
        const int buf = c % 3;
        if (c < 9) CP_WAIT(1); else CP_WAIT(0);
        __syncthreads();
        if (c + 2 < 10) {
            const int nb = (c + 2) % 3;
            size_t aG = ((size_t)by*20 + (c + 2)*2) * 256;
            size_t bG = ((size_t)bx*20 + (c + 2)*2) * 256;
            #pragma unroll
            for (int i = 0; i < 2; i++) {
                CP_ASYNC16(smb +         nb*8192 + (tid + i*256)*16, Ah4 + aG + tid + i*256);
                CP_ASYNC16(smb + 24576 + nb*8192 + (tid + i*256)*16, Bh4 + bG + tid + i*256);
            }
            CP_COMMIT();
        }

        const uint4* A4 = reinterpret_cast<const uint4*>(smc + buf*8192);
        const uint4* B4 = reinterpret_cast<const uint4*>(smc + 24576 + buf*8192);
        #pragma unroll
        for (int ks = 0; ks < 2; ks++) {
            uint32_t a[2][4], b[8][2];
            #pragma unroll
            for (int mt = 0; mt < 2; mt++) {
                uint4 v = A4[(ks*8 + warp_m*2 + mt)*32 + lane];
                a[mt][0] = v.x; a[mt][1] = v.y; a[mt][2] = v.z; a[mt][3] = v.w;
            }
            #pragma unroll
            for (int np = 0; np < 4; np++) {
                uint4 u = B4[(ks*8 + warp_n*4 + np)*32 + lane];
                b[2*np  ][0] = u.x; b[2*np  ][1] = u.y;
                b[2*np+1][0] = u.z; b[2*np+1][1] = u.w;
            }
            #pragma unroll
            for (int mt = 0; mt < 2; mt++)
                #pragma unroll
                for (int nt = 0; nt < 8; nt++)
                    mma_fp16(acc[mt][nt], a[mt], b[nt]);
        }
    }

    __half2* Z2 = reinterpret_cast<__half2*>(g_Zh);
    #pragma unroll
    for (int mt = 0; mt < 2; mt++) {
        int r = m0 + warp_m*32 + mt*16 + (lane >> 2);
        #pragma unroll
        for (int nt = 0; nt < 8; nt++) {
            int cc = n0 + warp_n*64 + nt*8 + (lane & 3)*2;
            Z2[((size_t) r      *NCOL + cc) >> 1] = __floats2half2_rn(acc[mt][nt][0], acc[mt][nt][1]);
            Z2[((size_t)(r + 8)*NCOL + cc) >> 1] = __floats2half2_rn(acc[mt][nt][2], acc[mt][nt][3]);
        }
    }
}

// ---------------- fused pool + relu + tanh projection -----------------------
#define POOL_T 768
#define POOL_SMEM (76800 + 200 + 6144 + 768)
__global__ void __launch_bounds__(POOL_T) poolsutt_kernel(
        const int* __restrict__ sents,
        const float* __restrict__ b3, const float* __restrict__ b4,
        const float* __restrict__ b5, const float* __restrict__ tb) {
    extern __shared__ char psm[];
    __half*  Zs    = reinterpret_cast<__half*>(psm);
    int*     toks  = reinterpret_cast<int*>(psm + 76800);
    float2*  pmax2 = reinterpret_cast<float2*>(psm + 77000);
    float*   fsh   = reinterpret_cast<float*>(psm + 83144);
    const int n = blockIdx.x;
    const int tid = threadIdx.x;
    const uint32_t zsb = smem_u32(Zs);

    if (tid < SL) toks[tid] = sents[n*SL + tid];
    __syncthreads();
    {
        const uint4* Zg4 = reinterpret_cast<const uint4*>(g_Zh);
        for (int i = tid; i < SL*96; i += POOL_T) {
            int row = i / 96, c4 = i - row*96;
            CP_ASYNC16(zsb + i*16, Zg4 + (size_t)toks[row]*96 + c4);
        }
        CP_COMMIT();
        CP_WAIT(0);
    }
    __syncthreads();
    {
        const int q  = tid / 96;
        const int p  = tid - q*96;
        const int fi = p >> 5, o2 = p & 31;
        const int fs  = 3 + fi;
        const int offh = ((fi == 0) ? 0 : (fi == 1) ? 192 : 448) / 2;
        const int T = SL - fs + 1;
        const int t0 = (T * q) >> 3;
        const int t1 = (T * (q + 1)) >> 3;
        const __half2* Zs2 = reinterpret_cast<const __half2*>(Zs);
        float mx0 = -1e30f, mx1 = -1e30f;
        for (int t = t0; t < t1; t++) {
            float v0 = 0.f, v1 = 0.f;
            #pragma unroll 5
            for (int dt = 0; dt < fs; dt++) {
                __half2 h = Zs2[(t + dt)*384 + offh + dt*32 + o2];
                float2 f = __half22float2(h);
                v0 += f.x; v1 += f.y;
            }
            mx0 = fmaxf(mx0, v0); mx1 = fmaxf(mx1, v1);
        }
        pmax2[q*96 + p] = make_float2(mx0, mx1);
    }
    __syncthreads();
    if (tid < 96) {
        const int fi = tid >> 5, o2 = tid & 31;
        const int fa = fi*64 + 2*o2;
        float m0 = -1e30f, m1 = -1e30f;
        #pragma unroll
        for (int q = 0; q < 8; q++) {
            float2 v = pmax2[q*96 + tid];
            m0 = fmaxf(m0, v.x); m1 = fmaxf(m1, v.y);
        }
        float ba = (fi == 0) ? b3[2*o2]     : (fi == 1) ? b4[2*o2]     : b5[2*o2];
        float bb = (fi == 0) ? b3[2*o2 + 1] : (fi == 1) ? b4[2*o2 + 1] : b5[2*o2 + 1];
        fsh[fa]     = fmaxf(0.f, m0 + ba);
        fsh[fa + 1] = fmaxf(0.f, m1 + bb);
    }
    __syncthreads();
    if (tid < DOUT) {
        float acc = tb[tid];
        #pragma unroll 8
        for (int j = 0; j < FCAT; j++) acc += fsh[j] * g_twT[j*DOUT + tid];
        g_sutt[n*DOUT + tid] = tanhf(acc);
    }
}

// ---------------- fused GRU v5: HMMA recurrent matmul ------------------------
// 256 thr = 8 warps. GRB=16 rows (one m16 tile). Per step:
//   convert hs->fp16 tile (stride 120 halves, conflict-free fragment LDS),
//   each warp: 7 k16 chunks x 5 n8 tiles of mma (B frags resident in regs),
//   store D-frags to gh, elementwise as before.
#define GRB 16
#define GRU_T 256
#define NXV (GRB + WIND - 1)   // 25
// smem: floats xp[7500] xvs[2500] hs[1600] gh[4800] bhs[300] = 16700 f -> 66800 B
//       h16 tile 16*120 halves -> 3840 B at offset 66800
#define GRU_SMEM (66800 + 3840)
__global__ void __launch_bounds__(GRU_T, 1) gru_fused(
        const float* __restrict__ wih, const float* __restrict__ bih,
        const float* __restrict__ bhh) {
    extern __shared__ char smraw[];
    float* xp  = reinterpret_cast<float*>(smraw);            // [25][300]
    float* xvs = xp + NXV*3*DOUT;                            // [25][100]
    float* hs  = xvs + NXV*DOUT;                             // [16][100]
    float* gh  = hs + GRB*DOUT;                              // [16][300]
    float* bhs = gh + GRB*3*DOUT;                            // [300]
    uint32_t* h16 = reinterpret_cast<uint32_t*>(smraw + 66800); // [16][60] u32 (120 halves/row)
    const int tid = threadIdx.x;
    const int lane = tid & 31, wid = tid >> 5;
    const int b0 = blockIdx.x * GRB;

    // B fragments resident in registers for all steps
    uint2 Bf[5][7];
    #pragma unroll
    for (int t = 0; t < 5; t++)
        #pragma unroll
        for (int c = 0; c < 7; c++)
            Bf[t][c] = g_WhhF[((wid*5 + t)*7 + c)*32 + lane];

    // stage s_utt slice + init
    for (int i = tid; i < NXV*DOUT; i += GRU_T) {
        int vi = i / DOUT, d = i - vi*DOUT;
        int v = b0 - (WIND - 1) + vi;
        xvs[i] = (v >= 0 && v < NB) ? g_sutt[v*DOUT + d] : 0.f;
    }
    for (int i = tid; i < GRB*DOUT; i += GRU_T) hs[i] = 0.f;
    for (int i = tid; i < 3*DOUT; i += GRU_T) bhs[i] = bhh[i];
    for (int i = tid; i < 16*60; i += GRU_T) h16[i] = 0;   // zero incl. K-pad
    __syncthreads();

    // local xproj: xp[vi][j] = xvs[vi] . wih[j] + bih[j]
    for (int i = tid; i < NXV*3*DOUT; i += GRU_T) {
        int vi = i / (3*DOUT), j = i - vi*3*DOUT;
        const float4* wI = reinterpret_cast<const float4*>(wih + j*DOUT);
        const float4* xv = reinterpret_cast<const float4*>(xvs + vi*DOUT);
        float acc = 0.f;
        #pragma unroll
        for (int k = 0; k < DOUT/4; k++) {
            float4 w = wI[k], x = xv[k];
            acc += w.x*x.x + w.y*x.y + w.z*x.z + w.w*x.w;
        }
        xp[i] = acc + bih[j];
    }
    __syncthreads();

    for (int s = 0; s < WIND; s++) {
        // convert hs -> fp16 tile (k < 100 only; pad stays 0)
        for (int i = tid; i < GRB*50; i += GRU_T) {
            int r = i / 50, kp = i - r*50;
            __half2 h = __floats2half2_rn(hs[r*DOUT + 2*kp], hs[r*DOUT + 2*kp + 1]);
            h16[r*60 + kp] = *(uint32_t*)&h;
        }
        __syncthreads();

        // HMMA: gh[0:16][wid*40 .. wid*40+40) (clipped to <300)
        {
            float acc[5][4];
            #pragma unroll
            for (int t = 0; t < 5; t++)
                #pragma unroll
                for (int i = 0; i < 4; i++) acc[t][i] = 0.f;
            const int row = lane >> 2, q = lane & 3;
            #pragma unroll
            for (int c = 0; c < 7; c++) {
                uint32_t a[4];
                a[0] = h16[ row      *60 + c*8 + q];
                a[1] = h16[(row + 8)*60 + c*8 + q];
                a[2] = h16[ row      *60 + c*8 + q + 4];
                a[3] = h16[(row + 8)*60 + c*8 + q + 4];
                #pragma unroll
                for (int t = 0; t < 5; t++)
                    mma_fp16(acc[t], a, (const uint32_t*)&Bf[t][c]);
            }
            #pragma unroll
            for (int t = 0; t < 5; t++) {
                int n = wid*40 + t*8 + q*2;
                if (n < 3*DOUT) {
                    *reinterpret_cast<float2*>(&gh[ row      *3*DOUT + n]) =
                        make_float2(acc[t][0], acc[t][1]);
                    *reinterpret_cast<float2*>(&gh[(row + 8)*3*DOUT + n]) =
                        make_float2(acc[t][2], acc[t][3]);
                }
            }
        }
        __syncthreads();

        // elementwise
        for (int idx = tid; idx < GRB*DOUT; idx += GRU_T) {
            int r = idx / DOUT, d = idx - r*DOUT;
            int b = b0 + r;
            if (b < NB) {
                int vi = r + s;
                float giR = xp[vi*3*DOUT + d];
                float giZ = xp[vi*3*DOUT + DOUT + d];
                float giN = xp[vi*3*DOUT + 2*DOUT + d];
                float xv  = xvs[vi*DOUT + d];
                float hr = gh[r*3*DOUT + d]          + bhs[d];
                float hz = gh[r*3*DOUT + DOUT + d]   + bhs[DOUT + d];
                float hn = gh[r*3*DOUT + 2*DOUT + d] + bhs[2*DOUT + d];
                float rr = 1.f / (1.f + expf(-(giR + hr)));
                float zz = 1.f / (1.f + expf(-(giZ + hz)));
                float nn = tanhf(giN + rr*hn);
                float hnew = (1.f - zz)*nn + zz*hs[r*DOUT + d];
                hs[r*DOUT + d] = hnew;
                g_memb[(b*WIND + s)*DOUT + d] = xv + hnew;
            }
        }
        __syncthreads();
    }
}

// ---------------- 3-hop attention: warp per window, register M --------------
__global__ void __launch_bounds__(256) attn_kernel(float* __restrict__ attn_out) {
    const int w = blockIdx.x * 8 + (threadIdx.x >> 5);
    const int lane = threadIdx.x & 31;
    if (w >= NB) return;

    float M[WIND][4], q[4];
    #pragma unroll
    for (int jj = 0; jj < 4; jj++) {
        int d = lane + 32*jj;
        bool ok = d < DOUT;
        q[jj] = ok ? g_sutt[(w + 1)*DOUT + d] : 0.f;
        #pragma unroll
        for (int k = 0; k < WIND; k++)
            M[k][jj] = ok ? g_memb[(w*WIND + k)*DOUT + d] : 0.f;
    }

    #pragma unroll
    for (int hop = 0; hop < HOPS; hop++) {
        float l[WIND];
        #pragma unroll
        for (int k = 0; k < WIND; k++) {
            float p = q[0]*M[k][0] + q[1]*M[k][1] + q[2]*M[k][2] + q[3]*M[k][3];
            #pragma unroll
            for (int off = 16; off; off >>= 1)
                p += __shfl_xor_sync(0xFFFFFFFFu, p, off);
            l[k] = (w + k - (WIND - 1) >= 0) ? p : -1e10f;
        }
        float mx = l[0];
        #pragma unroll
        for (int k = 1; k < WIND; k++) mx = fmaxf(mx, l[k]);
        float a[WIND], sum = 0.f;
        #pragma unroll
        for (int k = 0; k < WIND; k++) { a[k] = expf(l[k] - mx); sum += a[k]; }
        float inv = 1.f / sum;
        #pragma unroll
        for (int k = 0; k < WIND; k++) {
            a[k] *= inv;
            if (lane == k) attn_out[hop*(NB*WIND) + w*WIND + k] = a[k];
        }
        #pragma unroll
        for (int jj = 0; jj < 4; jj++) {
            float acc = 0.f;
            #pragma unroll
            for (int k = 0; k < WIND; k++) acc += a[k] * M[k][jj];
            q[jj] += acc;
        }
    }
    #pragma unroll
    for (int jj = 0; jj < 4; jj++) {
        int d = lane + 32*jj;
        if (d < DOUT) g_q[w*DOUT + d] = q[jj];
    }
}

// ---------------- classifier + log_softmax ----------------
__global__ void cls_kernel(const float* __restrict__ cw,
                           const float* __restrict__ cb,
                           float* __restrict__ pred_out) {
    int row = blockIdx.x * blockDim.x + threadIdx.x;
    if (row >= NU) return;
    const float* s = (row == 0) ? g_sutt : (g_q + (row - 1)*DOUT);
    float lg[NC];
    #pragma unroll
    for (int c = 0; c < NC; c++) {
        float acc = cb[c];
        const float* wr = cw + c*DOUT;
        #pragma unroll 4
        for (int k = 0; k < DOUT; k++) acc += s[k] * wr[k];
        lg[c] = acc;
    }
    float mx = lg[0];
    #pragma unroll
    for (int c = 1; c < NC; c++) mx = fmaxf(mx, lg[c]);
    float sum = 0.f;
    #pragma unroll
    for (int c = 0; c < NC; c++) sum += expf(lg[c] - mx);
    float lse = mx + logf(sum);
    #pragma unroll
    for (int c = 0; c < NC; c++) pred_out[row*NC + c] = lg[c] - lse;
}

// ---------------- launch sequence ----------------
extern "C" void kernel_launch(void* const* d_in, const int* in_sizes, int n_in,
                              void* d_out, int out_size) {
    const int*   sents   = (const int*)  d_in[0];
    const float* emb     = (const float*)d_in[2];
    const float* trans_w = (const float*)d_in[3];
    const float* trans_b = (const float*)d_in[4];
    const float* gru_wih = (const float*)d_in[5];
    const float* gru_whh = (const float*)d_in[6];
    const float* gru_bih = (const float*)d_in[7];
    const float* gru_bhh = (const float*)d_in[8];
    const float* cls_w   = (const float*)d_in[9];
    const float* cls_b   = (const float*)d_in[10];
    const float* conv_w3 = (const float*)d_in[11];
    const float* conv_b3 = (const float*)d_in[12];
    const float* conv_w4 = (const float*)d_in[13];
    const float* conv_b4 = (const float*)d_in[14];
    const float* conv_w5 = (const float*)d_in[15];
    const float* conv_b5 = (const float*)d_in[16];

    float* outF = (float*)d_out;
    float* pred_out = outF;
    float* attn_out;
    if (out_size >= NU*NC + HOPS*NB*WIND) attn_out = outF + NU*NC;
    else cudaGetSymbolAddress((void**)&attn_out, g_attn_scratch);

    cudaFuncSetAttribute(packall,         cudaFuncAttributeMaxDynamicSharedMemorySize, PACKA_SMEM);
    cudaFuncSetAttribute(conv_gemm_mma,   cudaFuncAttributeMaxDynamicSharedMemorySize, GEMM_SMEM);
    cudaFuncSetAttribute(poolsutt_kernel, cudaFuncAttributeMaxDynamicSharedMemorySize, POOL_SMEM);
    cudaFuncSetAttribute(gru_fused,       cudaFuncAttributeMaxDynamicSharedMemorySize, GRU_SMEM);

    packall<<<PA_BLOCKS + PB_BLOCKS + TW_BLOCKS + WF_BLOCKS, 256, PACKA_SMEM>>>(
        emb, conv_w3, conv_w4, conv_w5, trans_w, gru_whh);

    dim3 ggrid(NCOL/128, VPAD/128);   // (6, 391)
    conv_gemm_mma<<<ggrid, 256, GEMM_SMEM>>>();

    poolsutt_kernel<<<NU, POOL_T, POOL_SMEM>>>(sents, conv_b3, conv_b4, conv_b5, trans_b);
    gru_fused<<<(NB + GRB - 1)/GRB, GRU_T, GRU_SMEM>>>(gru_wih, gru_bih, gru_bhh);

    attn_kernel<<<(NB + 7)/8, 256>>>(attn_out);
    cls_kernel<<<(NU + 255)/256, 256>>>(cls_w, cls_b, pred_out);
}

// round 16
// speedup vs baseline: 1.3242x; 1.0294x over previous
#include <cuda_runtime.h>
#include <cuda_fp16.h>
#include <math.h>
#include <stdint.h>

// ---------------- problem constants ----------------
#define NU    2048
#define SL    50
#define DE    300
#define KPAD  320      // 20 k-groups of 16
#define DOUT  100
#define NC    7
#define WIND  10
#define HOPS  3
#define NB    2047
#define VOCAB 50000
#define VPAD  50048    // 391 * 128
#define NCOL  768
#define FCAT  192

// ---------------- static scratch ----------------
__device__ __half g_Ah[(size_t)VPAD*KPAD];      // A fp16 fragment order (128-row mblk)
__device__ __half g_Bh[NCOL*KPAD];              // B fp16 nt-pair fragment order (128-col nblk)
__device__ __half g_Zh[(size_t)VPAD*NCOL];      // fp16 projections (77 MB)
__device__ float g_twT[FCAT*DOUT];
__device__ float g_sutt[NU*DOUT];
__device__ float g_memb[NB*WIND*DOUT];
__device__ float g_q[NB*DOUT];
__device__ float g_attn_scratch[HOPS*NB*WIND];
__device__ uint2 g_WhhF[8*5*7*32];               // whh fp16 B-fragments [w][t][c][lane]

// ---------------- helpers ----------------
__device__ __forceinline__ uint32_t smem_u32(const void* p) {
    uint32_t a;
    asm("{ .reg .u64 t; cvta.to.shared.u64 t, %1; cvt.u32.u64 %0, t; }" : "=r"(a) : "l"(p));
    return a;
}
#define CP_ASYNC16(sa, gp) asm volatile("cp.async.cg.shared.global [%0], [%1], 16;" :: "r"(sa), "l"(gp) : "memory")
#define CP_COMMIT()        asm volatile("cp.async.commit_group;" ::: "memory")
#define CP_WAIT(n)         asm volatile("cp.async.wait_group %0;" :: "n"(n) : "memory")

__device__ __forceinline__ void mma_fp16(float* d, const uint32_t* a, const uint32_t* b) {
    asm volatile("mma.sync.aligned.m16n8k16.row.col.f32.f16.f16.f32 "
        "{%0,%1,%2,%3}, {%4,%5,%6,%7}, {%8,%9}, {%0,%1,%2,%3};"
        : "+f"(d[0]), "+f"(d[1]), "+f"(d[2]), "+f"(d[3])
        : "r"(a[0]), "r"(a[1]), "r"(a[2]), "r"(a[3]), "r"(b[0]), "r"(b[1]));
}
__device__ __forceinline__ float tanh_fast(float x) {
    float r; asm("tanh.approx.f32 %0, %1;" : "=f"(r) : "f"(x)); return r;
}
__device__ __forceinline__ float sigmoid_fast(float x) {
    return fmaf(tanh_fast(0.5f * x), 0.5f, 0.5f);
}

// ---------------- merged pack: A-transpose + B + twT + WhhF ----------------
#define PA_LDK 328
#define PACKA_SMEM (128*PA_LDK*2)
#define PA_BLOCKS (VPAD/128)   // 391
#define PB_BLOCKS 120          // 30720 d4 / 256
#define TW_BLOCKS 75           // 19200 / 256
#define WF_BLOCKS 35           // 8960 uint2 / 256

__device__ __forceinline__ __half wall_h(const float* w3, const float* w4,
                                         const float* w5, int c, int k) {
    if (k >= DE) return __float2half_rn(0.f);
    float v;
    if (c < 192)      { int cc = c;       int dt = cc >> 6, o = cc & 63; v = w3[(o*3 + dt)*DE + k]; }
    else if (c < 448) { int cc = c - 192; int dt = cc >> 6, o = cc & 63; v = w4[(o*4 + dt)*DE + k]; }
    else              { int cc = c - 448; int dt = cc >> 6, o = cc & 63; v = w5[(o*5 + dt)*DE + k]; }
    return __float2half_rn(v);
}
__device__ __forceinline__ __half whh_h(const float* whh, int n, int k) {
    if (n >= 3*DOUT || k >= DOUT) return __float2half_rn(0.f);
    return __float2half_rn(whh[n*DOUT + k]);
}

__global__ void __launch_bounds__(256) packall(
        const float* __restrict__ emb,
        const float* __restrict__ w3, const float* __restrict__ w4,
        const float* __restrict__ w5, const float* __restrict__ tw,
        const float* __restrict__ whh) {
    const int tid = threadIdx.x;
    if (blockIdx.x < PA_BLOCKS) {
        extern __shared__ __half sa[];
        const int mblk = blockIdx.x;
        {
            uint4* s4 = reinterpret_cast<uint4*>(sa);
            for (int i = tid; i < 128*PA_LDK/8; i += 256)
                s4[i] = make_uint4(0, 0, 0, 0);
        }
        __syncthreads();
        {
            const float4* e4 = reinterpret_cast<const float4*>(emb);
            for (int i = tid; i < 128*75; i += 256) {
                int row = i / 75, c4 = i - row*75;
                int m = mblk*128 + row;
                if (m < VOCAB) {
                    float4 v = e4[(size_t)m*75 + c4];
                    __half2 lo = __floats2half2_rn(v.x, v.y);
                    __half2 hi = __floats2half2_rn(v.z, v.w);
                    uint2 pk = make_uint2(*(uint32_t*)&lo, *(uint32_t*)&hi);
                    *reinterpret_cast<uint2*>(sa + row*PA_LDK + c4*4) = pk;
                }
            }
        }
        __syncthreads();
        {
            const int lane = tid & 31;
            const int r16  = tid >> 5;
            const int mloc = r16*16 + (lane >> 2);
            const int kk   = (lane & 3)*2;
            const uint32_t* s32 = reinterpret_cast<const uint32_t*>(sa);
            uint4* out4 = reinterpret_cast<uint4*>(g_Ah);
            #pragma unroll 4
            for (int kc16 = 0; kc16 < 20; kc16++) {
                int k = kc16*16 + kk;
                uint32_t h0 = s32[( mloc      *PA_LDK + k    ) >> 1];
                uint32_t h1 = s32[((mloc + 8)*PA_LDK + k    ) >> 1];
                uint32_t h2 = s32[( mloc      *PA_LDK + k + 8) >> 1];
                uint32_t h3 = s32[((mloc + 8)*PA_LDK + k + 8) >> 1];
                out4[((size_t)(mblk*20 + kc16)*8 + r16)*32 + lane] = make_uint4(h0, h1, h2, h3);
            }
        }
    } else if (blockIdx.x < PA_BLOCKS + PB_BLOCKS) {
        int d4 = (blockIdx.x - PA_BLOCKS) * 256 + tid;
        int lane = d4 & 31;
        int np   = (d4 >> 5) & 7;
        int rest = d4 >> 8;
        int kc16 = rest % 20;
        int nblk = rest / 20;
        int na = nblk*128 + np*16 + (lane >> 2);
        int nb = na + 8;
        int k = kc16*16 + (lane & 3)*2;
        __half2 h0 = __halves2half2(wall_h(w3,w4,w5, na, k),     wall_h(w3,w4,w5, na, k + 1));
        __half2 h1 = __halves2half2(wall_h(w3,w4,w5, na, k + 8), wall_h(w3,w4,w5, na, k + 9));
        __half2 h2 = __halves2half2(wall_h(w3,w4,w5, nb, k),     wall_h(w3,w4,w5, nb, k + 1));
        __half2 h3 = __halves2half2(wall_h(w3,w4,w5, nb, k + 8), wall_h(w3,w4,w5, nb, k + 9));
        uint4 v = make_uint4(*(uint32_t*)&h0, *(uint32_t*)&h1, *(uint32_t*)&h2, *(uint32_t*)&h3);
        reinterpret_cast<uint4*>(g_Bh)[d4] = v;
    } else if (blockIdx.x < PA_BLOCKS + PB_BLOCKS + TW_BLOCKS) {
        int idx = (blockIdx.x - PA_BLOCKS - PB_BLOCKS) * 256 + tid;
        if (idx < FCAT*DOUT) {
            int j = idx / DOUT, d = idx % DOUT;
            g_twT[idx] = tw[d*FCAT + j];
        }
    } else {
        int idx = (blockIdx.x - PA_BLOCKS - PB_BLOCKS - TW_BLOCKS) * 256 + tid;
        if (idx < 8*5*7*32) {
            int lane = idx & 31;
            int c = (idx >> 5) % 7;
            int rest = (idx >> 5) / 7;
            int t = rest % 5;
            int w = rest / 5;
            int n = w*40 + t*8 + (lane >> 2);
            int k = c*16 + (lane & 3)*2;
            __half2 b0 = __halves2half2(whh_h(whh, n, k),     whh_h(whh, n, k + 1));
            __half2 b1 = __halves2half2(whh_h(whh, n, k + 8), whh_h(whh, n, k + 9));
            g_WhhF[idx] = make_uint2(*(uint32_t*)&b0, *(uint32_t*)&b1);
        }
    }
}

// ---------------- fp16 mma GEMM: Z = Ah @ Bh^T (fp16 out) ----------------
#define GEMM_SMEM 49152

__global__ void __launch_bounds__(256, 2) conv_gemm_mma() {
    extern __shared__ char smc[];
    const int tid  = threadIdx.x;
    const int lane = tid & 31, wid = tid >> 5;
    const int warp_m = wid & 3;
    const int warp_n = wid >> 2;
    const int by = blockIdx.y, bx = blockIdx.x;
    const int m0 = by * 128, n0 = bx * 128;

    const uint32_t smb = smem_u32(smc);
    const uint4* Ah4 = reinterpret_cast<const uint4*>(g_Ah);
    const uint4* Bh4 = reinterpret_cast<const uint4*>(g_Bh);

    float acc[2][8][4];
    #pragma unroll
    for (int mt = 0; mt < 2; mt++)
        #pragma unroll
        for (int nt = 0; nt < 8; nt++)
            #pragma unroll
            for (int i = 0; i < 4; i++) acc[mt][nt][i] = 0.f;

    #pragma unroll
    for (int c = 0; c < 2; c++) {
        size_t aG = ((size_t)by*20 + c*2) * 256;
        size_t bG = ((size_t)bx*20 + c*2) * 256;
        #pragma unroll
        for (int i = 0; i < 2; i++) {
            CP_ASYNC16(smb +         c*8192 + (tid + i*256)*16, Ah4 + aG + tid + i*256);
            CP_ASYNC16(smb + 24576 + c*8192 + (tid + i*256)*16, Bh4 + bG + tid + i*256);
        }
        CP_COMMIT();
    }

    for (int c = 0; c < 10; c++) {
        const int buf = c % 3;
        if (c < 9) CP_WAIT(1); else CP_WAIT(0);
        __syncthreads();
        if (c + 2 < 10) {
            const int nb = (c + 2) % 3;
            size_t aG = ((size_t)by*20 + (c + 2)*2) * 256;
            size_t bG = ((size_t)bx*20 + (c + 2)*2) * 256;
            #pragma unroll
            for (int i = 0; i < 2; i++) {
                CP_ASYNC16(smb +         nb*8192 + (tid + i*256)*16, Ah4 + aG + tid + i*256);
                CP_ASYNC16(smb + 24576 + nb*8192 + (tid + i*256)*16, Bh4 + bG + tid + i*256);
            }
            CP_COMMIT();
        }

        const uint4* A4 = reinterpret_cast<const uint4*>(smc + buf*8192);
        const uint4* B4 = reinterpret_cast<const uint4*>(smc + 24576 + buf*8192);
        #pragma unroll
        for (int ks = 0; ks < 2; ks++) {
            uint32_t a[2][4], b[8][2];
            #pragma unroll
            for (int mt = 0; mt < 2; mt++) {
                uint4 v = A4[(ks*8 + warp_m*2 + mt)*32 + lane];
                a[mt][0] = v.x; a[mt][1] = v.y; a[mt][2] = v.z; a[mt][3] = v.w;
            }
            #pragma unroll
            for (int np = 0; np < 4; np++) {
                uint4 u = B4[(ks*8 + warp_n*4 + np)*32 + lane];
                b[2*np  ][0] = u.x; b[2*np  ][1] = u.y;
                b[2*np+1][0] = u.z; b[2*np+1][1] = u.w;
            }
            #pragma unroll
            for (int mt = 0; mt < 2; mt++)
                #pragma unroll
                for (int nt = 0; nt < 8; nt++)
                    mma_fp16(acc[mt][nt], a[mt], b[nt]);
        }
    }

    __half2* Z2 = reinterpret_cast<__half2*>(g_Zh);
    #pragma unroll
    for (int mt = 0; mt < 2; mt++) {
        int r = m0 + warp_m*32 + mt*16 + (lane >> 2);
        #pragma unroll
        for (int nt = 0; nt < 8; nt++) {
            int cc = n0 + warp_n*64 + nt*8 + (lane & 3)*2;
            Z2[((size_t) r      *NCOL + cc) >> 1] = __floats2half2_rn(acc[mt][nt][0], acc[mt][nt][1]);
            Z2[((size_t)(r + 8)*NCOL + cc) >> 1] = __floats2half2_rn(acc[mt][nt][2], acc[mt][nt][3]);
        }
    }
}

// ---------------- fused pool + relu + tanh projection -----------------------
#define POOL_T 768
#define POOL_SMEM (76800 + 200 + 6144 + 768)
__global__ void __launch_bounds__(POOL_T) poolsutt_kernel(
        const int* __restrict__ sents,
        const float* __restrict__ b3, const float* __restrict__ b4,
        const float* __restrict__ b5, const float* __restrict__ tb) {
    extern __shared__ char psm[];
    __half*  Zs    = reinterpret_cast<__half*>(psm);
    int*     toks  = reinterpret_cast<int*>(psm + 76800);
    float2*  pmax2 = reinterpret_cast<float2*>(psm + 77000);
    float*   fsh   = reinterpret_cast<float*>(psm + 83144);
    const int n = blockIdx.x;
    const int tid = threadIdx.x;
    const uint32_t zsb = smem_u32(Zs);

    if (tid < SL) toks[tid] = sents[n*SL + tid];
    __syncthreads();
    {
        const uint4* Zg4 = reinterpret_cast<const uint4*>(g_Zh);
        for (int i = tid; i < SL*96; i += POOL_T) {
            int row = i / 96, c4 = i - row*96;
            CP_ASYNC16(zsb + i*16, Zg4 + (size_t)toks[row]*96 + c4);
        }
        CP_COMMIT();
        CP_WAIT(0);
    }
    __syncthreads();
    {
        const int q  = tid / 96;
        const int p  = tid - q*96;
        const int fi = p >> 5, o2 = p & 31;
        const int fs  = 3 + fi;
        const int offh = ((fi == 0) ? 0 : (fi == 1) ? 192 : 448) / 2;
        const int T = SL - fs + 1;
        const int t0 = (T * q) >> 3;
        const int t1 = (T * (q + 1)) >> 3;
        const __half2* Zs2 = reinterpret_cast<const __half2*>(Zs);
        float mx0 = -1e30f, mx1 = -1e30f;
        for (int t = t0; t < t1; t++) {
            float v0 = 0.f, v1 = 0.f;
            #pragma unroll 5
            for (int dt = 0; dt < fs; dt++) {
                __half2 h = Zs2[(t + dt)*384 + offh + dt*32 + o2];
                float2 f = __half22float2(h);
                v0 += f.x; v1 += f.y;
            }
            mx0 = fmaxf(mx0, v0); mx1 = fmaxf(mx1, v1);
        }
        pmax2[q*96 + p] = make_float2(mx0, mx1);
    }
    __syncthreads();
    if (tid < 96) {
        const int fi = tid >> 5, o2 = tid & 31;
        const int fa = fi*64 + 2*o2;
        float m0 = -1e30f, m1 = -1e30f;
        #pragma unroll
        for (int q = 0; q < 8; q++) {
            float2 v = pmax2[q*96 + tid];
            m0 = fmaxf(m0, v.x); m1 = fmaxf(m1, v.y);
        }
        float ba = (fi == 0) ? b3[2*o2]     : (fi == 1) ? b4[2*o2]     : b5[2*o2];
        float bb = (fi == 0) ? b3[2*o2 + 1] : (fi == 1) ? b4[2*o2 + 1] : b5[2*o2 + 1];
        fsh[fa]     = fmaxf(0.f, m0 + ba);
        fsh[fa + 1] = fmaxf(0.f, m1 + bb);
    }
    __syncthreads();
    if (tid < DOUT) {
        float acc = tb[tid];
        #pragma unroll 8
        for (int j = 0; j < FCAT; j++) acc += fsh[j] * g_twT[j*DOUT + tid];
        g_sutt[n*DOUT + tid] = tanhf(acc);
    }
}

// ---------------- fused GRU v6: HMMA + fast gates + fused convert ------------
// 256 thr = 8 warps, GRB=16 rows. Per step: mma (reads h16) -> sync ->
// elementwise (d-pairs; writes hs, h16 for next step, g_memb) -> sync.
#define GRB 16
#define GRU_T 256
#define NXV (GRB + WIND - 1)   // 25
// smem: floats xp[7500] xvs[2500] hs[1600] gh[4800] bhs[300] = 16700 f -> 66800 B
//       h16 tile 16*120 halves -> 3840 B at offset 66800
#define GRU_SMEM (66800 + 3840)
__global__ void __launch_bounds__(GRU_T, 1) gru_fused(
        const float* __restrict__ wih, const float* __restrict__ bih,
        const float* __restrict__ bhh) {
    extern __shared__ char smraw[];
    float* xp  = reinterpret_cast<float*>(smraw);            // [25][300]
    float* xvs = xp + NXV*3*DOUT;                            // [25][100]
    float* hs  = xvs + NXV*DOUT;                             // [16][100]
    float* gh  = hs + GRB*DOUT;                              // [16][300]
    float* bhs = gh + GRB*3*DOUT;                            // [300]
    uint32_t* h16 = reinterpret_cast<uint32_t*>(smraw + 66800); // [16][60] u32
    const int tid = threadIdx.x;
    const int lane = tid & 31, wid = tid >> 5;
    const int b0 = blockIdx.x * GRB;

    // B fragments resident in registers for all steps
    uint2 Bf[5][7];
    #pragma unroll
    for (int t = 0; t < 5; t++)
        #pragma unroll
        for (int c = 0; c < 7; c++)
            Bf[t][c] = g_WhhF[((wid*5 + t)*7 + c)*32 + lane];

    // stage s_utt slice + init
    for (int i = tid; i < NXV*DOUT; i += GRU_T) {
        int vi = i / DOUT, d = i - vi*DOUT;
        int v = b0 - (WIND - 1) + vi;
        xvs[i] = (v >= 0 && v < NB) ? g_sutt[v*DOUT + d] : 0.f;
    }
    for (int i = tid; i < GRB*DOUT; i += GRU_T) hs[i] = 0.f;
    for (int i = tid; i < 3*DOUT; i += GRU_T) bhs[i] = bhh[i];
    for (int i = tid; i < 16*60; i += GRU_T) h16[i] = 0;   // h_0 = 0, K-pad = 0
    __syncthreads();

    // local xproj: xp[vi][j] = xvs[vi] . wih[j] + bih[j]
    for (int i = tid; i < NXV*3*DOUT; i += GRU_T) {
        int vi = i / (3*DOUT), j = i - vi*3*DOUT;
        const float4* wI = reinterpret_cast<const float4*>(wih + j*DOUT);
        const float4* xv = reinterpret_cast<const float4*>(xvs + vi*DOUT);
        float acc = 0.f;
        #pragma unroll
        for (int k = 0; k < DOUT/4; k++) {
            float4 w = wI[k], x = xv[k];
            acc += w.x*x.x + w.y*x.y + w.z*x.z + w.w*x.w;
        }
        xp[i] = acc + bih[j];
    }
    __syncthreads();

    for (int s = 0; s < WIND; s++) {
        // HMMA: gh = h @ whh^T  (reads h16 state of step s)
        {
            float acc[5][4];
            #pragma unroll
            for (int t = 0; t < 5; t++)
                #pragma unroll
                for (int i = 0; i < 4; i++) acc[t][i] = 0.f;
            const int row = lane >> 2, q = lane & 3;
            #pragma unroll
            for (int c = 0; c < 7; c++) {
                uint32_t a[4];
                a[0] = h16[ row      *60 + c*8 + q];
                a[1] = h16[(row + 8)*60 + c*8 + q];
                a[2] = h16[ row      *60 + c*8 + q + 4];
                a[3] = h16[(row + 8)*60 + c*8 + q + 4];
                #pragma unroll
                for (int t = 0; t < 5; t++)
                    mma_fp16(acc[t], a, (const uint32_t*)&Bf[t][c]);
            }
            #pragma unroll
            for (int t = 0; t < 5; t++) {
                int n = wid*40 + t*8 + q*2;
                if (n < 3*DOUT) {
                    *reinterpret_cast<float2*>(&gh[ row      *3*DOUT + n]) =
                        make_float2(acc[t][0], acc[t][1]);
                    *reinterpret_cast<float2*>(&gh[(row + 8)*3*DOUT + n]) =
                        make_float2(acc[t][2], acc[t][3]);
                }
            }
        }
        __syncthreads();

        // elementwise (d-pairs): gates via tanh.approx; writes hs, h16, g_memb
        for (int i = tid; i < GRB*50; i += GRU_T) {
            int r = i / 50, kp = i - r*50;
            int b = b0 + r;
            if (b < NB) {
                int d0 = kp*2;
                int vi = r + s;
                const float* xpr = xp + vi*3*DOUT;
                float hnew[2];
                #pragma unroll
                for (int u = 0; u < 2; u++) {
                    int d = d0 + u;
                    float giR = xpr[d];
                    float giZ = xpr[DOUT + d];
                    float giN = xpr[2*DOUT + d];
                    float hr = gh[r*3*DOUT + d]          + bhs[d];
                    float hz = gh[r*3*DOUT + DOUT + d]   + bhs[DOUT + d];
                    float hn = gh[r*3*DOUT + 2*DOUT + d] + bhs[2*DOUT + d];
                    float rr = sigmoid_fast(giR + hr);
                    float zz = sigmoid_fast(giZ + hz);
                    float nn = tanh_fast(giN + rr*hn);
                    float hprev = hs[r*DOUT + d];
                    hnew[u] = (1.f - zz)*nn + zz*hprev;
                    hs[r*DOUT + d] = hnew[u];
                }
                __half2 hp = __floats2half2_rn(hnew[0], hnew[1]);
                h16[r*60 + kp] = *(uint32_t*)&hp;
                float xv0 = xvs[vi*DOUT + d0], xv1 = xvs[vi*DOUT + d0 + 1];
                *reinterpret_cast<float2*>(
                    &g_memb[(size_t)(b*WIND + s)*DOUT + d0]) =
                    make_float2(xv0 + hnew[0], xv1 + hnew[1]);
            }
        }
        __syncthreads();
    }
}

// ---------------- 3-hop attention: warp per window, register M --------------
__global__ void __launch_bounds__(256) attn_kernel(float* __restrict__ attn_out) {
    const int w = blockIdx.x * 8 + (threadIdx.x >> 5);
    const int lane = threadIdx.x & 31;
    if (w >= NB) return;

    float M[WIND][4], q[4];
    #pragma unroll
    for (int jj = 0; jj < 4; jj++) {
        int d = lane + 32*jj;
        bool ok = d < DOUT;
        q[jj] = ok ? g_sutt[(w + 1)*DOUT + d] : 0.f;
        #pragma unroll
        for (int k = 0; k < WIND; k++)
            M[k][jj] = ok ? g_memb[(w*WIND + k)*DOUT + d] : 0.f;
    }

    #pragma unroll
    for (int hop = 0; hop < HOPS; hop++) {
        float l[WIND];
        #pragma unroll
        for (int k = 0; k < WIND; k++) {
            float p = q[0]*M[k][0] + q[1]*M[k][1] + q[2]*M[k][2] + q[3]*M[k][3];
            #pragma unroll
            for (int off = 16; off; off >>= 1)
                p += __shfl_xor_sync(0xFFFFFFFFu, p, off);
            l[k] = (w + k - (WIND - 1) >= 0) ? p : -1e10f;
        }
        float mx = l[0];
        #pragma unroll
        for (int k = 1; k < WIND; k++) mx = fmaxf(mx, l[k]);
        float a[WIND], sum = 0.f;
        #pragma unroll
        for (int k = 0; k < WIND; k++) { a[k] = expf(l[k] - mx); sum += a[k]; }
        float inv = 1.f / sum;
        #pragma unroll
        for (int k = 0; k < WIND; k++) {
            a[k] *= inv;
            if (lane == k) attn_out[hop*(NB*WIND) + w*WIND + k] = a[k];
        }
        #pragma unroll
        for (int jj = 0; jj < 4; jj++) {
            float acc = 0.f;
            #pragma unroll
            for (int k = 0; k < WIND; k++) acc += a[k] * M[k][jj];
            q[jj] += acc;
        }
    }
    #pragma unroll
    for (int jj = 0; jj < 4; jj++) {
        int d = lane + 32*jj;
        if (d < DOUT) g_q[w*DOUT + d] = q[jj];
    }
}

// ---------------- classifier + log_softmax ----------------
__global__ void cls_kernel(const float* __restrict__ cw,
                           const float* __restrict__ cb,
                           float* __restrict__ pred_out) {
    int row = blockIdx.x * blockDim.x + threadIdx.x;
    if (row >= NU) return;
    const float* s = (row == 0) ? g_sutt : (g_q + (row - 1)*DOUT);
    float lg[NC];
    #pragma unroll
    for (int c = 0; c < NC; c++) {
        float acc = cb[c];
        const float* wr = cw + c*DOUT;
        #pragma unroll 4
        for (int k = 0; k < DOUT; k++) acc += s[k] * wr[k];
        lg[c] = acc;
    }
    float mx = lg[0];
    #pragma unroll
    for (int c = 1; c < NC; c++) mx = fmaxf(mx, lg[c]);
    float sum = 0.f;
    #pragma unroll
    for (int c = 0; c < NC; c++) sum += expf(lg[c] - mx);
    float lse = mx + logf(sum);
    #pragma unroll
    for (int c = 0; c < NC; c++) pred_out[row*NC + c] = lg[c] - lse;
}

// ---------------- launch sequence ----------------
extern "C" void kernel_launch(void* const* d_in, const int* in_sizes, int n_in,
                              void* d_out, int out_size) {
    const int*   sents   = (const int*)  d_in[0];
    const float* emb     = (const float*)d_in[2];
    const float* trans_w = (const float*)d_in[3];
    const float* trans_b = (const float*)d_in[4];
    const float* gru_wih = (const float*)d_in[5];
    const float* gru_whh = (const float*)d_in[6];
    const float* gru_bih = (const float*)d_in[7];
    const float* gru_bhh = (const float*)d_in[8];
    const float* cls_w   = (const float*)d_in[9];
    const float* cls_b   = (const float*)d_in[10];
    const float* conv_w3 = (const float*)d_in[11];
    const float* conv_b3 = (const float*)d_in[12];
    const float* conv_w4 = (const float*)d_in[13];
    const float* conv_b4 = (const float*)d_in[14];
    const float* conv_w5 = (const float*)d_in[15];
    const float* conv_b5 = (const float*)d_in[16];

    float* outF = (float*)d_out;
    float* pred_out = outF;
    float* attn_out;
    if (out_size >= NU*NC + HOPS*NB*WIND) attn_out = outF + NU*NC;
    else cudaGetSymbolAddress((void**)&attn_out, g_attn_scratch);

    cudaFuncSetAttribute(packall,         cudaFuncAttributeMaxDynamicSharedMemorySize, PACKA_SMEM);
    cudaFuncSetAttribute(conv_gemm_mma,   cudaFuncAttributeMaxDynamicSharedMemorySize, GEMM_SMEM);
    cudaFuncSetAttribute(poolsutt_kernel, cudaFuncAttributeMaxDynamicSharedMemorySize, POOL_SMEM);
    cudaFuncSetAttribute(gru_fused,       cudaFuncAttributeMaxDynamicSharedMemorySize, GRU_SMEM);

    packall<<<PA_BLOCKS + PB_BLOCKS + TW_BLOCKS + WF_BLOCKS, 256, PACKA_SMEM>>>(
        emb, conv_w3, conv_w4, conv_w5, trans_w, gru_whh);

    dim3 ggrid(NCOL/128, VPAD/128);   // (6, 391)
    conv_gemm_mma<<<ggrid, 256, GEMM_SMEM>>>();

    poolsutt_kernel<<<NU, POOL_T, POOL_SMEM>>>(sents, conv_b3, conv_b4, conv_b5, trans_b);
    gru_fused<<<(NB + GRB - 1)/GRB, GRU_T, GRU_SMEM>>>(gru_wih, gru_bih, gru_bhh);

    attn_kernel<<<(NB + 7)/8, 256>>>(attn_out);
    cls_kernel<<<(NU + 255)/256, 256>>>(cls_w, cls_b, pred_out);
}

// round 17
// speedup vs baseline: 1.4574x; 1.1006x over previous
#include <cuda_runtime.h>
#include <cuda_fp16.h>
#include <math.h>
#include <stdint.h>

// ---------------- problem constants ----------------
#define NU    2048
#define SL    50
#define DE    300
#define KPAD  320
#define DOUT  100
#define NC    7
#define WIND  10
#define HOPS  3
#define NB    2047
#define VOCAB 50000
#define VPAD  50048    // 391 * 128
#define NCOL  768
#define FCAT  192

// ---------------- static scratch ----------------
__device__ __half g_Ah[(size_t)VPAD*KPAD];
__device__ __half g_Bh[NCOL*KPAD];
__device__ __half g_Zh[(size_t)VPAD*NCOL];
__device__ float g_twT[FCAT*DOUT];
__device__ float g_sutt[NU*DOUT];
__device__ float g_attn_scratch[HOPS*NB*WIND];
__device__ uint2 g_WhhF[8*5*7*32];

// ---------------- helpers ----------------
__device__ __forceinline__ uint32_t smem_u32(const void* p) {
    uint32_t a;
    asm("{ .reg .u64 t; cvta.to.shared.u64 t, %1; cvt.u32.u64 %0, t; }" : "=r"(a) : "l"(p));
    return a;
}
#define CP_ASYNC16(sa, gp) asm volatile("cp.async.cg.shared.global [%0], [%1], 16;" :: "r"(sa), "l"(gp) : "memory")
#define CP_COMMIT()        asm volatile("cp.async.commit_group;" ::: "memory")
#define CP_WAIT(n)         asm volatile("cp.async.wait_group %0;" :: "n"(n) : "memory")

__device__ __forceinline__ void mma_fp16(float* d, const uint32_t* a, const uint32_t* b) {
    asm volatile("mma.sync.aligned.m16n8k16.row.col.f32.f16.f16.f32 "
        "{%0,%1,%2,%3}, {%4,%5,%6,%7}, {%8,%9}, {%0,%1,%2,%3};"
        : "+f"(d[0]), "+f"(d[1]), "+f"(d[2]), "+f"(d[3])
        : "r"(a[0]), "r"(a[1]), "r"(a[2]), "r"(a[3]), "r"(b[0]), "r"(b[1]));
}
__device__ __forceinline__ float tanh_fast(float x) {
    float r; asm("tanh.approx.f32 %0, %1;" : "=f"(r) : "f"(x)); return r;
}
__device__ __forceinline__ float sigmoid_fast(float x) {
    return fmaf(tanh_fast(0.5f * x), 0.5f, 0.5f);
}

// ---------------- merged pack: A-transpose + B + twT + WhhF ----------------
#define PA_LDK 328
#define PACKA_SMEM (128*PA_LDK*2)
#define PA_BLOCKS (VPAD/128)   // 391
#define PB_BLOCKS 120
#define TW_BLOCKS 75
#define WF_BLOCKS 35

__device__ __forceinline__ __half wall_h(const float* w3, const float* w4,
                                         const float* w5, int c, int k) {
    if (k >= DE) return __float2half_rn(0.f);
    float v;
    if (c < 192)      { int cc = c;       int dt = cc >> 6, o = cc & 63; v = w3[(o*3 + dt)*DE + k]; }
    else if (c < 448) { int cc = c - 192; int dt = cc >> 6, o = cc & 63; v = w4[(o*4 + dt)*DE + k]; }
    else              { int cc = c - 448; int dt = cc >> 6, o = cc & 63; v = w5[(o*5 + dt)*DE + k]; }
    return __float2half_rn(v);
}
__device__ __forceinline__ __half whh_h(const float* whh, int n, int k) {
    if (n >= 3*DOUT || k >= DOUT) return __float2half_rn(0.f);
    return __float2half_rn(whh[n*DOUT + k]);
}

__global__ void __launch_bounds__(256) packall(
        const float* __restrict__ emb,
        const float* __restrict__ w3, const float* __restrict__ w4,
        const float* __restrict__ w5, const float* __restrict__ tw,
        const float* __restrict__ whh) {
    const int tid = threadIdx.x;
    if (blockIdx.x < PA_BLOCKS) {
        extern __shared__ __half sa[];
        const int mblk = blockIdx.x;
        {
            uint4* s4 = reinterpret_cast<uint4*>(sa);
            for (int i = tid; i < 128*PA_LDK/8; i += 256)
                s4[i] = make_uint4(0, 0, 0, 0);
        }
        __syncthreads();
        {
            const float4* e4 = reinterpret_cast<const float4*>(emb);
            for (int i = tid; i < 128*75; i += 256) {
                int row = i / 75, c4 = i - row*75;
                int m = mblk*128 + row;
                if (m < VOCAB) {
                    float4 v = e4[(size_t)m*75 + c4];
                    __half2 lo = __floats2half2_rn(v.x, v.y);
                    __half2 hi = __floats2half2_rn(v.z, v.w);
                    uint2 pk = make_uint2(*(uint32_t*)&lo, *(uint32_t*)&hi);
                    *reinterpret_cast<uint2*>(sa + row*PA_LDK + c4*4) = pk;
                }
            }
        }
        __syncthreads();
        {
            const int lane = tid & 31;
            const int r16  = tid >> 5;
            const int mloc = r16*16 + (lane >> 2);
            const int kk   = (lane & 3)*2;
            const uint32_t* s32 = reinterpret_cast<const uint32_t*>(sa);
            uint4* out4 = reinterpret_cast<uint4*>(g_Ah);
            #pragma unroll 4
            for (int kc16 = 0; kc16 < 20; kc16++) {
                int k = kc16*16 + kk;
                uint32_t h0 = s32[( mloc      *PA_LDK + k    ) >> 1];
                uint32_t h1 = s32[((mloc + 8)*PA_LDK + k    ) >> 1];
                uint32_t h2 = s32[( mloc      *PA_LDK + k + 8) >> 1];
                uint32_t h3 = s32[((mloc + 8)*PA_LDK + k + 8) >> 1];
                out4[((size_t)(mblk*20 + kc16)*8 + r16)*32 + lane] = make_uint4(h0, h1, h2, h3);
            }
        }
    } else if (blockIdx.x < PA_BLOCKS + PB_BLOCKS) {
        int d4 = (blockIdx.x - PA_BLOCKS) * 256 + tid;
        int lane = d4 & 31;
        int np   = (d4 >> 5) & 7;
        int rest = d4 >> 8;
        int kc16 = rest % 20;
        int nblk = rest / 20;
        int na = nblk*128 + np*16 + (lane >> 2);
        int nb = na + 8;
        int k = kc16*16 + (lane & 3)*2;
        __half2 h0 = __halves2half2(wall_h(w3,w4,w5, na, k),     wall_h(w3,w4,w5, na, k + 1));
        __half2 h1 = __halves2half2(wall_h(w3,w4,w5, na, k + 8), wall_h(w3,w4,w5, na, k + 9));
        __half2 h2 = __halves2half2(wall_h(w3,w4,w5, nb, k),     wall_h(w3,w4,w5, nb, k + 1));
        __half2 h3 = __halves2half2(wall_h(w3,w4,w5, nb, k + 8), wall_h(w3,w4,w5, nb, k + 9));
        uint4 v = make_uint4(*(uint32_t*)&h0, *(uint32_t*)&h1, *(uint32_t*)&h2, *(uint32_t*)&h3);
        reinterpret_cast<uint4*>(g_Bh)[d4] = v;
    } else if (blockIdx.x < PA_BLOCKS + PB_BLOCKS + TW_BLOCKS) {
        int idx = (blockIdx.x - PA_BLOCKS - PB_BLOCKS) * 256 + tid;
        if (idx < FCAT*DOUT) {
            int j = idx / DOUT, d = idx % DOUT;
            g_twT[idx] = tw[d*FCAT + j];
        }
    } else {
        int idx = (blockIdx.x - PA_BLOCKS - PB_BLOCKS - TW_BLOCKS) * 256 + tid;
        if (idx < 8*5*7*32) {
            int lane = idx & 31;
            int c = (idx >> 5) % 7;
            int rest = (idx >> 5) / 7;
            int t = rest % 5;
            int w = rest / 5;
            int n = w*40 + t*8 + (lane >> 2);
            int k = c*16 + (lane & 3)*2;
            __half2 b0 = __halves2half2(whh_h(whh, n, k),     whh_h(whh, n, k + 1));
            __half2 b1 = __halves2half2(whh_h(whh, n, k + 8), whh_h(whh, n, k + 9));
            g_WhhF[idx] = make_uint2(*(uint32_t*)&b0, *(uint32_t*)&b1);
        }
    }
}

// ---------------- fp16 mma GEMM: Z = Ah @ Bh^T (fp16 out) ----------------
#define GEMM_SMEM 49152

__global__ void __launch_bounds__(256, 2) conv_gemm_mma() {
    extern __shared__ char smc[];
    const int tid  = threadIdx.x;
    const int lane = tid & 31, wid = tid >> 5;
    const int warp_m = wid & 3;
    const int warp_n = wid >> 2;
    const int by = blockIdx.y, bx = blockIdx.x;
    const int m0 = by * 128, n0 = bx * 128;

    const uint32_t smb = smem_u32(smc);
    const uint4* Ah4 = reinterpret_cast<const uint4*>(g_Ah);
    const uint4* Bh4 = reinterpret_cast<const uint4*>(g_Bh);

    float acc[2][8][4];
    #pragma unroll
    for (int mt = 0; mt < 2; mt++)
        #pragma unroll
        for (int nt = 0; nt < 8; nt++)
            #pragma unroll
            for (int i = 0; i < 4; i++) acc[mt][nt][i] = 0.f;

    #pragma unroll
    for (int c = 0; c < 2; c++) {
        size_t aG = ((size_t)by*20 + c*2) * 256;
        size_t bG = ((size_t)bx*20 + c*2) * 256;
        #pragma unroll
        for (int i = 0; i < 2; i++) {
            CP_ASYNC16(smb +         c*8192 + (tid + i*256)*16, Ah4 + aG + tid + i*256);
            CP_ASYNC16(smb + 24576 + c*8192 + (tid + i*256)*16, Bh4 + bG + tid + i*256);
        }
        CP_COMMIT();
    }

    for (int c = 0; c < 10; c++) {
        const int buf = c % 3;
        if (c < 9) CP_WAIT(1); else CP_WAIT(0);
        __syncthreads();
        if (c + 2 < 10) {
            const int nb = (c + 2) % 3;
            size_t aG = ((size_t)by*20 + (c + 2)*2) * 256;
            size_t bG = ((size_t)bx*20 + (c + 2)*2) * 256;
            #pragma unroll
            for (int i = 0; i < 2; i++) {
                CP_ASYNC16(smb +         nb*8192 + (tid + i*256)*16, Ah4 + aG + tid + i*256);
                CP_ASYNC16(smb + 24576 + nb*8192 + (tid + i*256)*16, Bh4 + bG + tid + i*256);
            }
            CP_COMMIT();
        }

        const uint4* A4 = reinterpret_cast<const uint4*>(smc + buf*8192);
        const uint4* B4 = reinterpret_cast<const uint4*>(smc + 24576 + buf*8192);
        #pragma unroll
        for (int ks = 0; ks < 2; ks++) {
            uint32_t a[2][4], b[8][2];
            #pragma unroll
            for (int mt = 0; mt < 2; mt++) {
                uint4 v = A4[(ks*8 + warp_m*2 + mt)*32 + lane];
                a[mt][0] = v.x; a[mt][1] = v.y; a[mt][2] = v.z; a[mt][3] = v.w;
            }
            #pragma unroll
            for (int np = 0; np < 4; np++) {
                uint4 u = B4[(ks*8 + warp_n*4 + np)*32 + lane];
                b[2*np  ][0] = u.x; b[2*np  ][1] = u.y;
                b[2*np+1][0] = u.z; b[2*np+1][1] = u.w;
            }
            #pragma unroll
            for (int mt = 0; mt < 2; mt++)
                #pragma unroll
                for (int nt = 0; nt < 8; nt++)
                    mma_fp16(acc[mt][nt], a[mt], b[nt]);
        }
    }

    __half2* Z2 = reinterpret_cast<__half2*>(g_Zh);
    #pragma unroll
    for (int mt = 0; mt < 2; mt++) {
        int r = m0 + warp_m*32 + mt*16 + (lane >> 2);
        #pragma unroll
        for (int nt = 0; nt < 8; nt++) {
            int cc = n0 + warp_n*64 + nt*8 + (lane & 3)*2;
            Z2[((size_t) r      *NCOL + cc) >> 1] = __floats2half2_rn(acc[mt][nt][0], acc[mt][nt][1]);
            Z2[((size_t)(r + 8)*NCOL + cc) >> 1] = __floats2half2_rn(acc[mt][nt][2], acc[mt][nt][3]);
        }
    }
}

// ---------------- fused pool + relu + tanh projection -----------------------
#define POOL_T 768
#define POOL_SMEM (76800 + 200 + 6144 + 768)
__global__ void __launch_bounds__(POOL_T) poolsutt_kernel(
        const int* __restrict__ sents,
        const float* __restrict__ b3, const float* __restrict__ b4,
        const float* __restrict__ b5, const float* __restrict__ tb) {
    extern __shared__ char psm[];
    __half*  Zs    = reinterpret_cast<__half*>(psm);
    int*     toks  = reinterpret_cast<int*>(psm + 76800);
    float2*  pmax2 = reinterpret_cast<float2*>(psm + 77000);
    float*   fsh   = reinterpret_cast<float*>(psm + 83144);
    const int n = blockIdx.x;
    const int tid = threadIdx.x;
    const uint32_t zsb = smem_u32(Zs);

    if (tid < SL) toks[tid] = sents[n*SL + tid];
    __syncthreads();
    {
        const uint4* Zg4 = reinterpret_cast<const uint4*>(g_Zh);
        for (int i = tid; i < SL*96; i += POOL_T) {
            int row = i / 96, c4 = i - row*96;
            CP_ASYNC16(zsb + i*16, Zg4 + (size_t)toks[row]*96 + c4);
        }
        CP_COMMIT();
        CP_WAIT(0);
    }
    __syncthreads();
    {
        const int q  = tid / 96;
        const int p  = tid - q*96;
        const int fi = p >> 5, o2 = p & 31;
        const int fs  = 3 + fi;
        const int offh = ((fi == 0) ? 0 : (fi == 1) ? 192 : 448) / 2;
        const int T = SL - fs + 1;
        const int t0 = (T * q) >> 3;
        const int t1 = (T * (q + 1)) >> 3;
        const __half2* Zs2 = reinterpret_cast<const __half2*>(Zs);
        float mx0 = -1e30f, mx1 = -1e30f;
        for (int t = t0; t < t1; t++) {
            float v0 = 0.f, v1 = 0.f;
            #pragma unroll 5
            for (int dt = 0; dt < fs; dt++) {
                __half2 h = Zs2[(t + dt)*384 + offh + dt*32 + o2];
                float2 f = __half22float2(h);
                v0 += f.x; v1 += f.y;
            }
            mx0 = fmaxf(mx0, v0); mx1 = fmaxf(mx1, v1);
        }
        pmax2[q*96 + p] = make_float2(mx0, mx1);
    }
    __syncthreads();
    if (tid < 96) {
        const int fi = tid >> 5, o2 = tid & 31;
        const int fa = fi*64 + 2*o2;
        float m0 = -1e30f, m1 = -1e30f;
        #pragma unroll
        for (int q = 0; q < 8; q++) {
            float2 v = pmax2[q*96 + tid];
            m0 = fmaxf(m0, v.x); m1 = fmaxf(m1, v.y);
        }
        float ba = (fi == 0) ? b3[2*o2]     : (fi == 1) ? b4[2*o2]     : b5[2*o2];
        float bb = (fi == 0) ? b3[2*o2 + 1] : (fi == 1) ? b4[2*o2 + 1] : b5[2*o2 + 1];
        fsh[fa]     = fmaxf(0.f, m0 + ba);
        fsh[fa + 1] = fmaxf(0.f, m1 + bb);
    }
    __syncthreads();
    if (tid < DOUT) {
        float acc = tb[tid];
        #pragma unroll 8
        for (int j = 0; j < FCAT; j++) acc += fsh[j] * g_twT[j*DOUT + tid];
        g_sutt[n*DOUT + tid] = tanhf(acc);
    }
}

// ---------------- fused GRU v7: HMMA + smem memb + attn + cls epilogue -------
#define GRB 16
#define GRU_T 256
#define NXV (GRB + WIND - 1)   // 25
// smem: floats xp[7500] xvs[2500] hs[1600] gh[4800] bhs[300] = 66800 B
//       h16 [16][60] u32 = 3840 B @66800 ; memb_s [16][10][100] f = 64000 B @70640
#define GRU_SMEM (66800 + 3840 + 64000)
__global__ void __launch_bounds__(GRU_T, 1) gru_fused(
        const float* __restrict__ wih, const float* __restrict__ bih,
        const float* __restrict__ bhh,
        const float* __restrict__ cw,  const float* __restrict__ cb,
        float* __restrict__ attn_out,  float* __restrict__ pred_out) {
    extern __shared__ char smraw[];
    float* xp  = reinterpret_cast<float*>(smraw);            // [25][300]
    float* xvs = xp + NXV*3*DOUT;                            // [25][100]
    float* hs  = xvs + NXV*DOUT;                             // [16][100]
    float* gh  = hs + GRB*DOUT;                              // [16][300]
    float* bhs = gh + GRB*3*DOUT;                            // [300]
    uint32_t* h16   = reinterpret_cast<uint32_t*>(smraw + 66800); // [16][60]
    float*    membs = reinterpret_cast<float*>(smraw + 70640);    // [16][10][100]
    const int tid = threadIdx.x;
    const int lane = tid & 31, wid = tid >> 5;
    const int b0 = blockIdx.x * GRB;

    uint2 Bf[5][7];
    #pragma unroll
    for (int t = 0; t < 5; t++)
        #pragma unroll
        for (int c = 0; c < 7; c++)
            Bf[t][c] = g_WhhF[((wid*5 + t)*7 + c)*32 + lane];

    for (int i = tid; i < NXV*DOUT; i += GRU_T) {
        int vi = i / DOUT, d = i - vi*DOUT;
        int v = b0 - (WIND - 1) + vi;
        xvs[i] = (v >= 0 && v < NB) ? g_sutt[v*DOUT + d] : 0.f;
    }
    for (int i = tid; i < GRB*DOUT; i += GRU_T) hs[i] = 0.f;
    for (int i = tid; i < 3*DOUT; i += GRU_T) bhs[i] = bhh[i];
    for (int i = tid; i < 16*60; i += GRU_T) h16[i] = 0;
    __syncthreads();

    for (int i = tid; i < NXV*3*DOUT; i += GRU_T) {
        int vi = i / (3*DOUT), j = i - vi*3*DOUT;
        const float4* wI = reinterpret_cast<const float4*>(wih + j*DOUT);
        const float4* xv = reinterpret_cast<const float4*>(xvs + vi*DOUT);
        float acc = 0.f;
        #pragma unroll
        for (int k = 0; k < DOUT/4; k++) {
            float4 w = wI[k], x = xv[k];
            acc += w.x*x.x + w.y*x.y + w.z*x.z + w.w*x.w;
        }
        xp[i] = acc + bih[j];
    }
    __syncthreads();

    for (int s = 0; s < WIND; s++) {
        // HMMA: gh = h @ whh^T
        {
            float acc[5][4];
            #pragma unroll
            for (int t = 0; t < 5; t++)
                #pragma unroll
                for (int i = 0; i < 4; i++) acc[t][i] = 0.f;
            const int row = lane >> 2, q = lane & 3;
            #pragma unroll
            for (int c = 0; c < 7; c++) {
                uint32_t a[4];
                a[0] = h16[ row      *60 + c*8 + q];
                a[1] = h16[(row + 8)*60 + c*8 + q];
                a[2] = h16[ row      *60 + c*8 + q + 4];
                a[3] = h16[(row + 8)*60 + c*8 + q + 4];
                #pragma unroll
                for (int t = 0; t < 5; t++)
                    mma_fp16(acc[t], a, (const uint32_t*)&Bf[t][c]);
            }
            #pragma unroll
            for (int t = 0; t < 5; t++) {
                int n = wid*40 + t*8 + q*2;
                if (n < 3*DOUT) {
                    *reinterpret_cast<float2*>(&gh[ row      *3*DOUT + n]) =
                        make_float2(acc[t][0], acc[t][1]);
                    *reinterpret_cast<float2*>(&gh[(row + 8)*3*DOUT + n]) =
                        make_float2(acc[t][2], acc[t][3]);
                }
            }
        }
        __syncthreads();

        for (int i = tid; i < GRB*50; i += GRU_T) {
            int r = i / 50, kp = i - r*50;
            int d0 = kp*2;
            int vi = r + s;
            const float* xpr = xp + vi*3*DOUT;
            float hnew[2];
            #pragma unroll
            for (int u = 0; u < 2; u++) {
                int d = d0 + u;
                float giR = xpr[d];
                float giZ = xpr[DOUT + d];
                float giN = xpr[2*DOUT + d];
                float hr = gh[r*3*DOUT + d]          + bhs[d];
                float hz = gh[r*3*DOUT + DOUT + d]   + bhs[DOUT + d];
                float hn = gh[r*3*DOUT + 2*DOUT + d] + bhs[2*DOUT + d];
                float rr = sigmoid_fast(giR + hr);
                float zz = sigmoid_fast(giZ + hz);
                float nn = tanh_fast(giN + rr*hn);
                float hprev = hs[r*DOUT + d];
                hnew[u] = (1.f - zz)*nn + zz*hprev;
                hs[r*DOUT + d] = hnew[u];
            }
            __half2 hp = __floats2half2_rn(hnew[0], hnew[1]);
            h16[r*60 + kp] = *(uint32_t*)&hp;
            float xv0 = xvs[vi*DOUT + d0], xv1 = xvs[vi*DOUT + d0 + 1];
            *reinterpret_cast<float2*>(&membs[(r*WIND + s)*DOUT + d0]) =
                make_float2(xv0 + hnew[0], xv1 + hnew[1]);
        }
        __syncthreads();
    }

    // ---- epilogue: attention (2 windows per warp) + classifier ----
    #pragma unroll
    for (int wi = 0; wi < 2; wi++) {
        const int r = wid*2 + wi;
        const int w = b0 + r;
        if (w < NB) {
            float M[WIND][4], q[4];
            #pragma unroll
            for (int jj = 0; jj < 4; jj++) {
                int d = lane + 32*jj;
                bool ok = d < DOUT;
                q[jj] = ok ? g_sutt[(w + 1)*DOUT + d] : 0.f;
                #pragma unroll
                for (int k = 0; k < WIND; k++)
                    M[k][jj] = ok ? membs[(r*WIND + k)*DOUT + d] : 0.f;
            }
            #pragma unroll
            for (int hop = 0; hop < HOPS; hop++) {
                float l[WIND];
                #pragma unroll
                for (int k = 0; k < WIND; k++) {
                    float p = q[0]*M[k][0] + q[1]*M[k][1] + q[2]*M[k][2] + q[3]*M[k][3];
                    #pragma unroll
                    for (int off = 16; off; off >>= 1)
                        p += __shfl_xor_sync(0xFFFFFFFFu, p, off);
                    l[k] = (w + k - (WIND - 1) >= 0) ? p : -1e10f;
                }
                float mx = l[0];
                #pragma unroll
                for (int k = 1; k < WIND; k++) mx = fmaxf(mx, l[k]);
                float a[WIND], sum = 0.f;
                #pragma unroll
                for (int k = 0; k < WIND; k++) { a[k] = expf(l[k] - mx); sum += a[k]; }
                float inv = 1.f / sum;
                #pragma unroll
                for (int k = 0; k < WIND; k++) {
                    a[k] *= inv;
                    if (lane == k) attn_out[hop*(NB*WIND) + w*WIND + k] = a[k];
                }
                #pragma unroll
                for (int jj = 0; jj < 4; jj++) {
                    float acc = 0.f;
                    #pragma unroll
                    for (int k = 0; k < WIND; k++) acc += a[k] * M[k][jj];
                    q[jj] += acc;
                }
            }
            // classifier + log_softmax for pred row w+1
            float lg[NC];
            #pragma unroll
            for (int c = 0; c < NC; c++) {
                float p = 0.f;
                #pragma unroll
                for (int jj = 0; jj < 4; jj++) {
                    int d = lane + 32*jj;
                    if (d < DOUT) p += q[jj] * cw[c*DOUT + d];
                }
                #pragma unroll
                for (int off = 16; off; off >>= 1)
                    p += __shfl_xor_sync(0xFFFFFFFFu, p, off);
                lg[c] = p + cb[c];
            }
            float mx = lg[0];
            #pragma unroll
            for (int c = 1; c < NC; c++) mx = fmaxf(mx, lg[c]);
            float sum = 0.f;
            #pragma unroll
            for (int c = 0; c < NC; c++) sum += expf(lg[c] - mx);
            float lse = mx + logf(sum);
            if (lane < NC) pred_out[(w + 1)*NC + lane] = lg[lane] - lse;
        }
    }
    // pred row 0 from s_utt[0] (block 0, warp 0)
    if (blockIdx.x == 0 && wid == 0) {
        float q[4];
        #pragma unroll
        for (int jj = 0; jj < 4; jj++) {
            int d = lane + 32*jj;
            q[jj] = (d < DOUT) ? g_sutt[d] : 0.f;
        }
        float lg[NC];
        #pragma unroll
        for (int c = 0; c < NC; c++) {
            float p = 0.f;
            #pragma unroll
            for (int jj = 0; jj < 4; jj++) {
                int d = lane + 32*jj;
                if (d < DOUT) p += q[jj] * cw[c*DOUT + d];
            }
            #pragma unroll
            for (int off = 16; off; off >>= 1)
                p += __shfl_xor_sync(0xFFFFFFFFu, p, off);
            lg[c] = p + cb[c];
        }
        float mx = lg[0];
        #pragma unroll
        for (int c = 1; c < NC; c++) mx = fmaxf(mx, lg[c]);
        float sum = 0.f;
        #pragma unroll
        for (int c = 0; c < NC; c++) sum += expf(lg[c] - mx);
        float lse = mx + logf(sum);
        if (lane < NC) pred_out[lane] = lg[lane] - lse;
    }
}

// ---------------- launch sequence ----------------
extern "C" void kernel_launch(void* const* d_in, const int* in_sizes, int n_in,
                              void* d_out, int out_size) {
    const int*   sents   = (const int*)  d_in[0];
    const float* emb     = (const float*)d_in[2];
    const float* trans_w = (const float*)d_in[3];
    const float* trans_b = (const float*)d_in[4];
    const float* gru_wih = (const float*)d_in[5];
    const float* gru_whh = (const float*)d_in[6];
    const float* gru_bih = (const float*)d_in[7];
    const float* gru_bhh = (const float*)d_in[8];
    const float* cls_w   = (const float*)d_in[9];
    const float* cls_b   = (const float*)d_in[10];
    const float* conv_w3 = (const float*)d_in[11];
    const float* conv_b3 = (const float*)d_in[12];
    const float* conv_w4 = (const float*)d_in[13];
    const float* conv_b4 = (const float*)d_in[14];
    const float* conv_w5 = (const float*)d_in[15];
    const float* conv_b5 = (const float*)d_in[16];

    float* outF = (float*)d_out;
    float* pred_out = outF;
    float* attn_out;
    if (out_size >= NU*NC + HOPS*NB*WIND) attn_out = outF + NU*NC;
    else cudaGetSymbolAddress((void**)&attn_out, g_attn_scratch);

    cudaFuncSetAttribute(packall,         cudaFuncAttributeMaxDynamicSharedMemorySize, PACKA_SMEM);
    cudaFuncSetAttribute(conv_gemm_mma,   cudaFuncAttributeMaxDynamicSharedMemorySize, GEMM_SMEM);
    cudaFuncSetAttribute(poolsutt_kernel, cudaFuncAttributeMaxDynamicSharedMemorySize, POOL_SMEM);
    cudaFuncSetAttribute(gru_fused,       cudaFuncAttributeMaxDynamicSharedMemorySize, GRU_SMEM);

    packall<<<PA_BLOCKS + PB_BLOCKS + TW_BLOCKS + WF_BLOCKS, 256, PACKA_SMEM>>>(
        emb, conv_w3, conv_w4, conv_w5, trans_w, gru_whh);

    dim3 ggrid(NCOL/128, VPAD/128);   // (6, 391)
    conv_gemm_mma<<<ggrid, 256, GEMM_SMEM>>>();

    poolsutt_kernel<<<NU, POOL_T, POOL_SMEM>>>(sents, conv_b3, conv_b4, conv_b5, trans_b);
    gru_fused<<<(NB + GRB - 1)/GRB, GRU_T, GRU_SMEM>>>(
        gru_wih, gru_bih, gru_bhh, cls_w, cls_b, attn_out, pred_out);
}